// round 3
// baseline (speedup 1.0000x reference)
#include <cuda_runtime.h>
#include <math.h>
#include <float.h>
#include <stdint.h>

// ---------------------------------------------------------------------------
// Informer: B=4, L=1024, DM=512, NH=8, HD=64, DFF=2048, SK=35, 2 layers
// ---------------------------------------------------------------------------
#define B_   4
#define L_   1024
#define DM   512
#define NH   8
#define HD   64
#define DFF  2048
#define SK   35
#define NTOK (B_*L_)   // 4096

__device__ float g_x   [NTOK*DM];
__device__ float g_tmp [NTOK*DM];
__device__ float g_q   [NTOK*DM];
__device__ float g_k   [NTOK*DM];
__device__ float g_v   [NTOK*DM];
__device__ float g_ctx [NTOK*DM];
__device__ float g_ff  [NTOK*DFF];
__device__ float g_M   [B_*NH*L_];
__device__ int   g_top [B_*NH*SK];
__device__ float g_poolp[B_*8*DM];
__device__ float g_pool [B_*DM];

// ---------------------------------------------------------------------------
__device__ __forceinline__ float to_tf32(float x) {
    uint32_t u;
    asm("cvt.rna.tf32.f32 %0, %1;" : "=r"(u) : "f"(x));
    return __uint_as_float(u);
}

__device__ __forceinline__ void mma_tf32(float* c, const uint32_t* a,
                                         uint32_t b0, uint32_t b1) {
    asm volatile(
        "mma.sync.aligned.m16n8k8.row.col.f32.tf32.tf32.f32 "
        "{%0,%1,%2,%3},{%4,%5,%6,%7},{%8,%9},{%0,%1,%2,%3};"
        : "+f"(c[0]), "+f"(c[1]), "+f"(c[2]), "+f"(c[3])
        : "r"(a[0]), "r"(a[1]), "r"(a[2]), "r"(a[3]), "r"(b0), "r"(b1));
}

// ---------------------------------------------------------------------------
// Embedding + positional encoding
// ---------------------------------------------------------------------------
__global__ void embed_kernel(const float* __restrict__ src,
                             const float* __restrict__ Wemb,
                             const float* __restrict__ bemb) {
    int row = blockIdx.x;
    int l   = row & (L_-1);
    int d   = threadIdx.x;
    __shared__ float s[32];
    if (d < 32) s[d] = src[row*32 + d];
    __syncthreads();
    float acc = bemb[d];
    #pragma unroll
    for (int k = 0; k < 32; k++) acc += s[k] * Wemb[k*DM + d];
    int i2 = d & ~1;
    float div = expf(-(float)i2 * (9.210340371976184f / 512.0f));
    float ang = (float)l * div;
    acc += (d & 1) ? cosf(ang) : sinf(ang);
    g_x[row*DM + d] = acc;
}

// ---------------------------------------------------------------------------
// tf32 tensor-core GEMM body. Block tile 128 x BN x 16, 256 threads (8 warps,
// 4m x 2n), warp tile 32 x (BN/2). Double-buffered smem, register staging.
// ---------------------------------------------------------------------------
template<int BN, bool GELU>
__device__ __forceinline__ void gemm_body(
        const float* __restrict__ A, const float* __restrict__ W,
        const float* __restrict__ bias, const float* __restrict__ resid,
        float* __restrict__ C, int N, int K, int bx, int by) {
    constexpr int NT = BN / 16;            // n-tiles (m16n8) per warp: 8 or 4
    __shared__ float As[2][16][136];       // [k][m], padded
    __shared__ float Bs[2][16][BN + 8];    // [k][n], padded

    const int tid  = threadIdx.x;
    const int w    = tid >> 5;
    const int lane = tid & 31;
    const int grp  = lane >> 2;            // 0..7
    const int qd   = lane & 3;             // 0..3
    const int warp_m = (w & 3) * 32;
    const int warp_n = (w >> 2) * (BN / 2);
    const int m0 = by * 128;
    const int n0 = bx * BN;

    // A staging: rows am and am+64, 4 k-floats each
    const int am  = tid >> 2;
    const int akc = (tid & 3) << 2;
    // B staging
    const int bkr = (BN == 128) ? (tid >> 5) : (tid >> 4);
    const int bnc = (BN == 128) ? ((tid & 31) << 2) : ((tid & 15) << 2);

    float acc[2][NT][4];
    #pragma unroll
    for (int mi = 0; mi < 2; mi++)
        #pragma unroll
        for (int ni = 0; ni < NT; ni++)
            #pragma unroll
            for (int j = 0; j < 4; j++) acc[mi][ni][j] = 0.f;

    const int nt = K >> 4;

    // prologue: stage tile 0
    {
        float4 ra0 = *(const float4*)&A[(size_t)(m0+am)*K + akc];
        float4 ra1 = *(const float4*)&A[(size_t)(m0+am+64)*K + akc];
        As[0][akc+0][am] = to_tf32(ra0.x); As[0][akc+1][am] = to_tf32(ra0.y);
        As[0][akc+2][am] = to_tf32(ra0.z); As[0][akc+3][am] = to_tf32(ra0.w);
        As[0][akc+0][am+64] = to_tf32(ra1.x); As[0][akc+1][am+64] = to_tf32(ra1.y);
        As[0][akc+2][am+64] = to_tf32(ra1.z); As[0][akc+3][am+64] = to_tf32(ra1.w);
        float4 rb0 = *(const float4*)&W[(size_t)bkr*N + n0 + bnc];
        Bs[0][bkr][bnc+0] = to_tf32(rb0.x); Bs[0][bkr][bnc+1] = to_tf32(rb0.y);
        Bs[0][bkr][bnc+2] = to_tf32(rb0.z); Bs[0][bkr][bnc+3] = to_tf32(rb0.w);
        if (BN == 128) {
            float4 rb1 = *(const float4*)&W[(size_t)(bkr+8)*N + n0 + bnc];
            Bs[0][bkr+8][bnc+0] = to_tf32(rb1.x); Bs[0][bkr+8][bnc+1] = to_tf32(rb1.y);
            Bs[0][bkr+8][bnc+2] = to_tf32(rb1.z); Bs[0][bkr+8][bnc+3] = to_tf32(rb1.w);
        }
    }
    __syncthreads();

    for (int t = 0; t < nt; t++) {
        const int buf = t & 1;
        const bool more = (t + 1 < nt);
        float4 ra0, ra1, rb0, rb1;
        if (more) {
            int k0 = (t+1) << 4;
            ra0 = *(const float4*)&A[(size_t)(m0+am)*K + k0 + akc];
            ra1 = *(const float4*)&A[(size_t)(m0+am+64)*K + k0 + akc];
            rb0 = *(const float4*)&W[(size_t)(k0+bkr)*N + n0 + bnc];
            if (BN == 128)
                rb1 = *(const float4*)&W[(size_t)(k0+bkr+8)*N + n0 + bnc];
        }

        #pragma unroll
        for (int kk = 0; kk < 16; kk += 8) {
            uint32_t af[2][4];
            #pragma unroll
            for (int mi = 0; mi < 2; mi++) {
                int mb = warp_m + mi*16 + grp;
                af[mi][0] = __float_as_uint(As[buf][kk+qd  ][mb]);
                af[mi][1] = __float_as_uint(As[buf][kk+qd  ][mb+8]);
                af[mi][2] = __float_as_uint(As[buf][kk+qd+4][mb]);
                af[mi][3] = __float_as_uint(As[buf][kk+qd+4][mb+8]);
            }
            #pragma unroll
            for (int ni = 0; ni < NT; ni++) {
                int nb = warp_n + ni*8 + grp;
                uint32_t b0 = __float_as_uint(Bs[buf][kk+qd  ][nb]);
                uint32_t b1 = __float_as_uint(Bs[buf][kk+qd+4][nb]);
                mma_tf32(acc[0][ni], af[0], b0, b1);
                mma_tf32(acc[1][ni], af[1], b0, b1);
            }
        }

        if (more) {
            int nb = buf ^ 1;
            As[nb][akc+0][am] = to_tf32(ra0.x); As[nb][akc+1][am] = to_tf32(ra0.y);
            As[nb][akc+2][am] = to_tf32(ra0.z); As[nb][akc+3][am] = to_tf32(ra0.w);
            As[nb][akc+0][am+64] = to_tf32(ra1.x); As[nb][akc+1][am+64] = to_tf32(ra1.y);
            As[nb][akc+2][am+64] = to_tf32(ra1.z); As[nb][akc+3][am+64] = to_tf32(ra1.w);
            Bs[nb][bkr][bnc+0] = to_tf32(rb0.x); Bs[nb][bkr][bnc+1] = to_tf32(rb0.y);
            Bs[nb][bkr][bnc+2] = to_tf32(rb0.z); Bs[nb][bkr][bnc+3] = to_tf32(rb0.w);
            if (BN == 128) {
                Bs[nb][bkr+8][bnc+0] = to_tf32(rb1.x); Bs[nb][bkr+8][bnc+1] = to_tf32(rb1.y);
                Bs[nb][bkr+8][bnc+2] = to_tf32(rb1.z); Bs[nb][bkr+8][bnc+3] = to_tf32(rb1.w);
            }
        }
        __syncthreads();
    }

    // epilogue
    #pragma unroll
    for (int mi = 0; mi < 2; mi++) {
        int r0 = m0 + warp_m + mi*16 + grp;
        #pragma unroll
        for (int ni = 0; ni < NT; ni++) {
            int c = n0 + warp_n + ni*8 + qd*2;
            float b0 = bias[c], b1 = bias[c+1];
            float v0 = acc[mi][ni][0] + b0;
            float v1 = acc[mi][ni][1] + b1;
            float v2 = acc[mi][ni][2] + b0;
            float v3 = acc[mi][ni][3] + b1;
            if (resid) {
                v0 += resid[(size_t)r0*N + c];     v1 += resid[(size_t)r0*N + c + 1];
                v2 += resid[(size_t)(r0+8)*N + c]; v3 += resid[(size_t)(r0+8)*N + c + 1];
            }
            if (GELU) {
                v0 = 0.5f*v0*(1.0f + erff(v0*0.70710678118654752f));
                v1 = 0.5f*v1*(1.0f + erff(v1*0.70710678118654752f));
                v2 = 0.5f*v2*(1.0f + erff(v2*0.70710678118654752f));
                v3 = 0.5f*v3*(1.0f + erff(v3*0.70710678118654752f));
            }
            *(float2*)&C[(size_t)r0*N + c]     = make_float2(v0, v1);
            *(float2*)&C[(size_t)(r0+8)*N + c] = make_float2(v2, v3);
        }
    }
}

template<int BN, bool GELU>
__global__ void __launch_bounds__(256, (BN == 64) ? 3 : 2)
gemm_tc(const float* __restrict__ A, const float* __restrict__ W,
        const float* __restrict__ bias, const float* __restrict__ resid,
        float* __restrict__ C, int N, int K) {
    gemm_body<BN, GELU>(A, W, bias, resid, C, N, K, blockIdx.x, blockIdx.y);
}

// Fused QKV: blockIdx.z selects projection. BN=64 tiles, grid (8, 32, 3).
__global__ void __launch_bounds__(256, 3)
qkv_tc(const float* __restrict__ A,
       const float* __restrict__ Wq, const float* __restrict__ bq,
       const float* __restrict__ Wk, const float* __restrict__ bk,
       const float* __restrict__ Wv, const float* __restrict__ bv,
       float* __restrict__ Q, float* __restrict__ Ko, float* __restrict__ V) {
    const float* W; const float* bias; float* C;
    if (blockIdx.z == 0)      { W = Wq; bias = bq; C = Q;  }
    else if (blockIdx.z == 1) { W = Wk; bias = bk; C = Ko; }
    else                      { W = Wv; bias = bv; C = V;  }
    gemm_body<64, false>(A, W, bias, nullptr, C, DM, DM, blockIdx.x, blockIdx.y);
}

// ---------------------------------------------------------------------------
// Sampled sparsity measure M (one warp per (b,h,i))
// ---------------------------------------------------------------------------
__global__ void sampleM_kernel(const int* __restrict__ idxs) {
    int wg   = (blockIdx.x * blockDim.x + threadIdx.x) >> 5;
    int lane = threadIdx.x & 31;
    if (wg >= B_*NH*L_) return;
    int i = wg & (L_-1);
    int h = (wg >> 10) & (NH-1);
    int b = wg >> 13;
    const float* Qrow = &g_q[(size_t)(b*L_ + i)*DM + h*HD];
    float qa = Qrow[lane], qb = Qrow[lane+32];
    float mx = -FLT_MAX, sm = 0.f;
    for (int j = 0; j < SK; j++) {
        int s = idxs[i*SK + j];
        const float* Krow = &g_k[(size_t)(b*L_ + s)*DM + h*HD];
        float p = qa*Krow[lane] + qb*Krow[lane+32];
        #pragma unroll
        for (int o = 16; o > 0; o >>= 1) p += __shfl_xor_sync(0xffffffffu, p, o);
        mx = fmaxf(mx, p);
        sm += p;
    }
    if (lane == 0) g_M[(b*NH+h)*L_ + i] = mx - sm * (1.0f/SK);
}

// ---------------------------------------------------------------------------
// Exact top-35 (lowest-index tie-break). 1024 threads.
// ---------------------------------------------------------------------------
__global__ void topk_kernel() {
    int bh = blockIdx.x;
    int t  = threadIdx.x;
    int lane = t & 31, w = t >> 5;
    float v = g_M[bh*L_ + t];
    __shared__ float wv[32];
    __shared__ int   wi[32];
    __shared__ int   win;
    for (int iter = 0; iter < SK; iter++) {
        float bv = v; int bi = t;
        #pragma unroll
        for (int o = 16; o > 0; o >>= 1) {
            float ov = __shfl_xor_sync(0xffffffffu, bv, o);
            int   oi = __shfl_xor_sync(0xffffffffu, bi, o);
            if (ov > bv || (ov == bv && oi < bi)) { bv = ov; bi = oi; }
        }
        if (lane == 0) { wv[w] = bv; wi[w] = bi; }
        __syncthreads();
        if (w == 0) {
            float bv2 = wv[lane]; int bi2 = wi[lane];
            #pragma unroll
            for (int o = 16; o > 0; o >>= 1) {
                float ov = __shfl_xor_sync(0xffffffffu, bv2, o);
                int   oi = __shfl_xor_sync(0xffffffffu, bi2, o);
                if (ov > bv2 || (ov == bv2 && oi < bi2)) { bv2 = ov; bi2 = oi; }
            }
            if (lane == 0) { win = bi2; g_top[bh*SK + iter] = bi2; }
        }
        __syncthreads();
        if (t == win) v = -FLT_MAX;
    }
}

// ---------------------------------------------------------------------------
// Fused attention per (b,h): vmean + broadcast fill + scores + softmax + ctx
// ---------------------------------------------------------------------------
#define ATT_THREADS 512
#define SQ_ROWS 48
#define ATT_SMEM_FLOATS (35*1024 + SQ_ROWS*64 + 64*129 + 64 + 512 + 64)

__global__ void __launch_bounds__(ATT_THREADS, 1)
attn_fused() {
    extern __shared__ float dsm[];
    float* scores = dsm;                          // 35*1024
    float* sq     = scores + 35*1024;             // 48*64
    float* kt     = sq + SQ_ROWS*64;              // 64*129
    float* vmean  = kt + 64*129;                  // 64
    float* red    = vmean + 64;                   // 512
    int*   tops   = (int*)(red + 512);            // 48

    const int bh = blockIdx.x;
    const int b  = bh >> 3;
    const int h  = bh & 7;
    const int t  = threadIdx.x;
    const int lane = t & 31;
    const int w  = t >> 5;

    if (t < SK) tops[t] = g_top[bh*SK + t];
    __syncthreads();

    for (int f = t; f < SQ_ROWS*64; f += ATT_THREADS) {
        int u = f >> 6, k = f & 63;
        sq[f] = (u < SK) ? g_q[(size_t)((b<<10) + tops[u])*DM + h*HD + k] : 0.f;
    }

    {
        int e = t & 63, r = t >> 6;
        float acc = 0.f;
        for (int l = r*128; l < r*128 + 128; l++)
            acc += g_v[(size_t)((b<<10) + l)*DM + h*HD + e];
        red[t] = acc;
        __syncthreads();
        if (t < 64) {
            float s = 0.f;
            #pragma unroll
            for (int rr = 0; rr < 8; rr++) s += red[t + rr*64];
            vmean[t] = s * (1.0f/L_);
        }
        __syncthreads();
    }

    {
        const float4* vm4 = (const float4*)vmean;
        for (int f = t; f < (L_*HD)/4; f += ATT_THREADS) {
            int l = f >> 4, ev = f & 15;
            *(float4*)&g_ctx[(size_t)((b<<10) + l)*DM + h*HD + ev*4] = vm4[ev];
        }
    }

    for (int st = 0; st < 8; st++) {
        #pragma unroll
        for (int i = 0; i < 4; i++) {
            int f = t + i*ATT_THREADS;
            int s = f >> 4, ec = (f & 15) << 2;
            float4 kv = *(const float4*)&g_k[(size_t)((b<<10) + st*128 + s)*DM + h*HD + ec];
            kt[(ec+0)*129 + s] = kv.x;
            kt[(ec+1)*129 + s] = kv.y;
            kt[(ec+2)*129 + s] = kv.z;
            kt[(ec+3)*129 + s] = kv.w;
        }
        __syncthreads();

        float acc[3][4];
        #pragma unroll
        for (int uu = 0; uu < 3; uu++)
            #pragma unroll
            for (int j = 0; j < 4; j++) acc[uu][j] = 0.f;

        for (int k = 0; k < 64; k++) {
            float kv0 = kt[k*129 + lane];
            float kv1 = kt[k*129 + lane + 32];
            float kv2 = kt[k*129 + lane + 64];
            float kv3 = kt[k*129 + lane + 96];
            #pragma unroll
            for (int uu = 0; uu < 3; uu++) {
                float qv = sq[(uu*16 + w)*64 + k];
                acc[uu][0] += qv*kv0; acc[uu][1] += qv*kv1;
                acc[uu][2] += qv*kv2; acc[uu][3] += qv*kv3;
            }
        }
        #pragma unroll
        for (int uu = 0; uu < 3; uu++) {
            int u = uu*16 + w;
            if (u < SK) {
                scores[u*1024 + st*128 + lane]      = acc[uu][0]*0.125f;
                scores[u*1024 + st*128 + lane + 32] = acc[uu][1]*0.125f;
                scores[u*1024 + st*128 + lane + 64] = acc[uu][2]*0.125f;
                scores[u*1024 + st*128 + lane + 96] = acc[uu][3]*0.125f;
            }
        }
        __syncthreads();
    }

    for (int u = w; u < SK; u += 16) {
        float* row = &scores[u*1024];
        float m = -FLT_MAX;
        #pragma unroll
        for (int i = 0; i < 32; i++) m = fmaxf(m, row[lane + 32*i]);
        #pragma unroll
        for (int o = 16; o > 0; o >>= 1) m = fmaxf(m, __shfl_xor_sync(0xffffffffu, m, o));
        float s = 0.f;
        #pragma unroll
        for (int i = 0; i < 32; i++) {
            float e = expf(row[lane + 32*i] - m);
            row[lane + 32*i] = e;
            s += e;
        }
        #pragma unroll
        for (int o = 16; o > 0; o >>= 1) s += __shfl_xor_sync(0xffffffffu, s, o);
        float inv = 1.0f / s;
        #pragma unroll
        for (int i = 0; i < 32; i++) row[lane + 32*i] *= inv;
    }
    __syncthreads();

    {
        int e = t & 63, ug = t >> 6;
        float acc9[5] = {0.f, 0.f, 0.f, 0.f, 0.f};
        for (int st = 0; st < 8; st++) {
            #pragma unroll
            for (int i = 0; i < 4; i++) {
                int f = t + i*ATT_THREADS;
                int s = f >> 4, ec = (f & 15) << 2;
                float4 vv = *(const float4*)&g_v[(size_t)((b<<10) + st*128 + s)*DM + h*HD + ec];
                kt[(ec+0)*129 + s] = vv.x;
                kt[(ec+1)*129 + s] = vv.y;
                kt[(ec+2)*129 + s] = vv.z;
                kt[(ec+3)*129 + s] = vv.w;
            }
            __syncthreads();
            for (int s = 0; s < 128; s++) {
                float v = kt[e*129 + s];
                #pragma unroll
                for (int uu = 0; uu < 5; uu++) {
                    int u = ug + (uu << 3);
                    if (u < SK) acc9[uu] += scores[u*1024 + st*128 + s] * v;
                }
            }
            __syncthreads();
        }
        #pragma unroll
        for (int uu = 0; uu < 5; uu++) {
            int u = ug + (uu << 3);
            if (u < SK) {
                int qi = tops[u];
                g_ctx[(size_t)((b<<10) + qi)*DM + h*HD + e] = acc9[uu];
            }
        }
    }
}

// ---------------------------------------------------------------------------
// LayerNorm (row of 512, 256 threads)
// ---------------------------------------------------------------------------
__global__ void ln_kernel(const float* __restrict__ in, float* __restrict__ out,
                          const float* __restrict__ g, const float* __restrict__ be) {
    int row = blockIdx.x;
    int t   = threadIdx.x;
    float v0 = in[(size_t)row*DM + t];
    float v1 = in[(size_t)row*DM + t + 256];
    __shared__ float red[256];
    red[t] = v0 + v1; __syncthreads();
    for (int s = 128; s > 0; s >>= 1) { if (t < s) red[t] += red[t+s]; __syncthreads(); }
    float mean = red[0] * (1.0f/DM);
    __syncthreads();
    float d0 = v0 - mean, d1 = v1 - mean;
    red[t] = d0*d0 + d1*d1; __syncthreads();
    for (int s = 128; s > 0; s >>= 1) { if (t < s) red[t] += red[t+s]; __syncthreads(); }
    float rstd = rsqrtf(red[0] * (1.0f/DM) + 1e-5f);
    out[(size_t)row*DM + t]       = d0*rstd*g[t]     + be[t];
    out[(size_t)row*DM + t + 256] = d1*rstd*g[t+256] + be[t+256];
}

// ---------------------------------------------------------------------------
// Mean pool + classifier
// ---------------------------------------------------------------------------
__global__ void pool1_kernel() {
    int b = blockIdx.x, r = blockIdx.y;
    int d = threadIdx.x;
    float acc = 0.f;
    for (int l = r*128; l < r*128 + 128; l++)
        acc += g_tmp[(size_t)(b*L_+l)*DM + d];
    g_poolp[(b*8 + r)*DM + d] = acc;
}

__global__ void pool2_kernel() {
    int b = blockIdx.x;
    int d = threadIdx.x;
    float acc = 0.f;
    #pragma unroll
    for (int r = 0; r < 8; r++) acc += g_poolp[(b*8 + r)*DM + d];
    g_pool[b*DM + d] = acc * (1.0f/L_);
}

__global__ void cls_kernel(const float* __restrict__ Wc,
                           const float* __restrict__ bc,
                           float* __restrict__ out) {
    int t = threadIdx.x;
    if (t >= B_*10) return;
    int b = t / 10, c = t % 10;
    float acc = bc[c];
    for (int d = 0; d < DM; d++) acc += g_pool[b*DM + d] * Wc[d*10 + c];
    out[b*10 + c] = acc;
}

// ---------------------------------------------------------------------------
extern "C" void kernel_launch(void* const* d_in, const int* in_sizes, int n_in,
                              void* d_out, int out_size) {
    const float* src   = (const float*)d_in[0];
    const int*   idxs  = (const int*)  d_in[1];
    const float* Wemb  = (const float*)d_in[2];
    const float* bemb  = (const float*)d_in[3];
    const float* Wq    = (const float*)d_in[4];
    const float* bq    = (const float*)d_in[5];
    const float* Wk    = (const float*)d_in[6];
    const float* bk    = (const float*)d_in[7];
    const float* Wv    = (const float*)d_in[8];
    const float* bv    = (const float*)d_in[9];
    const float* Wo    = (const float*)d_in[10];
    const float* bo    = (const float*)d_in[11];
    const float* g1    = (const float*)d_in[12];
    const float* beta1 = (const float*)d_in[13];
    const float* W1    = (const float*)d_in[14];
    const float* bf1   = (const float*)d_in[15];
    const float* W2    = (const float*)d_in[16];
    const float* bf2   = (const float*)d_in[17];
    const float* g2    = (const float*)d_in[18];
    const float* beta2 = (const float*)d_in[19];
    const float* gf    = (const float*)d_in[20];
    const float* betaf = (const float*)d_in[21];
    const float* Wc    = (const float*)d_in[22];
    const float* bc    = (const float*)d_in[23];

    void *px_, *ptmp_, *pq_, *pk_, *pv_, *pctx_, *pff_;
    cudaGetSymbolAddress(&px_,   g_x);
    cudaGetSymbolAddress(&ptmp_, g_tmp);
    cudaGetSymbolAddress(&pq_,   g_q);
    cudaGetSymbolAddress(&pk_,   g_k);
    cudaGetSymbolAddress(&pv_,   g_v);
    cudaGetSymbolAddress(&pctx_, g_ctx);
    cudaGetSymbolAddress(&pff_,  g_ff);
    float* px   = (float*)px_;
    float* ptmp = (float*)ptmp_;
    float* pq   = (float*)pq_;
    float* pk   = (float*)pk_;
    float* pv   = (float*)pv_;
    float* pctx = (float*)pctx_;
    float* pff  = (float*)pff_;

    const int attn_smem = ATT_SMEM_FLOATS * 4;
    cudaFuncSetAttribute(attn_fused, cudaFuncAttributeMaxDynamicSharedMemorySize, attn_smem);

    embed_kernel<<<NTOK, 512>>>(src, Wemb, bemb);

    for (int l = 0; l < 2; l++) {
        const float* Wq_l = Wq + (size_t)l*DM*DM;
        const float* Wk_l = Wk + (size_t)l*DM*DM;
        const float* Wv_l = Wv + (size_t)l*DM*DM;
        const float* Wo_l = Wo + (size_t)l*DM*DM;
        const float* W1_l = W1 + (size_t)l*DM*DFF;
        const float* W2_l = W2 + (size_t)l*DFF*DM;

        dim3 gQKV(DM/64, NTOK/128, 3);   // (8, 32, 3) = 768 blocks
        dim3 gDM64(DM/64, NTOK/128);     // (8, 32)   = 256 blocks
        dim3 gFF(DFF/128, NTOK/128);     // (16, 32)  = 512 blocks

        qkv_tc<<<gQKV, 256>>>(px, Wq_l, bq + l*DM, Wk_l, bk + l*DM,
                              Wv_l, bv + l*DM, pq, pk, pv);

        sampleM_kernel<<<(B_*NH*L_)/4, 128>>>(idxs + (size_t)l*L_*SK);
        topk_kernel<<<B_*NH, 1024>>>();
        attn_fused<<<B_*NH, ATT_THREADS, attn_smem>>>();

        gemm_tc<64, false><<<gDM64, 256>>>(pctx, Wo_l, bo + l*DM, px, ptmp, DM, DM);
        ln_kernel<<<NTOK, 256>>>(ptmp, px, g1 + l*DM, beta1 + l*DM);

        gemm_tc<128, true><<<gFF, 256>>>(px, W1_l, bf1 + l*DFF, nullptr, pff, DFF, DM);
        gemm_tc<64, false><<<gDM64, 256>>>(pff, W2_l, bf2 + l*DM, px, ptmp, DM, DFF);
        ln_kernel<<<NTOK, 256>>>(ptmp, px, g2 + l*DM, beta2 + l*DM);
    }

    ln_kernel<<<NTOK, 256>>>(px, ptmp, gf, betaf);
    pool1_kernel<<<dim3(B_, 8), 512>>>();
    pool2_kernel<<<B_, 512>>>();
    cls_kernel<<<1, 64>>>(Wc, bc, (float*)d_out);
}

// round 4
// speedup vs baseline: 1.1321x; 1.1321x over previous
#include <cuda_runtime.h>
#include <math.h>
#include <float.h>
#include <stdint.h>

// ---------------------------------------------------------------------------
// Informer: B=4, L=1024, DM=512, NH=8, HD=64, DFF=2048, SK=35, 2 layers
// ---------------------------------------------------------------------------
#define B_   4
#define L_   1024
#define DM   512
#define NH   8
#define HD   64
#define DFF  2048
#define SK   35
#define NTOK (B_*L_)   // 4096
#define SPLITK 4

__device__ float g_x   [NTOK*DM];
__device__ float g_tmp [NTOK*DM];
__device__ float g_q   [NTOK*DM];
__device__ float g_k   [NTOK*DM];
__device__ float g_v   [NTOK*DM];
__device__ float g_ctx [NTOK*DM];
__device__ float g_ff  [NTOK*DFF];
__device__ float g_split[SPLITK*NTOK*DM];
__device__ float g_M   [B_*NH*L_];
__device__ int   g_top [B_*NH*SK];
__device__ float g_poolp[B_*8*DM];
__device__ float g_pool [B_*DM];

// ---------------------------------------------------------------------------
__device__ __forceinline__ float to_tf32(float x) {
    uint32_t u;
    asm("cvt.rna.tf32.f32 %0, %1;" : "=r"(u) : "f"(x));
    return __uint_as_float(u);
}

__device__ __forceinline__ void mma_tf32(float* c, const uint32_t* a,
                                         uint32_t b0, uint32_t b1) {
    asm volatile(
        "mma.sync.aligned.m16n8k8.row.col.f32.tf32.tf32.f32 "
        "{%0,%1,%2,%3},{%4,%5,%6,%7},{%8,%9},{%0,%1,%2,%3};"
        : "+f"(c[0]), "+f"(c[1]), "+f"(c[2]), "+f"(c[3])
        : "r"(a[0]), "r"(a[1]), "r"(a[2]), "r"(a[3]), "r"(b0), "r"(b1));
}

// ---------------------------------------------------------------------------
// Embedding + positional encoding
// ---------------------------------------------------------------------------
__global__ void embed_kernel(const float* __restrict__ src,
                             const float* __restrict__ Wemb,
                             const float* __restrict__ bemb) {
    int row = blockIdx.x;
    int l   = row & (L_-1);
    int d   = threadIdx.x;
    __shared__ float s[32];
    if (d < 32) s[d] = src[row*32 + d];
    __syncthreads();
    float acc = bemb[d];
    #pragma unroll
    for (int k = 0; k < 32; k++) acc += s[k] * Wemb[k*DM + d];
    int i2 = d & ~1;
    float div = expf(-(float)i2 * (9.210340371976184f / 512.0f));
    float ang = (float)l * div;
    acc += (d & 1) ? cosf(ang) : sinf(ang);
    g_x[row*DM + d] = acc;
}

// ---------------------------------------------------------------------------
// tf32 tensor-core GEMM body. Block tile 128x128x16, 256 threads (8 warps,
// 4m x 2n). Double-buffered smem, register prefetch. lda = A row stride.
// RAW: store bare accumulators (split-K partial), no bias/resid/gelu.
// ---------------------------------------------------------------------------
template<bool GELU, bool RAW>
__device__ __forceinline__ void gemm_body(
        const float* __restrict__ A, const float* __restrict__ W,
        const float* __restrict__ bias, const float* __restrict__ resid,
        float* __restrict__ C, int N, int K, int lda, int bx, int by) {
    __shared__ float As[2][16][136];
    __shared__ float Bs[2][16][136];

    const int tid  = threadIdx.x;
    const int w    = tid >> 5;
    const int lane = tid & 31;
    const int grp  = lane >> 2;
    const int qd   = lane & 3;
    const int warp_m = (w & 3) * 32;
    const int warp_n = (w >> 2) * 64;
    const int m0 = by * 128;
    const int n0 = bx * 128;

    const int am  = tid >> 2;
    const int akc = (tid & 3) << 2;
    const int bkr = tid >> 5;
    const int bnc = (tid & 31) << 2;

    float acc[2][8][4];
    #pragma unroll
    for (int mi = 0; mi < 2; mi++)
        #pragma unroll
        for (int ni = 0; ni < 8; ni++)
            #pragma unroll
            for (int j = 0; j < 4; j++) acc[mi][ni][j] = 0.f;

    const int nt = K >> 4;

    {
        float4 ra0 = *(const float4*)&A[(size_t)(m0+am)*lda + akc];
        float4 ra1 = *(const float4*)&A[(size_t)(m0+am+64)*lda + akc];
        float4 rb0 = *(const float4*)&W[(size_t)bkr*N + n0 + bnc];
        float4 rb1 = *(const float4*)&W[(size_t)(bkr+8)*N + n0 + bnc];
        As[0][akc+0][am] = to_tf32(ra0.x); As[0][akc+1][am] = to_tf32(ra0.y);
        As[0][akc+2][am] = to_tf32(ra0.z); As[0][akc+3][am] = to_tf32(ra0.w);
        As[0][akc+0][am+64] = to_tf32(ra1.x); As[0][akc+1][am+64] = to_tf32(ra1.y);
        As[0][akc+2][am+64] = to_tf32(ra1.z); As[0][akc+3][am+64] = to_tf32(ra1.w);
        Bs[0][bkr][bnc+0] = to_tf32(rb0.x); Bs[0][bkr][bnc+1] = to_tf32(rb0.y);
        Bs[0][bkr][bnc+2] = to_tf32(rb0.z); Bs[0][bkr][bnc+3] = to_tf32(rb0.w);
        Bs[0][bkr+8][bnc+0] = to_tf32(rb1.x); Bs[0][bkr+8][bnc+1] = to_tf32(rb1.y);
        Bs[0][bkr+8][bnc+2] = to_tf32(rb1.z); Bs[0][bkr+8][bnc+3] = to_tf32(rb1.w);
    }
    __syncthreads();

    for (int t = 0; t < nt; t++) {
        const int buf = t & 1;
        const bool more = (t + 1 < nt);
        float4 ra0, ra1, rb0, rb1;
        if (more) {
            int k0 = (t+1) << 4;
            ra0 = *(const float4*)&A[(size_t)(m0+am)*lda + k0 + akc];
            ra1 = *(const float4*)&A[(size_t)(m0+am+64)*lda + k0 + akc];
            rb0 = *(const float4*)&W[(size_t)(k0+bkr)*N + n0 + bnc];
            rb1 = *(const float4*)&W[(size_t)(k0+bkr+8)*N + n0 + bnc];
        }

        #pragma unroll
        for (int kk = 0; kk < 16; kk += 8) {
            uint32_t af[2][4];
            #pragma unroll
            for (int mi = 0; mi < 2; mi++) {
                int mb = warp_m + mi*16 + grp;
                af[mi][0] = __float_as_uint(As[buf][kk+qd  ][mb]);
                af[mi][1] = __float_as_uint(As[buf][kk+qd  ][mb+8]);
                af[mi][2] = __float_as_uint(As[buf][kk+qd+4][mb]);
                af[mi][3] = __float_as_uint(As[buf][kk+qd+4][mb+8]);
            }
            #pragma unroll
            for (int ni = 0; ni < 8; ni++) {
                int nb = warp_n + ni*8 + grp;
                uint32_t b0 = __float_as_uint(Bs[buf][kk+qd  ][nb]);
                uint32_t b1 = __float_as_uint(Bs[buf][kk+qd+4][nb]);
                mma_tf32(acc[0][ni], af[0], b0, b1);
                mma_tf32(acc[1][ni], af[1], b0, b1);
            }
        }

        if (more) {
            int nb = buf ^ 1;
            As[nb][akc+0][am] = to_tf32(ra0.x); As[nb][akc+1][am] = to_tf32(ra0.y);
            As[nb][akc+2][am] = to_tf32(ra0.z); As[nb][akc+3][am] = to_tf32(ra0.w);
            As[nb][akc+0][am+64] = to_tf32(ra1.x); As[nb][akc+1][am+64] = to_tf32(ra1.y);
            As[nb][akc+2][am+64] = to_tf32(ra1.z); As[nb][akc+3][am+64] = to_tf32(ra1.w);
            Bs[nb][bkr][bnc+0] = to_tf32(rb0.x); Bs[nb][bkr][bnc+1] = to_tf32(rb0.y);
            Bs[nb][bkr][bnc+2] = to_tf32(rb0.z); Bs[nb][bkr][bnc+3] = to_tf32(rb0.w);
            Bs[nb][bkr+8][bnc+0] = to_tf32(rb1.x); Bs[nb][bkr+8][bnc+1] = to_tf32(rb1.y);
            Bs[nb][bkr+8][bnc+2] = to_tf32(rb1.z); Bs[nb][bkr+8][bnc+3] = to_tf32(rb1.w);
        }
        __syncthreads();
    }

    #pragma unroll
    for (int mi = 0; mi < 2; mi++) {
        int r0 = m0 + warp_m + mi*16 + grp;
        #pragma unroll
        for (int ni = 0; ni < 8; ni++) {
            int c = n0 + warp_n + ni*8 + qd*2;
            float v0 = acc[mi][ni][0];
            float v1 = acc[mi][ni][1];
            float v2 = acc[mi][ni][2];
            float v3 = acc[mi][ni][3];
            if (!RAW) {
                float b0 = bias[c], b1 = bias[c+1];
                v0 += b0; v1 += b1; v2 += b0; v3 += b1;
                if (resid) {
                    v0 += resid[(size_t)r0*N + c];     v1 += resid[(size_t)r0*N + c + 1];
                    v2 += resid[(size_t)(r0+8)*N + c]; v3 += resid[(size_t)(r0+8)*N + c + 1];
                }
                if (GELU) {
                    v0 = 0.5f*v0*(1.0f + erff(v0*0.70710678118654752f));
                    v1 = 0.5f*v1*(1.0f + erff(v1*0.70710678118654752f));
                    v2 = 0.5f*v2*(1.0f + erff(v2*0.70710678118654752f));
                    v3 = 0.5f*v3*(1.0f + erff(v3*0.70710678118654752f));
                }
            }
            *(float2*)&C[(size_t)r0*N + c]     = make_float2(v0, v1);
            *(float2*)&C[(size_t)(r0+8)*N + c] = make_float2(v2, v3);
        }
    }
}

template<bool GELU>
__global__ void __launch_bounds__(256, 2)
gemm_tc(const float* __restrict__ A, const float* __restrict__ W,
        const float* __restrict__ bias, const float* __restrict__ resid,
        float* __restrict__ C, int N, int K) {
    gemm_body<GELU, false>(A, W, bias, resid, C, N, K, K, blockIdx.x, blockIdx.y);
}

// Fused QKV: blockIdx.z selects projection. grid (4, 32, 3).
__global__ void __launch_bounds__(256, 2)
qkv_tc(const float* __restrict__ A,
       const float* __restrict__ Wq, const float* __restrict__ bq,
       const float* __restrict__ Wk, const float* __restrict__ bk,
       const float* __restrict__ Wv, const float* __restrict__ bv,
       float* __restrict__ Q, float* __restrict__ Ko, float* __restrict__ V) {
    const float* W; const float* bias; float* C;
    if (blockIdx.z == 0)      { W = Wq; bias = bq; C = Q;  }
    else if (blockIdx.z == 1) { W = Wk; bias = bk; C = Ko; }
    else                      { W = Wv; bias = bv; C = V;  }
    gemm_body<false, false>(A, W, bias, nullptr, C, DM, DM, DM, blockIdx.x, blockIdx.y);
}

// Split-K FF2 partial: blockIdx.z = k-chunk. A row stride DFF, K=DFF/SPLITK.
__global__ void __launch_bounds__(256, 2)
ff2_splitk(const float* __restrict__ A, const float* __restrict__ W,
           float* __restrict__ Cpart) {
    const int kc = blockIdx.z;
    gemm_body<false, true>(A + kc*(DFF/SPLITK), W + (size_t)kc*(DFF/SPLITK)*DM,
                           nullptr, nullptr, Cpart + (size_t)kc*NTOK*DM,
                           DM, DFF/SPLITK, DFF, blockIdx.x, blockIdx.y);
}

// Fused split-K reduce + bias + residual + LayerNorm. One block (256) per row.
__global__ void reduce_ln_kernel(const float* __restrict__ bias,
                                 const float* __restrict__ resid,
                                 const float* __restrict__ g,
                                 const float* __restrict__ be,
                                 float* __restrict__ out) {
    int row = blockIdx.x;
    int t   = threadIdx.x;
    size_t o0 = (size_t)row*DM + t;
    size_t o1 = o0 + 256;
    float v0 = resid[o0] + bias[t];
    float v1 = resid[o1] + bias[t+256];
    #pragma unroll
    for (int s = 0; s < SPLITK; s++) {
        v0 += g_split[(size_t)s*NTOK*DM + o0];
        v1 += g_split[(size_t)s*NTOK*DM + o1];
    }
    __shared__ float red[256];
    red[t] = v0 + v1; __syncthreads();
    for (int s = 128; s > 0; s >>= 1) { if (t < s) red[t] += red[t+s]; __syncthreads(); }
    float mean = red[0] * (1.0f/DM);
    __syncthreads();
    float d0 = v0 - mean, d1 = v1 - mean;
    red[t] = d0*d0 + d1*d1; __syncthreads();
    for (int s = 128; s > 0; s >>= 1) { if (t < s) red[t] += red[t+s]; __syncthreads(); }
    float rstd = rsqrtf(red[0] * (1.0f/DM) + 1e-5f);
    out[o0] = d0*rstd*g[t]     + be[t];
    out[o1] = d1*rstd*g[t+256] + be[t+256];
}

// ---------------------------------------------------------------------------
// Sampled sparsity measure M (one warp per (b,h,i))
// ---------------------------------------------------------------------------
__global__ void sampleM_kernel(const int* __restrict__ idxs) {
    int wg   = (blockIdx.x * blockDim.x + threadIdx.x) >> 5;
    int lane = threadIdx.x & 31;
    if (wg >= B_*NH*L_) return;
    int i = wg & (L_-1);
    int h = (wg >> 10) & (NH-1);
    int b = wg >> 13;
    const float* Qrow = &g_q[(size_t)(b*L_ + i)*DM + h*HD];
    float qa = Qrow[lane], qb = Qrow[lane+32];
    float mx = -FLT_MAX, sm = 0.f;
    for (int j = 0; j < SK; j++) {
        int s = idxs[i*SK + j];
        const float* Krow = &g_k[(size_t)(b*L_ + s)*DM + h*HD];
        float p = qa*Krow[lane] + qb*Krow[lane+32];
        #pragma unroll
        for (int o = 16; o > 0; o >>= 1) p += __shfl_xor_sync(0xffffffffu, p, o);
        mx = fmaxf(mx, p);
        sm += p;
    }
    if (lane == 0) g_M[(b*NH+h)*L_ + i] = mx - sm * (1.0f/SK);
}

// ---------------------------------------------------------------------------
// Exact top-35, single warp per (b,h). 32 values/thread in registers,
// incremental local argmax + warp argmax. Tie-break: lowest global index.
// ---------------------------------------------------------------------------
__global__ void topk_kernel() {
    int bh = blockIdx.x;
    int t  = threadIdx.x;       // 32
    float v[32];
    const float* src = &g_M[bh*L_ + t*32];
    #pragma unroll
    for (int j = 0; j < 32; j += 4) {
        float4 q = *(const float4*)&src[j];
        v[j] = q.x; v[j+1] = q.y; v[j+2] = q.z; v[j+3] = q.w;
    }
    float lmax = -FLT_MAX; int lj = 0;
    #pragma unroll
    for (int j = 0; j < 32; j++)
        if (v[j] > lmax) { lmax = v[j]; lj = j; }

    for (int iter = 0; iter < SK; iter++) {
        float bv = lmax; int bi = t*32 + lj;
        #pragma unroll
        for (int o = 16; o > 0; o >>= 1) {
            float ov = __shfl_xor_sync(0xffffffffu, bv, o);
            int   oi = __shfl_xor_sync(0xffffffffu, bi, o);
            if (ov > bv || (ov == bv && oi < bi)) { bv = ov; bi = oi; }
        }
        if (t == 0) g_top[bh*SK + iter] = bi;
        if (t == (bi >> 5)) {
            v[bi & 31] = -FLT_MAX;
            lmax = -FLT_MAX; lj = 0;
            #pragma unroll
            for (int j = 0; j < 32; j++)
                if (v[j] > lmax) { lmax = v[j]; lj = j; }
        }
    }
}

// ---------------------------------------------------------------------------
// Fused attention per (b,h): vmean + broadcast fill + scores + softmax + ctx
// ---------------------------------------------------------------------------
#define ATT_THREADS 512
#define SQ_ROWS 48
#define ATT_SMEM_FLOATS (35*1024 + SQ_ROWS*64 + 64*129 + 64 + 512 + 64)

__global__ void __launch_bounds__(ATT_THREADS, 1)
attn_fused() {
    extern __shared__ float dsm[];
    float* scores = dsm;
    float* sq     = scores + 35*1024;
    float* kt     = sq + SQ_ROWS*64;
    float* vmean  = kt + 64*129;
    float* red    = vmean + 64;
    int*   tops   = (int*)(red + 512);

    const int bh = blockIdx.x;
    const int b  = bh >> 3;
    const int h  = bh & 7;
    const int t  = threadIdx.x;
    const int lane = t & 31;
    const int w  = t >> 5;

    if (t < SK) tops[t] = g_top[bh*SK + t];
    __syncthreads();

    for (int f = t; f < SQ_ROWS*64; f += ATT_THREADS) {
        int u = f >> 6, k = f & 63;
        sq[f] = (u < SK) ? g_q[(size_t)((b<<10) + tops[u])*DM + h*HD + k] : 0.f;
    }

    {
        int e = t & 63, r = t >> 6;
        float acc = 0.f;
        for (int l = r*128; l < r*128 + 128; l++)
            acc += g_v[(size_t)((b<<10) + l)*DM + h*HD + e];
        red[t] = acc;
        __syncthreads();
        if (t < 64) {
            float s = 0.f;
            #pragma unroll
            for (int rr = 0; rr < 8; rr++) s += red[t + rr*64];
            vmean[t] = s * (1.0f/L_);
        }
        __syncthreads();
    }

    {
        const float4* vm4 = (const float4*)vmean;
        for (int f = t; f < (L_*HD)/4; f += ATT_THREADS) {
            int l = f >> 4, ev = f & 15;
            *(float4*)&g_ctx[(size_t)((b<<10) + l)*DM + h*HD + ev*4] = vm4[ev];
        }
    }

    for (int st = 0; st < 8; st++) {
        #pragma unroll
        for (int i = 0; i < 4; i++) {
            int f = t + i*ATT_THREADS;
            int s = f >> 4, ec = (f & 15) << 2;
            float4 kv = *(const float4*)&g_k[(size_t)((b<<10) + st*128 + s)*DM + h*HD + ec];
            kt[(ec+0)*129 + s] = kv.x;
            kt[(ec+1)*129 + s] = kv.y;
            kt[(ec+2)*129 + s] = kv.z;
            kt[(ec+3)*129 + s] = kv.w;
        }
        __syncthreads();

        float acc[3][4];
        #pragma unroll
        for (int uu = 0; uu < 3; uu++)
            #pragma unroll
            for (int j = 0; j < 4; j++) acc[uu][j] = 0.f;

        for (int k = 0; k < 64; k++) {
            float kv0 = kt[k*129 + lane];
            float kv1 = kt[k*129 + lane + 32];
            float kv2 = kt[k*129 + lane + 64];
            float kv3 = kt[k*129 + lane + 96];
            #pragma unroll
            for (int uu = 0; uu < 3; uu++) {
                float qv = sq[(uu*16 + w)*64 + k];
                acc[uu][0] += qv*kv0; acc[uu][1] += qv*kv1;
                acc[uu][2] += qv*kv2; acc[uu][3] += qv*kv3;
            }
        }
        #pragma unroll
        for (int uu = 0; uu < 3; uu++) {
            int u = uu*16 + w;
            if (u < SK) {
                scores[u*1024 + st*128 + lane]      = acc[uu][0]*0.125f;
                scores[u*1024 + st*128 + lane + 32] = acc[uu][1]*0.125f;
                scores[u*1024 + st*128 + lane + 64] = acc[uu][2]*0.125f;
                scores[u*1024 + st*128 + lane + 96] = acc[uu][3]*0.125f;
            }
        }
        __syncthreads();
    }

    for (int u = w; u < SK; u += 16) {
        float* row = &scores[u*1024];
        float m = -FLT_MAX;
        #pragma unroll
        for (int i = 0; i < 32; i++) m = fmaxf(m, row[lane + 32*i]);
        #pragma unroll
        for (int o = 16; o > 0; o >>= 1) m = fmaxf(m, __shfl_xor_sync(0xffffffffu, m, o));
        float s = 0.f;
        #pragma unroll
        for (int i = 0; i < 32; i++) {
            float e = expf(row[lane + 32*i] - m);
            row[lane + 32*i] = e;
            s += e;
        }
        #pragma unroll
        for (int o = 16; o > 0; o >>= 1) s += __shfl_xor_sync(0xffffffffu, s, o);
        float inv = 1.0f / s;
        #pragma unroll
        for (int i = 0; i < 32; i++) row[lane + 32*i] *= inv;
    }
    __syncthreads();

    {
        int e = t & 63, ug = t >> 6;
        float acc9[5] = {0.f, 0.f, 0.f, 0.f, 0.f};
        for (int st = 0; st < 8; st++) {
            #pragma unroll
            for (int i = 0; i < 4; i++) {
                int f = t + i*ATT_THREADS;
                int s = f >> 4, ec = (f & 15) << 2;
                float4 vv = *(const float4*)&g_v[(size_t)((b<<10) + st*128 + s)*DM + h*HD + ec];
                kt[(ec+0)*129 + s] = vv.x;
                kt[(ec+1)*129 + s] = vv.y;
                kt[(ec+2)*129 + s] = vv.z;
                kt[(ec+3)*129 + s] = vv.w;
            }
            __syncthreads();
            for (int s = 0; s < 128; s++) {
                float v = kt[e*129 + s];
                #pragma unroll
                for (int uu = 0; uu < 5; uu++) {
                    int u = ug + (uu << 3);
                    if (u < SK) acc9[uu] += scores[u*1024 + st*128 + s] * v;
                }
            }
            __syncthreads();
        }
        #pragma unroll
        for (int uu = 0; uu < 5; uu++) {
            int u = ug + (uu << 3);
            if (u < SK) {
                int qi = tops[u];
                g_ctx[(size_t)((b<<10) + qi)*DM + h*HD + e] = acc9[uu];
            }
        }
    }
}

// ---------------------------------------------------------------------------
// LayerNorm (row of 512, 256 threads)
// ---------------------------------------------------------------------------
__global__ void ln_kernel(const float* __restrict__ in, float* __restrict__ out,
                          const float* __restrict__ g, const float* __restrict__ be) {
    int row = blockIdx.x;
    int t   = threadIdx.x;
    float v0 = in[(size_t)row*DM + t];
    float v1 = in[(size_t)row*DM + t + 256];
    __shared__ float red[256];
    red[t] = v0 + v1; __syncthreads();
    for (int s = 128; s > 0; s >>= 1) { if (t < s) red[t] += red[t+s]; __syncthreads(); }
    float mean = red[0] * (1.0f/DM);
    __syncthreads();
    float d0 = v0 - mean, d1 = v1 - mean;
    red[t] = d0*d0 + d1*d1; __syncthreads();
    for (int s = 128; s > 0; s >>= 1) { if (t < s) red[t] += red[t+s]; __syncthreads(); }
    float rstd = rsqrtf(red[0] * (1.0f/DM) + 1e-5f);
    out[(size_t)row*DM + t]       = d0*rstd*g[t]     + be[t];
    out[(size_t)row*DM + t + 256] = d1*rstd*g[t+256] + be[t+256];
}

// ---------------------------------------------------------------------------
// Mean pool + classifier
// ---------------------------------------------------------------------------
__global__ void pool1_kernel() {
    int b = blockIdx.x, r = blockIdx.y;
    int d = threadIdx.x;
    float acc = 0.f;
    for (int l = r*128; l < r*128 + 128; l++)
        acc += g_tmp[(size_t)(b*L_+l)*DM + d];
    g_poolp[(b*8 + r)*DM + d] = acc;
}

__global__ void pool2_kernel() {
    int b = blockIdx.x;
    int d = threadIdx.x;
    float acc = 0.f;
    #pragma unroll
    for (int r = 0; r < 8; r++) acc += g_poolp[(b*8 + r)*DM + d];
    g_pool[b*DM + d] = acc * (1.0f/L_);
}

__global__ void cls_kernel(const float* __restrict__ Wc,
                           const float* __restrict__ bc,
                           float* __restrict__ out) {
    int t = threadIdx.x;
    if (t >= B_*10) return;
    int b = t / 10, c = t % 10;
    float acc = bc[c];
    for (int d = 0; d < DM; d++) acc += g_pool[b*DM + d] * Wc[d*10 + c];
    out[b*10 + c] = acc;
}

// ---------------------------------------------------------------------------
extern "C" void kernel_launch(void* const* d_in, const int* in_sizes, int n_in,
                              void* d_out, int out_size) {
    const float* src   = (const float*)d_in[0];
    const int*   idxs  = (const int*)  d_in[1];
    const float* Wemb  = (const float*)d_in[2];
    const float* bemb  = (const float*)d_in[3];
    const float* Wq    = (const float*)d_in[4];
    const float* bq    = (const float*)d_in[5];
    const float* Wk    = (const float*)d_in[6];
    const float* bk    = (const float*)d_in[7];
    const float* Wv    = (const float*)d_in[8];
    const float* bv    = (const float*)d_in[9];
    const float* Wo    = (const float*)d_in[10];
    const float* bo    = (const float*)d_in[11];
    const float* g1    = (const float*)d_in[12];
    const float* beta1 = (const float*)d_in[13];
    const float* W1    = (const float*)d_in[14];
    const float* bf1   = (const float*)d_in[15];
    const float* W2    = (const float*)d_in[16];
    const float* bf2   = (const float*)d_in[17];
    const float* g2    = (const float*)d_in[18];
    const float* beta2 = (const float*)d_in[19];
    const float* gf    = (const float*)d_in[20];
    const float* betaf = (const float*)d_in[21];
    const float* Wc    = (const float*)d_in[22];
    const float* bc    = (const float*)d_in[23];

    void *px_, *ptmp_, *pq_, *pk_, *pv_, *pctx_, *pff_, *psp_;
    cudaGetSymbolAddress(&px_,   g_x);
    cudaGetSymbolAddress(&ptmp_, g_tmp);
    cudaGetSymbolAddress(&pq_,   g_q);
    cudaGetSymbolAddress(&pk_,   g_k);
    cudaGetSymbolAddress(&pv_,   g_v);
    cudaGetSymbolAddress(&pctx_, g_ctx);
    cudaGetSymbolAddress(&pff_,  g_ff);
    cudaGetSymbolAddress(&psp_,  g_split);
    float* px   = (float*)px_;
    float* ptmp = (float*)ptmp_;
    float* pq   = (float*)pq_;
    float* pk   = (float*)pk_;
    float* pv   = (float*)pv_;
    float* pctx = (float*)pctx_;
    float* pff  = (float*)pff_;
    float* psp  = (float*)psp_;

    const int attn_smem = ATT_SMEM_FLOATS * 4;
    cudaFuncSetAttribute(attn_fused, cudaFuncAttributeMaxDynamicSharedMemorySize, attn_smem);

    embed_kernel<<<NTOK, 512>>>(src, Wemb, bemb);

    for (int l = 0; l < 2; l++) {
        const float* Wq_l = Wq + (size_t)l*DM*DM;
        const float* Wk_l = Wk + (size_t)l*DM*DM;
        const float* Wv_l = Wv + (size_t)l*DM*DM;
        const float* Wo_l = Wo + (size_t)l*DM*DM;
        const float* W1_l = W1 + (size_t)l*DM*DFF;
        const float* W2_l = W2 + (size_t)l*DFF*DM;

        dim3 gQKV(DM/128, NTOK/128, 3);      // (4, 32, 3) = 384 blocks
        dim3 gDM(DM/128, NTOK/128);          // (4, 32)
        dim3 gFF(DFF/128, NTOK/128);         // (16, 32)
        dim3 gSP(DM/128, NTOK/128, SPLITK);  // (4, 32, 4) = 512 blocks

        qkv_tc<<<gQKV, 256>>>(px, Wq_l, bq + l*DM, Wk_l, bk + l*DM,
                              Wv_l, bv + l*DM, pq, pk, pv);

        sampleM_kernel<<<(B_*NH*L_)/4, 128>>>(idxs + (size_t)l*L_*SK);
        topk_kernel<<<B_*NH, 32>>>();
        attn_fused<<<B_*NH, ATT_THREADS, attn_smem>>>();

        gemm_tc<false><<<gDM, 256>>>(pctx, Wo_l, bo + l*DM, px, ptmp, DM, DM);
        ln_kernel<<<NTOK, 256>>>(ptmp, px, g1 + l*DM, beta1 + l*DM);

        gemm_tc<true><<<gFF, 256>>>(px, W1_l, bf1 + l*DFF, nullptr, pff, DFF, DM);
        ff2_splitk<<<gSP, 256>>>(pff, W2_l, psp);
        reduce_ln_kernel<<<NTOK, 256>>>(bf2 + l*DM, px, g2 + l*DM, beta2 + l*DM, px);
    }

    ln_kernel<<<NTOK, 256>>>(px, ptmp, gf, betaf);
    pool1_kernel<<<dim3(B_, 8), 512>>>();
    pool2_kernel<<<B_, 512>>>();
    cls_kernel<<<1, 64>>>(Wc, bc, (float*)d_out);
}

// round 5
// speedup vs baseline: 1.2378x; 1.0933x over previous
#include <cuda_runtime.h>
#include <math.h>
#include <float.h>
#include <stdint.h>

// ---------------------------------------------------------------------------
// Informer: B=4, L=1024, DM=512, NH=8, HD=64, DFF=2048, SK=35, 2 layers
// ---------------------------------------------------------------------------
#define B_   4
#define L_   1024
#define DM   512
#define NH   8
#define HD   64
#define DFF  2048
#define SK   35
#define NTOK (B_*L_)   // 4096
#define SPLITK 4
#define GS 3           // cp.async pipeline stages

__device__ float g_x   [NTOK*DM];
__device__ float g_tmp [NTOK*DM];
__device__ float g_q   [NTOK*DM];
__device__ float g_k   [NTOK*DM];
__device__ float g_v   [NTOK*DM];
__device__ float g_ctx [NTOK*DM];
__device__ float g_ff  [NTOK*DFF];
__device__ float g_split[SPLITK*NTOK*DM];
__device__ float g_M   [B_*NH*L_];
__device__ float g_poolp[B_*8*DM];
__device__ float g_pool [B_*DM];
// pre-rounded (tf32-rna) weights: Wq|Wk|Wv|Wo (both layers each) then W1, W2
#define WR_TOTAL (4*2*DM*DM + 2*DM*DFF + 2*DFF*DM)
__device__ float g_wr[WR_TOTAL];

// ---------------------------------------------------------------------------
__device__ __forceinline__ float to_tf32(float x) {
    uint32_t u;
    asm("cvt.rna.tf32.f32 %0, %1;" : "=r"(u) : "f"(x));
    return __uint_as_float(u);
}

__device__ __forceinline__ void mma_tf32(float* c, const uint32_t* a,
                                         uint32_t b0, uint32_t b1) {
    asm volatile(
        "mma.sync.aligned.m16n8k8.row.col.f32.tf32.tf32.f32 "
        "{%0,%1,%2,%3},{%4,%5,%6,%7},{%8,%9},{%0,%1,%2,%3};"
        : "+f"(c[0]), "+f"(c[1]), "+f"(c[2]), "+f"(c[3])
        : "r"(a[0]), "r"(a[1]), "r"(a[2]), "r"(a[3]), "r"(b0), "r"(b1));
}

__device__ __forceinline__ void cp16(void* smem, const void* g) {
    uint32_t s = (uint32_t)__cvta_generic_to_shared(smem);
    asm volatile("cp.async.cg.shared.global [%0], [%1], 16;\n" :: "r"(s), "l"(g));
}
#define CP_COMMIT() asm volatile("cp.async.commit_group;\n" ::: "memory")
#define CP_WAIT1()  asm volatile("cp.async.wait_group 1;\n" ::: "memory")

// ---------------------------------------------------------------------------
// Pre-round all weights to tf32 (rna) into g_wr. float4 grid-stride.
// ---------------------------------------------------------------------------
__global__ void round_weights(const float* __restrict__ Wq, const float* __restrict__ Wk,
                              const float* __restrict__ Wv, const float* __restrict__ Wo,
                              const float* __restrict__ W1, const float* __restrict__ W2) {
    const int QS = 2*DM*DM;          // 524288 per projection (both layers)
    int i4 = blockIdx.x * blockDim.x + threadIdx.x;
    int f  = i4 * 4;
    if (f >= WR_TOTAL) return;
    const float* src;
    int off;
    if      (f < QS)      { src = Wq; off = f; }
    else if (f < 2*QS)    { src = Wk; off = f - QS; }
    else if (f < 3*QS)    { src = Wv; off = f - 2*QS; }
    else if (f < 4*QS)    { src = Wo; off = f - 3*QS; }
    else if (f < 4*QS + 2*DM*DFF) { src = W1; off = f - 4*QS; }
    else                  { src = W2; off = f - 4*QS - 2*DM*DFF; }
    float4 v = *(const float4*)&src[off];
    v.x = to_tf32(v.x); v.y = to_tf32(v.y); v.z = to_tf32(v.z); v.w = to_tf32(v.w);
    *(float4*)&g_wr[f] = v;
}

// ---------------------------------------------------------------------------
// Embedding + positional encoding (output rounded to tf32 — feeds QKV GEMM)
// ---------------------------------------------------------------------------
__global__ void embed_kernel(const float* __restrict__ src,
                             const float* __restrict__ Wemb,
                             const float* __restrict__ bemb) {
    int row = blockIdx.x;
    int l   = row & (L_-1);
    int d   = threadIdx.x;
    __shared__ float s[32];
    if (d < 32) s[d] = src[row*32 + d];
    __syncthreads();
    float acc = bemb[d];
    #pragma unroll
    for (int k = 0; k < 32; k++) acc += s[k] * Wemb[k*DM + d];
    int i2 = d & ~1;
    float div = expf(-(float)i2 * (9.210340371976184f / 512.0f));
    float ang = (float)l * div;
    acc += (d & 1) ? cosf(ang) : sinf(ang);
    g_x[row*DM + d] = to_tf32(acc);
}

// ---------------------------------------------------------------------------
// tf32 GEMM, cp.async 3-stage pipeline. Block tile 128x128x16, 256 threads.
// A layout [m][20] (pad), B layout [k][136]. Inputs must be pre-rounded tf32.
// ---------------------------------------------------------------------------
#define AS(s,m,k) As[(s)*2560 + (m)*20 + (k)]
#define BS(s,k,n) Bs[(s)*2176 + (k)*136 + (n)]
#define GEMM_SMEM ((GS*2560 + GS*2176) * 4)    // 56832 bytes

__device__ __forceinline__ void issue_tile(
        float* As, float* Bs, const float* A, const float* W,
        int lda, int N, int m0, int n0, int k0, int s, int tid) {
    int f0 = tid, f1 = tid + 256;
    int ma0 = f0 >> 2, kc0 = (f0 & 3) << 2;
    int ma1 = f1 >> 2, kc1 = (f1 & 3) << 2;
    cp16(&AS(s,ma0,kc0), A + (size_t)(m0+ma0)*lda + k0 + kc0);
    cp16(&AS(s,ma1,kc1), A + (size_t)(m0+ma1)*lda + k0 + kc1);
    int kr0 = f0 >> 5, nc0 = (f0 & 31) << 2;
    int kr1 = f1 >> 5, nc1 = (f1 & 31) << 2;
    cp16(&BS(s,kr0,nc0), W + (size_t)(k0+kr0)*N + n0 + nc0);
    cp16(&BS(s,kr1,nc1), W + (size_t)(k0+kr1)*N + n0 + nc1);
}

template<bool GELU, bool RAW, bool RND>
__device__ __forceinline__ void gemm_body(
        const float* __restrict__ A, const float* __restrict__ W,
        const float* __restrict__ bias, const float* __restrict__ resid,
        float* __restrict__ C, int N, int K, int lda, int bx, int by) {
    extern __shared__ float gsm[];
    float* As = gsm;
    float* Bs = gsm + GS*2560;

    const int tid  = threadIdx.x;
    const int w    = tid >> 5;
    const int lane = tid & 31;
    const int grp  = lane >> 2;
    const int qd   = lane & 3;
    const int warp_m = (w & 3) * 32;
    const int warp_n = (w >> 2) * 64;
    const int m0 = by * 128;
    const int n0 = bx * 128;

    float acc[2][8][4];
    #pragma unroll
    for (int mi = 0; mi < 2; mi++)
        #pragma unroll
        for (int ni = 0; ni < 8; ni++)
            #pragma unroll
            for (int j = 0; j < 4; j++) acc[mi][ni][j] = 0.f;

    const int nt = K >> 4;

    issue_tile(As, Bs, A, W, lda, N, m0, n0, 0, 0, tid);  CP_COMMIT();
    issue_tile(As, Bs, A, W, lda, N, m0, n0, 16, 1, tid); CP_COMMIT();

    for (int t = 0; t < nt; t++) {
        CP_WAIT1();
        __syncthreads();
        const int s = t % GS;
        if (t + 2 < nt)
            issue_tile(As, Bs, A, W, lda, N, m0, n0, (t+2) << 4, (t+2) % GS, tid);
        CP_COMMIT();

        #pragma unroll
        for (int kk = 0; kk < 16; kk += 8) {
            uint32_t af[2][4];
            #pragma unroll
            for (int mi = 0; mi < 2; mi++) {
                int mb = warp_m + mi*16 + grp;
                af[mi][0] = __float_as_uint(AS(s, mb,   kk+qd));
                af[mi][1] = __float_as_uint(AS(s, mb+8, kk+qd));
                af[mi][2] = __float_as_uint(AS(s, mb,   kk+qd+4));
                af[mi][3] = __float_as_uint(AS(s, mb+8, kk+qd+4));
            }
            #pragma unroll
            for (int ni = 0; ni < 8; ni++) {
                int nb = warp_n + ni*8 + grp;
                uint32_t b0 = __float_as_uint(BS(s, kk+qd,   nb));
                uint32_t b1 = __float_as_uint(BS(s, kk+qd+4, nb));
                mma_tf32(acc[0][ni], af[0], b0, b1);
                mma_tf32(acc[1][ni], af[1], b0, b1);
            }
        }
    }

    #pragma unroll
    for (int mi = 0; mi < 2; mi++) {
        int r0 = m0 + warp_m + mi*16 + grp;
        #pragma unroll
        for (int ni = 0; ni < 8; ni++) {
            int c = n0 + warp_n + ni*8 + qd*2;
            float v0 = acc[mi][ni][0];
            float v1 = acc[mi][ni][1];
            float v2 = acc[mi][ni][2];
            float v3 = acc[mi][ni][3];
            if (!RAW) {
                float b0 = bias[c], b1 = bias[c+1];
                v0 += b0; v1 += b1; v2 += b0; v3 += b1;
                if (resid) {
                    v0 += resid[(size_t)r0*N + c];     v1 += resid[(size_t)r0*N + c + 1];
                    v2 += resid[(size_t)(r0+8)*N + c]; v3 += resid[(size_t)(r0+8)*N + c + 1];
                }
                if (GELU) {
                    v0 = 0.5f*v0*(1.0f + erff(v0*0.70710678118654752f));
                    v1 = 0.5f*v1*(1.0f + erff(v1*0.70710678118654752f));
                    v2 = 0.5f*v2*(1.0f + erff(v2*0.70710678118654752f));
                    v3 = 0.5f*v3*(1.0f + erff(v3*0.70710678118654752f));
                }
            }
            if (RND) {
                v0 = to_tf32(v0); v1 = to_tf32(v1);
                v2 = to_tf32(v2); v3 = to_tf32(v3);
            }
            *(float2*)&C[(size_t)r0*N + c]     = make_float2(v0, v1);
            *(float2*)&C[(size_t)(r0+8)*N + c] = make_float2(v2, v3);
        }
    }
}

template<bool GELU, bool RND>
__global__ void __launch_bounds__(256, 2)
gemm_tc(const float* __restrict__ A, const float* __restrict__ W,
        const float* __restrict__ bias, const float* __restrict__ resid,
        float* __restrict__ C, int N, int K) {
    gemm_body<GELU, false, RND>(A, W, bias, resid, C, N, K, K, blockIdx.x, blockIdx.y);
}

// Fused QKV: blockIdx.z selects projection (weights from g_wr).
__global__ void __launch_bounds__(256, 2)
qkv_tc(const float* __restrict__ A, int layer,
       const float* __restrict__ bq, const float* __restrict__ bk,
       const float* __restrict__ bv,
       float* __restrict__ Q, float* __restrict__ Ko, float* __restrict__ V) {
    const float* W; const float* bias; float* C;
    const int QS = 2*DM*DM;
    size_t loff = (size_t)layer*DM*DM;
    if (blockIdx.z == 0)      { W = g_wr + loff;        bias = bq; C = Q;  }
    else if (blockIdx.z == 1) { W = g_wr + QS + loff;   bias = bk; C = Ko; }
    else                      { W = g_wr + 2*QS + loff; bias = bv; C = V;  }
    gemm_body<false, false, false>(A, W, bias, nullptr, C, DM, DM, DM,
                                   blockIdx.x, blockIdx.y);
}

// Split-K FF2 partial: blockIdx.z = k-chunk.
__global__ void __launch_bounds__(256, 2)
ff2_splitk(const float* __restrict__ A, const float* __restrict__ W,
           float* __restrict__ Cpart) {
    const int kc = blockIdx.z;
    gemm_body<false, true, false>(A + kc*(DFF/SPLITK), W + (size_t)kc*(DFF/SPLITK)*DM,
                                  nullptr, nullptr, Cpart + (size_t)kc*NTOK*DM,
                                  DM, DFF/SPLITK, DFF, blockIdx.x, blockIdx.y);
}

// Fused split-K reduce + bias + residual + LayerNorm (output rounded).
__global__ void reduce_ln_kernel(const float* __restrict__ bias,
                                 const float* __restrict__ resid,
                                 const float* __restrict__ g,
                                 const float* __restrict__ be,
                                 float* __restrict__ out) {
    int row = blockIdx.x;
    int t   = threadIdx.x;
    size_t o0 = (size_t)row*DM + t;
    size_t o1 = o0 + 256;
    float v0 = resid[o0] + bias[t];
    float v1 = resid[o1] + bias[t+256];
    #pragma unroll
    for (int s = 0; s < SPLITK; s++) {
        v0 += g_split[(size_t)s*NTOK*DM + o0];
        v1 += g_split[(size_t)s*NTOK*DM + o1];
    }
    __shared__ float red[256];
    red[t] = v0 + v1; __syncthreads();
    for (int s = 128; s > 0; s >>= 1) { if (t < s) red[t] += red[t+s]; __syncthreads(); }
    float mean = red[0] * (1.0f/DM);
    __syncthreads();
    float d0 = v0 - mean, d1 = v1 - mean;
    red[t] = d0*d0 + d1*d1; __syncthreads();
    for (int s = 128; s > 0; s >>= 1) { if (t < s) red[t] += red[t+s]; __syncthreads(); }
    float rstd = rsqrtf(red[0] * (1.0f/DM) + 1e-5f);
    out[o0] = to_tf32(d0*rstd*g[t]     + be[t]);
    out[o1] = to_tf32(d1*rstd*g[t+256] + be[t+256]);
}

// ---------------------------------------------------------------------------
// Sampled sparsity measure M (one warp per (b,h,i))
// ---------------------------------------------------------------------------
__global__ void sampleM_kernel(const int* __restrict__ idxs) {
    int wg   = (blockIdx.x * blockDim.x + threadIdx.x) >> 5;
    int lane = threadIdx.x & 31;
    if (wg >= B_*NH*L_) return;
    int i = wg & (L_-1);
    int h = (wg >> 10) & (NH-1);
    int b = wg >> 13;
    const float* Qrow = &g_q[(size_t)(b*L_ + i)*DM + h*HD];
    float qa = Qrow[lane], qb = Qrow[lane+32];
    float mx = -FLT_MAX, sm = 0.f;
    for (int j = 0; j < SK; j++) {
        int s = idxs[i*SK + j];
        const float* Krow = &g_k[(size_t)(b*L_ + s)*DM + h*HD];
        float p = qa*Krow[lane] + qb*Krow[lane+32];
        #pragma unroll
        for (int o = 16; o > 0; o >>= 1) p += __shfl_xor_sync(0xffffffffu, p, o);
        mx = fmaxf(mx, p);
        sm += p;
    }
    if (lane == 0) g_M[(b*NH+h)*L_ + i] = mx - sm * (1.0f/SK);
}

// ---------------------------------------------------------------------------
// Fused attention per (b,h): radix-select top-35 + vmean + fill + scores +
// softmax + ctx. Grid = 32 blocks, 512 threads, ~187KB dynamic smem.
// ---------------------------------------------------------------------------
#define ATT_THREADS 512
#define SQ_ROWS 48
#define ATT_SMEM_FLOATS (35*1024 + SQ_ROWS*64 + 64*129 + 64 + 512 + 64)

__device__ __forceinline__ uint32_t f2ord(float f) {
    uint32_t u = __float_as_uint(f);
    return (u & 0x80000000u) ? ~u : (u | 0x80000000u);
}

__global__ void __launch_bounds__(ATT_THREADS, 1)
attn_fused() {
    extern __shared__ float dsm[];
    float* scores = dsm;                          // 35*1024
    float* sq     = scores + 35*1024;             // 48*64
    float* kt     = sq + SQ_ROWS*64;              // 64*129
    float* vmean  = kt + 64*129;                  // 64
    float* red    = vmean + 64;                   // 512
    int*   tops   = (int*)(red + 512);            // 48

    const int bh = blockIdx.x;
    const int b  = bh >> 3;
    const int h  = bh & 7;
    const int t  = threadIdx.x;
    const int lane = t & 31;
    const int w  = t >> 5;

    // ---- exact top-35 via MSB radix select (set semantics; ties -> low idx)
    {
        __shared__ int s_cntA[32];
        __shared__ int s_gt, s_tn;
        int* ties = (int*)scores;                 // scratch before scores used
        uint32_t u0 = f2ord(g_M[bh*L_ + t]);
        uint32_t u1 = f2ord(g_M[bh*L_ + t + 512]);
        if (t < 32) s_cntA[t] = 0;
        if (t == 0) { s_gt = 0; s_tn = 0; }
        __syncthreads();
        uint32_t prefix = 0;
        int need = SK;
        for (int bit = 31; bit >= 0; --bit) {
            uint32_t cd = (prefix >> bit) | 1u;
            int c = ((u0 >> bit) == cd) + ((u1 >> bit) == cd);
            int ws = __reduce_add_sync(0xffffffffu, c);
            if (lane == 0 && ws) atomicAdd(&s_cntA[bit], ws);
            __syncthreads();
            int cnt = s_cntA[bit];
            if (cnt >= need) prefix |= (1u << bit);
            else             need -= cnt;
        }
        // collect: strictly greater -> in; equal -> tie candidates
        if (u0 > prefix) tops[atomicAdd(&s_gt, 1)] = t;
        else if (u0 == prefix) ties[atomicAdd(&s_tn, 1)] = t;
        if (u1 > prefix) tops[atomicAdd(&s_gt, 1)] = t + 512;
        else if (u1 == prefix) ties[atomicAdd(&s_tn, 1)] = t + 512;
        __syncthreads();
        if (t == 0) {
            int base = s_gt, tn = s_tn;
            for (int sel = 0; sel < need; sel++) {
                int bi = -1, bvv = 0x7fffffff;
                for (int j = 0; j < tn; j++)
                    if (ties[j] < bvv) { bvv = ties[j]; bi = j; }
                tops[base + sel] = bvv;
                ties[bi] = 0x7fffffff;
            }
        }
        __syncthreads();
    }

    // ---- selected Q rows (rows >= SK zero)
    for (int f = t; f < SQ_ROWS*64; f += ATT_THREADS) {
        int u = f >> 6, k = f & 63;
        sq[f] = (u < SK) ? g_q[(size_t)((b<<10) + tops[u])*DM + h*HD + k] : 0.f;
    }

    // ---- vmean
    {
        int e = t & 63, r = t >> 6;
        float acc = 0.f;
        for (int l = r*128; l < r*128 + 128; l++)
            acc += g_v[(size_t)((b<<10) + l)*DM + h*HD + e];
        red[t] = acc;
        __syncthreads();
        if (t < 64) {
            float s = 0.f;
            #pragma unroll
            for (int rr = 0; rr < 8; rr++) s += red[t + rr*64];
            vmean[t] = to_tf32(s * (1.0f/L_));
        }
        __syncthreads();
    }

    // ---- broadcast fill ctx
    {
        const float4* vm4 = (const float4*)vmean;
        for (int f = t; f < (L_*HD)/4; f += ATT_THREADS) {
            int l = f >> 4, ev = f & 15;
            *(float4*)&g_ctx[(size_t)((b<<10) + l)*DM + h*HD + ev*4] = vm4[ev];
        }
    }

    // ---- scores
    for (int st = 0; st < 8; st++) {
        #pragma unroll
        for (int i = 0; i < 4; i++) {
            int f = t + i*ATT_THREADS;
            int s = f >> 4, ec = (f & 15) << 2;
            float4 kv = *(const float4*)&g_k[(size_t)((b<<10) + st*128 + s)*DM + h*HD + ec];
            kt[(ec+0)*129 + s] = kv.x;
            kt[(ec+1)*129 + s] = kv.y;
            kt[(ec+2)*129 + s] = kv.z;
            kt[(ec+3)*129 + s] = kv.w;
        }
        __syncthreads();

        float acc[3][4];
        #pragma unroll
        for (int uu = 0; uu < 3; uu++)
            #pragma unroll
            for (int j = 0; j < 4; j++) acc[uu][j] = 0.f;

        for (int k = 0; k < 64; k++) {
            float kv0 = kt[k*129 + lane];
            float kv1 = kt[k*129 + lane + 32];
            float kv2 = kt[k*129 + lane + 64];
            float kv3 = kt[k*129 + lane + 96];
            #pragma unroll
            for (int uu = 0; uu < 3; uu++) {
                float qv = sq[(uu*16 + w)*64 + k];
                acc[uu][0] += qv*kv0; acc[uu][1] += qv*kv1;
                acc[uu][2] += qv*kv2; acc[uu][3] += qv*kv3;
            }
        }
        #pragma unroll
        for (int uu = 0; uu < 3; uu++) {
            int u = uu*16 + w;
            if (u < SK) {
                scores[u*1024 + st*128 + lane]      = acc[uu][0]*0.125f;
                scores[u*1024 + st*128 + lane + 32] = acc[uu][1]*0.125f;
                scores[u*1024 + st*128 + lane + 64] = acc[uu][2]*0.125f;
                scores[u*1024 + st*128 + lane + 96] = acc[uu][3]*0.125f;
            }
        }
        __syncthreads();
    }

    // ---- softmax
    for (int u = w; u < SK; u += 16) {
        float* row = &scores[u*1024];
        float m = -FLT_MAX;
        #pragma unroll
        for (int i = 0; i < 32; i++) m = fmaxf(m, row[lane + 32*i]);
        #pragma unroll
        for (int o = 16; o > 0; o >>= 1) m = fmaxf(m, __shfl_xor_sync(0xffffffffu, m, o));
        float s = 0.f;
        #pragma unroll
        for (int i = 0; i < 32; i++) {
            float e = expf(row[lane + 32*i] - m);
            row[lane + 32*i] = e;
            s += e;
        }
        #pragma unroll
        for (int o = 16; o > 0; o >>= 1) s += __shfl_xor_sync(0xffffffffu, s, o);
        float inv = 1.0f / s;
        #pragma unroll
        for (int i = 0; i < 32; i++) row[lane + 32*i] *= inv;
    }
    __syncthreads();

    // ---- ctx = probs @ V (scatter, rounded)
    {
        int e = t & 63, ug = t >> 6;
        float acc9[5] = {0.f, 0.f, 0.f, 0.f, 0.f};
        for (int st = 0; st < 8; st++) {
            #pragma unroll
            for (int i = 0; i < 4; i++) {
                int f = t + i*ATT_THREADS;
                int s = f >> 4, ec = (f & 15) << 2;
                float4 vv = *(const float4*)&g_v[(size_t)((b<<10) + st*128 + s)*DM + h*HD + ec];
                kt[(ec+0)*129 + s] = vv.x;
                kt[(ec+1)*129 + s] = vv.y;
                kt[(ec+2)*129 + s] = vv.z;
                kt[(ec+3)*129 + s] = vv.w;
            }
            __syncthreads();
            for (int s = 0; s < 128; s++) {
                float v = kt[e*129 + s];
                #pragma unroll
                for (int uu = 0; uu < 5; uu++) {
                    int u = ug + (uu << 3);
                    if (u < SK) acc9[uu] += scores[u*1024 + st*128 + s] * v;
                }
            }
            __syncthreads();
        }
        #pragma unroll
        for (int uu = 0; uu < 5; uu++) {
            int u = ug + (uu << 3);
            if (u < SK) {
                int qi = tops[u];
                g_ctx[(size_t)((b<<10) + qi)*DM + h*HD + e] = to_tf32(acc9[uu]);
            }
        }
    }
}

// ---------------------------------------------------------------------------
// LayerNorm (row of 512, 256 threads). RND: round output to tf32.
// ---------------------------------------------------------------------------
template<bool RND>
__global__ void ln_kernel(const float* __restrict__ in, float* __restrict__ out,
                          const float* __restrict__ g, const float* __restrict__ be) {
    int row = blockIdx.x;
    int t   = threadIdx.x;
    float v0 = in[(size_t)row*DM + t];
    float v1 = in[(size_t)row*DM + t + 256];
    __shared__ float red[256];
    red[t] = v0 + v1; __syncthreads();
    for (int s = 128; s > 0; s >>= 1) { if (t < s) red[t] += red[t+s]; __syncthreads(); }
    float mean = red[0] * (1.0f/DM);
    __syncthreads();
    float d0 = v0 - mean, d1 = v1 - mean;
    red[t] = d0*d0 + d1*d1; __syncthreads();
    for (int s = 128; s > 0; s >>= 1) { if (t < s) red[t] += red[t+s]; __syncthreads(); }
    float rstd = rsqrtf(red[0] * (1.0f/DM) + 1e-5f);
    float o0 = d0*rstd*g[t]     + be[t];
    float o1 = d1*rstd*g[t+256] + be[t+256];
    if (RND) { o0 = to_tf32(o0); o1 = to_tf32(o1); }
    out[(size_t)row*DM + t]       = o0;
    out[(size_t)row*DM + t + 256] = o1;
}

// ---------------------------------------------------------------------------
// Mean pool stage 1; fused pool stage 2 + classifier
// ---------------------------------------------------------------------------
__global__ void pool1_kernel() {
    int b = blockIdx.x, r = blockIdx.y;
    int d = threadIdx.x;
    float acc = 0.f;
    for (int l = r*128; l < r*128 + 128; l++)
        acc += g_tmp[(size_t)(b*L_+l)*DM + d];
    g_poolp[(b*8 + r)*DM + d] = acc;
}

__global__ void poolcls_kernel(const float* __restrict__ Wc,
                               const float* __restrict__ bc,
                               float* __restrict__ out) {
    __shared__ float pooled[B_*DM];
    int t = threadIdx.x;          // 512
    #pragma unroll
    for (int i = 0; i < 4; i++) {
        int f = t + i*512;        // (b,d)
        int b = f >> 9, d = f & 511;
        float acc = 0.f;
        #pragma unroll
        for (int r = 0; r < 8; r++) acc += g_poolp[(b*8 + r)*DM + d];
        pooled[f] = acc * (1.0f/L_);
    }
    __syncthreads();
    if (t < B_*10) {
        int b = t / 10, c = t % 10;
        float acc = bc[c];
        for (int d = 0; d < DM; d++) acc += pooled[b*DM + d] * Wc[d*10 + c];
        out[b*10 + c] = acc;
    }
}

// ---------------------------------------------------------------------------
extern "C" void kernel_launch(void* const* d_in, const int* in_sizes, int n_in,
                              void* d_out, int out_size) {
    const float* src   = (const float*)d_in[0];
    const int*   idxs  = (const int*)  d_in[1];
    const float* Wemb  = (const float*)d_in[2];
    const float* bemb  = (const float*)d_in[3];
    const float* Wq    = (const float*)d_in[4];
    const float* bq    = (const float*)d_in[5];
    const float* Wk    = (const float*)d_in[6];
    const float* bk    = (const float*)d_in[7];
    const float* Wv    = (const float*)d_in[8];
    const float* bv    = (const float*)d_in[9];
    const float* Wo    = (const float*)d_in[10];
    const float* bo    = (const float*)d_in[11];
    const float* g1    = (const float*)d_in[12];
    const float* beta1 = (const float*)d_in[13];
    const float* W1    = (const float*)d_in[14];
    const float* bf1   = (const float*)d_in[15];
    const float* W2    = (const float*)d_in[16];
    const float* bf2   = (const float*)d_in[17];
    const float* g2    = (const float*)d_in[18];
    const float* beta2 = (const float*)d_in[19];
    const float* gf    = (const float*)d_in[20];
    const float* betaf = (const float*)d_in[21];
    const float* Wc    = (const float*)d_in[22];
    const float* bc    = (const float*)d_in[23];

    void *px_, *ptmp_, *pq_, *pk_, *pv_, *pctx_, *pff_, *psp_, *pwr_;
    cudaGetSymbolAddress(&px_,   g_x);
    cudaGetSymbolAddress(&ptmp_, g_tmp);
    cudaGetSymbolAddress(&pq_,   g_q);
    cudaGetSymbolAddress(&pk_,   g_k);
    cudaGetSymbolAddress(&pv_,   g_v);
    cudaGetSymbolAddress(&pctx_, g_ctx);
    cudaGetSymbolAddress(&pff_,  g_ff);
    cudaGetSymbolAddress(&psp_,  g_split);
    cudaGetSymbolAddress(&pwr_,  g_wr);
    float* px   = (float*)px_;
    float* ptmp = (float*)ptmp_;
    float* pq   = (float*)pq_;
    float* pk   = (float*)pk_;
    float* pv   = (float*)pv_;
    float* pctx = (float*)pctx_;
    float* pff  = (float*)pff_;
    float* psp  = (float*)psp_;
    float* pwr  = (float*)pwr_;

    const int attn_smem = ATT_SMEM_FLOATS * 4;
    static int configured = 0;
    if (!configured) {
        configured = 1;
        cudaFuncSetAttribute(attn_fused, cudaFuncAttributeMaxDynamicSharedMemorySize, attn_smem);
        cudaFuncSetAttribute((const void*)qkv_tc, cudaFuncAttributeMaxDynamicSharedMemorySize, GEMM_SMEM);
        cudaFuncSetAttribute((const void*)gemm_tc<false,false>, cudaFuncAttributeMaxDynamicSharedMemorySize, GEMM_SMEM);
        cudaFuncSetAttribute((const void*)gemm_tc<true,true>,   cudaFuncAttributeMaxDynamicSharedMemorySize, GEMM_SMEM);
        cudaFuncSetAttribute((const void*)ff2_splitk, cudaFuncAttributeMaxDynamicSharedMemorySize, GEMM_SMEM);
    }

    const int QS = 2*DM*DM;
    round_weights<<<(WR_TOTAL/4 + 255)/256, 256>>>(Wq, Wk, Wv, Wo, W1, W2);
    embed_kernel<<<NTOK, 512>>>(src, Wemb, bemb);

    for (int l = 0; l < 2; l++) {
        const float* W1_l = pwr + 4*QS + (size_t)l*DM*DFF;
        const float* W2_l = pwr + 4*QS + 2*DM*DFF + (size_t)l*DFF*DM;
        const float* Wo_l = pwr + 3*QS + (size_t)l*DM*DM;

        dim3 gQKV(DM/128, NTOK/128, 3);      // (4, 32, 3)
        dim3 gDM(DM/128, NTOK/128);          // (4, 32)
        dim3 gFF(DFF/128, NTOK/128);         // (16, 32)
        dim3 gSP(DM/128, NTOK/128, SPLITK);  // (4, 32, 4)

        qkv_tc<<<gQKV, 256, GEMM_SMEM>>>(px, l, bq + l*DM, bk + l*DM, bv + l*DM,
                                         pq, pk, pv);

        sampleM_kernel<<<(B_*NH*L_)/4, 128>>>(idxs + (size_t)l*L_*SK);
        attn_fused<<<B_*NH, ATT_THREADS, attn_smem>>>();

        gemm_tc<false,false><<<gDM, 256, GEMM_SMEM>>>(pctx, Wo_l, bo + l*DM, px, ptmp, DM, DM);
        ln_kernel<true><<<NTOK, 256>>>(ptmp, px, g1 + l*DM, beta1 + l*DM);

        gemm_tc<true,true><<<gFF, 256, GEMM_SMEM>>>(px, W1_l, bf1 + l*DFF, nullptr, pff, DFF, DM);
        ff2_splitk<<<gSP, 256, GEMM_SMEM>>>(pff, W2_l, psp);
        reduce_ln_kernel<<<NTOK, 256>>>(bf2 + l*DM, px, g2 + l*DM, beta2 + l*DM, px);
    }

    ln_kernel<false><<<NTOK, 256>>>(px, ptmp, gf, betaf);
    pool1_kernel<<<dim3(B_, 8), 512>>>();
    poolcls_kernel<<<1, 512>>>(Wc, bc, (float*)d_out);
}

// round 7
// speedup vs baseline: 1.2841x; 1.0374x over previous
#include <cuda_runtime.h>
#include <cuda_bf16.h>
#include <math.h>
#include <float.h>
#include <stdint.h>

// ---------------------------------------------------------------------------
// Informer: B=4, L=1024, DM=512, NH=8, HD=64, DFF=2048, SK=35, 2 layers
// ---------------------------------------------------------------------------
#define B_   4
#define L_   1024
#define DM   512
#define NH   8
#define HD   64
#define DFF  2048
#define SK   35
#define NTOK (B_*L_)   // 4096
#define SPLITK 4
#define GS 3           // cp.async pipeline stages

__device__ float g_x   [NTOK*DM];
__device__ float g_tmp [NTOK*DM];
__device__ float g_q   [NTOK*DM];
__device__ float g_k   [NTOK*DM];
__device__ float g_v   [NTOK*DM];
__device__ float g_ctx [NTOK*DM];
__device__ float g_ff  [NTOK*DFF];
__device__ float g_split[SPLITK*NTOK*DM];
__device__ float g_M   [B_*NH*L_];
__device__ float g_poolp[B_*8*DM];
__device__ __nv_bfloat16 g_qh[NTOK*DM];   // bf16 copies for sampling
__device__ __nv_bfloat16 g_kh[NTOK*DM];
// pre-rounded (tf32-rna) weights: Wq|Wk|Wv|Wo (both layers each) then W1, W2
#define WR_TOTAL (4*2*DM*DM + 2*DM*DFF + 2*DFF*DM)
__device__ float g_wr[WR_TOTAL];

// ---------------------------------------------------------------------------
__device__ __forceinline__ float to_tf32(float x) {
    uint32_t u;
    asm("cvt.rna.tf32.f32 %0, %1;" : "=r"(u) : "f"(x));
    return __uint_as_float(u);
}

__device__ __forceinline__ void mma_tf32(float* c, const uint32_t* a,
                                         uint32_t b0, uint32_t b1) {
    asm volatile(
        "mma.sync.aligned.m16n8k8.row.col.f32.tf32.tf32.f32 "
        "{%0,%1,%2,%3},{%4,%5,%6,%7},{%8,%9},{%0,%1,%2,%3};"
        : "+f"(c[0]), "+f"(c[1]), "+f"(c[2]), "+f"(c[3])
        : "r"(a[0]), "r"(a[1]), "r"(a[2]), "r"(a[3]), "r"(b0), "r"(b1));
}

__device__ __forceinline__ void cp16(void* smem, const void* g) {
    uint32_t s = (uint32_t)__cvta_generic_to_shared(smem);
    asm volatile("cp.async.cg.shared.global [%0], [%1], 16;\n" :: "r"(s), "l"(g));
}
#define CP_COMMIT() asm volatile("cp.async.commit_group;\n" ::: "memory")
#define CP_WAIT1()  asm volatile("cp.async.wait_group 1;\n" ::: "memory")

// ---------------------------------------------------------------------------
// Pre-round all weights to tf32 (rna) into g_wr.
// ---------------------------------------------------------------------------
__global__ void round_weights(const float* __restrict__ Wq, const float* __restrict__ Wk,
                              const float* __restrict__ Wv, const float* __restrict__ Wo,
                              const float* __restrict__ W1, const float* __restrict__ W2) {
    const int QS = 2*DM*DM;
    int i4 = blockIdx.x * blockDim.x + threadIdx.x;
    int f  = i4 * 4;
    if (f >= WR_TOTAL) return;
    const float* src;
    int off;
    if      (f < QS)      { src = Wq; off = f; }
    else if (f < 2*QS)    { src = Wk; off = f - QS; }
    else if (f < 3*QS)    { src = Wv; off = f - 2*QS; }
    else if (f < 4*QS)    { src = Wo; off = f - 3*QS; }
    else if (f < 4*QS + 2*DM*DFF) { src = W1; off = f - 4*QS; }
    else                  { src = W2; off = f - 4*QS - 2*DM*DFF; }
    float4 v = *(const float4*)&src[off];
    v.x = to_tf32(v.x); v.y = to_tf32(v.y); v.z = to_tf32(v.z); v.w = to_tf32(v.w);
    *(float4*)&g_wr[f] = v;
}

// ---------------------------------------------------------------------------
// Embedding + positional encoding (output rounded to tf32)
// ---------------------------------------------------------------------------
__global__ void embed_kernel(const float* __restrict__ src,
                             const float* __restrict__ Wemb,
                             const float* __restrict__ bemb) {
    int row = blockIdx.x;
    int l   = row & (L_-1);
    int d   = threadIdx.x;
    __shared__ float s[32];
    if (d < 32) s[d] = src[row*32 + d];
    __syncthreads();
    float acc = bemb[d];
    #pragma unroll
    for (int k = 0; k < 32; k++) acc += s[k] * Wemb[k*DM + d];
    int i2 = d & ~1;
    float div = expf(-(float)i2 * (9.210340371976184f / 512.0f));
    float ang = (float)l * div;
    acc += (d & 1) ? cosf(ang) : sinf(ang);
    g_x[row*DM + d] = to_tf32(acc);
}

// ---------------------------------------------------------------------------
// tf32 GEMM, cp.async 3-stage pipeline. Block tile 128x128x16, 256 threads.
// Hout != nullptr: also store bf16 copy of the (bias-added) result.
// ---------------------------------------------------------------------------
#define AS(s,m,k) As[(s)*2560 + (m)*20 + (k)]
#define BS(s,k,n) Bs[(s)*2176 + (k)*136 + (n)]
#define GEMM_SMEM ((GS*2560 + GS*2176) * 4)    // 56832 bytes

__device__ __forceinline__ void issue_tile(
        float* As, float* Bs, const float* A, const float* W,
        int lda, int N, int m0, int n0, int k0, int s, int tid) {
    int f0 = tid, f1 = tid + 256;
    int ma0 = f0 >> 2, kc0 = (f0 & 3) << 2;
    int ma1 = f1 >> 2, kc1 = (f1 & 3) << 2;
    cp16(&AS(s,ma0,kc0), A + (size_t)(m0+ma0)*lda + k0 + kc0);
    cp16(&AS(s,ma1,kc1), A + (size_t)(m0+ma1)*lda + k0 + kc1);
    int kr0 = f0 >> 5, nc0 = (f0 & 31) << 2;
    int kr1 = f1 >> 5, nc1 = (f1 & 31) << 2;
    cp16(&BS(s,kr0,nc0), W + (size_t)(k0+kr0)*N + n0 + nc0);
    cp16(&BS(s,kr1,nc1), W + (size_t)(k0+kr1)*N + n0 + nc1);
}

template<bool GELU, bool RAW, bool RND>
__device__ __forceinline__ void gemm_body(
        const float* __restrict__ A, const float* __restrict__ W,
        const float* __restrict__ bias, const float* __restrict__ resid,
        float* __restrict__ C, __nv_bfloat16* __restrict__ Hout,
        int N, int K, int lda, int bx, int by) {
    extern __shared__ float gsm[];
    float* As = gsm;
    float* Bs = gsm + GS*2560;

    const int tid  = threadIdx.x;
    const int w    = tid >> 5;
    const int lane = tid & 31;
    const int grp  = lane >> 2;
    const int qd   = lane & 3;
    const int warp_m = (w & 3) * 32;
    const int warp_n = (w >> 2) * 64;
    const int m0 = by * 128;
    const int n0 = bx * 128;

    float acc[2][8][4];
    #pragma unroll
    for (int mi = 0; mi < 2; mi++)
        #pragma unroll
        for (int ni = 0; ni < 8; ni++)
            #pragma unroll
            for (int j = 0; j < 4; j++) acc[mi][ni][j] = 0.f;

    const int nt = K >> 4;

    issue_tile(As, Bs, A, W, lda, N, m0, n0, 0, 0, tid);  CP_COMMIT();
    issue_tile(As, Bs, A, W, lda, N, m0, n0, 16, 1, tid); CP_COMMIT();

    for (int t = 0; t < nt; t++) {
        CP_WAIT1();
        __syncthreads();
        const int s = t % GS;
        if (t + 2 < nt)
            issue_tile(As, Bs, A, W, lda, N, m0, n0, (t+2) << 4, (t+2) % GS, tid);
        CP_COMMIT();

        #pragma unroll
        for (int kk = 0; kk < 16; kk += 8) {
            uint32_t af[2][4];
            #pragma unroll
            for (int mi = 0; mi < 2; mi++) {
                int mb = warp_m + mi*16 + grp;
                af[mi][0] = __float_as_uint(AS(s, mb,   kk+qd));
                af[mi][1] = __float_as_uint(AS(s, mb+8, kk+qd));
                af[mi][2] = __float_as_uint(AS(s, mb,   kk+qd+4));
                af[mi][3] = __float_as_uint(AS(s, mb+8, kk+qd+4));
            }
            #pragma unroll
            for (int ni = 0; ni < 8; ni++) {
                int nb = warp_n + ni*8 + grp;
                uint32_t b0 = __float_as_uint(BS(s, kk+qd,   nb));
                uint32_t b1 = __float_as_uint(BS(s, kk+qd+4, nb));
                mma_tf32(acc[0][ni], af[0], b0, b1);
                mma_tf32(acc[1][ni], af[1], b0, b1);
            }
        }
    }

    #pragma unroll
    for (int mi = 0; mi < 2; mi++) {
        int r0 = m0 + warp_m + mi*16 + grp;
        #pragma unroll
        for (int ni = 0; ni < 8; ni++) {
            int c = n0 + warp_n + ni*8 + qd*2;
            float v0 = acc[mi][ni][0];
            float v1 = acc[mi][ni][1];
            float v2 = acc[mi][ni][2];
            float v3 = acc[mi][ni][3];
            if (!RAW) {
                float b0 = bias[c], b1 = bias[c+1];
                v0 += b0; v1 += b1; v2 += b0; v3 += b1;
                if (resid) {
                    v0 += resid[(size_t)r0*N + c];     v1 += resid[(size_t)r0*N + c + 1];
                    v2 += resid[(size_t)(r0+8)*N + c]; v3 += resid[(size_t)(r0+8)*N + c + 1];
                }
                if (GELU) {
                    v0 = 0.5f*v0*(1.0f + erff(v0*0.70710678118654752f));
                    v1 = 0.5f*v1*(1.0f + erff(v1*0.70710678118654752f));
                    v2 = 0.5f*v2*(1.0f + erff(v2*0.70710678118654752f));
                    v3 = 0.5f*v3*(1.0f + erff(v3*0.70710678118654752f));
                }
            }
            if (RND) {
                v0 = to_tf32(v0); v1 = to_tf32(v1);
                v2 = to_tf32(v2); v3 = to_tf32(v3);
            }
            *(float2*)&C[(size_t)r0*N + c]     = make_float2(v0, v1);
            *(float2*)&C[(size_t)(r0+8)*N + c] = make_float2(v2, v3);
            if (Hout) {
                *(__nv_bfloat162*)&Hout[(size_t)r0*N + c] =
                    __floats2bfloat162_rn(v0, v1);
                *(__nv_bfloat162*)&Hout[(size_t)(r0+8)*N + c] =
                    __floats2bfloat162_rn(v2, v3);
            }
        }
    }
}

template<bool GELU, bool RND>
__global__ void __launch_bounds__(256, 2)
gemm_tc(const float* __restrict__ A, const float* __restrict__ W,
        const float* __restrict__ bias, const float* __restrict__ resid,
        float* __restrict__ C, int N, int K) {
    gemm_body<GELU, false, RND>(A, W, bias, resid, C, nullptr, N, K, K,
                                blockIdx.x, blockIdx.y);
}

// Fused QKV: blockIdx.z selects projection; Q,K also dual-stored as bf16.
__global__ void __launch_bounds__(256, 2)
qkv_tc(const float* __restrict__ A, int layer,
       const float* __restrict__ bq, const float* __restrict__ bk,
       const float* __restrict__ bv,
       float* __restrict__ Q, float* __restrict__ Ko, float* __restrict__ V) {
    const float* W; const float* bias; float* C; __nv_bfloat16* H;
    const int QS = 2*DM*DM;
    size_t loff = (size_t)layer*DM*DM;
    if (blockIdx.z == 0)      { W = g_wr + loff;        bias = bq; C = Q;  H = g_qh; }
    else if (blockIdx.z == 1) { W = g_wr + QS + loff;   bias = bk; C = Ko; H = g_kh; }
    else                      { W = g_wr + 2*QS + loff; bias = bv; C = V;  H = nullptr; }
    gemm_body<false, false, false>(A, W, bias, nullptr, C, H, DM, DM, DM,
                                   blockIdx.x, blockIdx.y);
}

// Split-K FF2 partial: blockIdx.z = k-chunk.
__global__ void __launch_bounds__(256, 2)
ff2_splitk(const float* __restrict__ A, const float* __restrict__ W,
           float* __restrict__ Cpart) {
    const int kc = blockIdx.z;
    gemm_body<false, true, false>(A + kc*(DFF/SPLITK), W + (size_t)kc*(DFF/SPLITK)*DM,
                                  nullptr, nullptr, Cpart + (size_t)kc*NTOK*DM,
                                  nullptr, DM, DFF/SPLITK, DFF, blockIdx.x, blockIdx.y);
}

// Fused split-K reduce + bias + residual + LayerNorm (output rounded).
__global__ void reduce_ln_kernel(const float* __restrict__ bias,
                                 const float* __restrict__ resid,
                                 const float* __restrict__ g,
                                 const float* __restrict__ be,
                                 float* __restrict__ out) {
    int row = blockIdx.x;
    int t   = threadIdx.x;
    size_t o0 = (size_t)row*DM + t;
    size_t o1 = o0 + 256;
    float v0 = resid[o0] + bias[t];
    float v1 = resid[o1] + bias[t+256];
    #pragma unroll
    for (int s = 0; s < SPLITK; s++) {
        v0 += g_split[(size_t)s*NTOK*DM + o0];
        v1 += g_split[(size_t)s*NTOK*DM + o1];
    }
    __shared__ float red[256];
    red[t] = v0 + v1; __syncthreads();
    for (int s = 128; s > 0; s >>= 1) { if (t < s) red[t] += red[t+s]; __syncthreads(); }
    float mean = red[0] * (1.0f/DM);
    __syncthreads();
    float d0 = v0 - mean, d1 = v1 - mean;
    red[t] = d0*d0 + d1*d1; __syncthreads();
    for (int s = 128; s > 0; s >>= 1) { if (t < s) red[t] += red[t+s]; __syncthreads(); }
    float rstd = rsqrtf(red[0] * (1.0f/DM) + 1e-5f);
    out[o0] = to_tf32(d0*rstd*g[t]     + be[t]);
    out[o1] = to_tf32(d1*rstd*g[t+256] + be[t+256]);
}

// ---------------------------------------------------------------------------
// Sampled sparsity measure M. One warp per (b,h,i); two j's per iteration
// (16-lane halves), bf16 Q/K, Q held in registers, idx via register shuffle.
// ---------------------------------------------------------------------------
__global__ void sampleM_kernel(const int* __restrict__ idxs) {
    int wg   = (blockIdx.x * blockDim.x + threadIdx.x) >> 5;
    int lane = threadIdx.x & 31;
    if (wg >= B_*NH*L_) return;
    int i = wg & (L_-1);
    int h = (wg >> 10) & (NH-1);
    int b = wg >> 13;
    const int half = lane >> 4;       // 0: even j, 1: odd j
    const int sub  = lane & 15;       // covers k elems 4*sub..4*sub+3

    // Q slice for this lane: 4 bf16 = 8 bytes
    const float2* Qr8 = (const float2*)&g_qh[(size_t)(b*L_ + i)*DM + h*HD];
    float2 qraw = Qr8[sub];
    uint32_t qlo = __float_as_uint(qraw.x), qhi = __float_as_uint(qraw.y);
    float2 q0 = __bfloat1622float2(*(__nv_bfloat162*)&qlo);
    float2 q1 = __bfloat1622float2(*(__nv_bfloat162*)&qhi);

    // preload idx into registers
    int idxA = idxs[i*SK + (lane < SK ? lane : 0)];
    int idxB = idxs[i*SK + ((32 + lane) < SK ? 32 + lane : 0)];

    float mx = -FLT_MAX, sm = 0.f;
    #pragma unroll 2
    for (int jj = 0; jj < 18; jj++) {
        int j = 2*jj + half;          // 0..35; halves interleave
        int srcA = __shfl_sync(0xffffffffu, idxA, j & 31);
        int srcB = __shfl_sync(0xffffffffu, idxB, (j - 32) & 31);
        int src  = (j < 32) ? srcA : srcB;
        bool valid = (j < SK);
        float p = 0.f;
        if (valid) {
            const float2* Kr8 = (const float2*)&g_kh[(size_t)(b*L_ + src)*DM + h*HD];
            float2 kraw = Kr8[sub];
            uint32_t klo = __float_as_uint(kraw.x), khi = __float_as_uint(kraw.y);
            float2 k0 = __bfloat1622float2(*(__nv_bfloat162*)&klo);
            float2 k1 = __bfloat1622float2(*(__nv_bfloat162*)&khi);
            p = q0.x*k0.x + q0.y*k0.y + q1.x*k1.x + q1.y*k1.y;
        }
        p += __shfl_xor_sync(0xffffffffu, p, 8);
        p += __shfl_xor_sync(0xffffffffu, p, 4);
        p += __shfl_xor_sync(0xffffffffu, p, 2);
        p += __shfl_xor_sync(0xffffffffu, p, 1);
        if (valid) { mx = fmaxf(mx, p); sm += p; }
    }
    // combine the two halves
    float mxo = __shfl_xor_sync(0xffffffffu, mx, 16);
    float smo = __shfl_xor_sync(0xffffffffu, sm, 16);
    mx = fmaxf(mx, mxo);
    sm += smo;
    if (lane == 0) g_M[(b*NH+h)*L_ + i] = mx - sm * (1.0f/SK);
}

// ---------------------------------------------------------------------------
// Fused attention per (b,h): radix-select top-35 + vmean + fill + scores +
// softmax + ctx. Grid = 32 blocks, 512 threads, ~187KB dynamic smem.
// ---------------------------------------------------------------------------
#define ATT_THREADS 512
#define SQ_ROWS 48
#define ATT_SMEM_FLOATS (35*1024 + SQ_ROWS*64 + 64*129 + 64 + 512 + 64)

__device__ __forceinline__ uint32_t f2ord(float f) {
    uint32_t u = __float_as_uint(f);
    return (u & 0x80000000u) ? ~u : (u | 0x80000000u);
}

__global__ void __launch_bounds__(ATT_THREADS, 1)
attn_fused() {
    extern __shared__ float dsm[];
    float* scores = dsm;
    float* sq     = scores + 35*1024;
    float* kt     = sq + SQ_ROWS*64;
    float* vmean  = kt + 64*129;
    float* red    = vmean + 64;
    int*   tops   = (int*)(red + 512);

    const int bh = blockIdx.x;
    const int b  = bh >> 3;
    const int h  = bh & 7;
    const int t  = threadIdx.x;
    const int lane = t & 31;
    const int w  = t >> 5;

    // ---- exact top-35 via MSB radix select
    {
        __shared__ int s_cntA[32];
        __shared__ int s_gt, s_tn;
        int* ties = (int*)scores;
        uint32_t u0 = f2ord(g_M[bh*L_ + t]);
        uint32_t u1 = f2ord(g_M[bh*L_ + t + 512]);
        if (t < 32) s_cntA[t] = 0;
        if (t == 0) { s_gt = 0; s_tn = 0; }
        __syncthreads();
        uint32_t prefix = 0;
        int need = SK;
        for (int bit = 31; bit >= 0; --bit) {
            uint32_t cd = (prefix >> bit) | 1u;
            int c = ((u0 >> bit) == cd) + ((u1 >> bit) == cd);
            int ws = __reduce_add_sync(0xffffffffu, c);
            if (lane == 0 && ws) atomicAdd(&s_cntA[bit], ws);
            __syncthreads();
            int cnt = s_cntA[bit];
            if (cnt >= need) prefix |= (1u << bit);
            else             need -= cnt;
        }
        if (u0 > prefix) tops[atomicAdd(&s_gt, 1)] = t;
        else if (u0 == prefix) ties[atomicAdd(&s_tn, 1)] = t;
        if (u1 > prefix) tops[atomicAdd(&s_gt, 1)] = t + 512;
        else if (u1 == prefix) ties[atomicAdd(&s_tn, 1)] = t + 512;
        __syncthreads();
        if (t == 0) {
            int base = s_gt, tn = s_tn;
            for (int sel = 0; sel < need; sel++) {
                int bi = -1, bvv = 0x7fffffff;
                for (int j = 0; j < tn; j++)
                    if (ties[j] < bvv) { bvv = ties[j]; bi = j; }
                tops[base + sel] = bvv;
                ties[bi] = 0x7fffffff;
            }
        }
        __syncthreads();
    }

    // ---- selected Q rows
    for (int f = t; f < SQ_ROWS*64; f += ATT_THREADS) {
        int u = f >> 6, k = f & 63;
        sq[f] = (u < SK) ? g_q[(size_t)((b<<10) + tops[u])*DM + h*HD + k] : 0.f;
    }

    // ---- vmean
    {
        int e = t & 63, r = t >> 6;
        float acc = 0.f;
        for (int l = r*128; l < r*128 + 128; l++)
            acc += g_v[(size_t)((b<<10) + l)*DM + h*HD + e];
        red[t] = acc;
        __syncthreads();
        if (t < 64) {
            float s = 0.f;
            #pragma unroll
            for (int rr = 0; rr < 8; rr++) s += red[t + rr*64];
            vmean[t] = to_tf32(s * (1.0f/L_));
        }
        __syncthreads();
    }

    // ---- broadcast fill ctx
    {
        const float4* vm4 = (const float4*)vmean;
        for (int f = t; f < (L_*HD)/4; f += ATT_THREADS) {
            int l = f >> 4, ev = f & 15;
            *(float4*)&g_ctx[(size_t)((b<<10) + l)*DM + h*HD + ev*4] = vm4[ev];
        }
    }

    // ---- scores
    for (int st = 0; st < 8; st++) {
        #pragma unroll
        for (int i = 0; i < 4; i++) {
            int f = t + i*ATT_THREADS;
            int s = f >> 4, ec = (f & 15) << 2;
            float4 kv = *(const float4*)&g_k[(size_t)((b<<10) + st*128 + s)*DM + h*HD + ec];
            kt[(ec+0)*129 + s] = kv.x;
            kt[(ec+1)*129 + s] = kv.y;
            kt[(ec+2)*129 + s] = kv.z;
            kt[(ec+3)*129 + s] = kv.w;
        }
        __syncthreads();

        float acc[3][4];
        #pragma unroll
        for (int uu = 0; uu < 3; uu++)
            #pragma unroll
            for (int j = 0; j < 4; j++) acc[uu][j] = 0.f;

        for (int k = 0; k < 64; k++) {
            float kv0 = kt[k*129 + lane];
            float kv1 = kt[k*129 + lane + 32];
            float kv2 = kt[k*129 + lane + 64];
            float kv3 = kt[k*129 + lane + 96];
            #pragma unroll
            for (int uu = 0; uu < 3; uu++) {
                float qv = sq[(uu*16 + w)*64 + k];
                acc[uu][0] += qv*kv0; acc[uu][1] += qv*kv1;
                acc[uu][2] += qv*kv2; acc[uu][3] += qv*kv3;
            }
        }
        #pragma unroll
        for (int uu = 0; uu < 3; uu++) {
            int u = uu*16 + w;
            if (u < SK) {
                scores[u*1024 + st*128 + lane]      = acc[uu][0]*0.125f;
                scores[u*1024 + st*128 + lane + 32] = acc[uu][1]*0.125f;
                scores[u*1024 + st*128 + lane + 64] = acc[uu][2]*0.125f;
                scores[u*1024 + st*128 + lane + 96] = acc[uu][3]*0.125f;
            }
        }
        __syncthreads();
    }

    // ---- softmax
    for (int u = w; u < SK; u += 16) {
        float* row = &scores[u*1024];
        float m = -FLT_MAX;
        #pragma unroll
        for (int i = 0; i < 32; i++) m = fmaxf(m, row[lane + 32*i]);
        #pragma unroll
        for (int o = 16; o > 0; o >>= 1) m = fmaxf(m, __shfl_xor_sync(0xffffffffu, m, o));
        float s = 0.f;
        #pragma unroll
        for (int i = 0; i < 32; i++) {
            float e = expf(row[lane + 32*i] - m);
            row[lane + 32*i] = e;
            s += e;
        }
        #pragma unroll
        for (int o = 16; o > 0; o >>= 1) s += __shfl_xor_sync(0xffffffffu, s, o);
        float inv = 1.0f / s;
        #pragma unroll
        for (int i = 0; i < 32; i++) row[lane + 32*i] *= inv;
    }
    __syncthreads();

    // ---- ctx = probs @ V (scatter, rounded)
    {
        int e = t & 63, ug = t >> 6;
        float acc9[5] = {0.f, 0.f, 0.f, 0.f, 0.f};
        for (int st = 0; st < 8; st++) {
            #pragma unroll
            for (int i = 0; i < 4; i++) {
                int f = t + i*ATT_THREADS;
                int s = f >> 4, ec = (f & 15) << 2;
                float4 vv = *(const float4*)&g_v[(size_t)((b<<10) + st*128 + s)*DM + h*HD + ec];
                kt[(ec+0)*129 + s] = vv.x;
                kt[(ec+1)*129 + s] = vv.y;
                kt[(ec+2)*129 + s] = vv.z;
                kt[(ec+3)*129 + s] = vv.w;
            }
            __syncthreads();
            for (int s = 0; s < 128; s++) {
                float v = kt[e*129 + s];
                #pragma unroll
                for (int uu = 0; uu < 5; uu++) {
                    int u = ug + (uu << 3);
                    if (u < SK) acc9[uu] += scores[u*1024 + st*128 + s] * v;
                }
            }
            __syncthreads();
        }
        #pragma unroll
        for (int uu = 0; uu < 5; uu++) {
            int u = ug + (uu << 3);
            if (u < SK) {
                int qi = tops[u];
                g_ctx[(size_t)((b<<10) + qi)*DM + h*HD + e] = to_tf32(acc9[uu]);
            }
        }
    }
}

// ---------------------------------------------------------------------------
// LayerNorm (row of 512, 256 threads). RND: round output to tf32.
// ---------------------------------------------------------------------------
template<bool RND>
__global__ void ln_kernel(const float* __restrict__ in, float* __restrict__ out,
                          const float* __restrict__ g, const float* __restrict__ be) {
    int row = blockIdx.x;
    int t   = threadIdx.x;
    float v0 = in[(size_t)row*DM + t];
    float v1 = in[(size_t)row*DM + t + 256];
    __shared__ float red[256];
    red[t] = v0 + v1; __syncthreads();
    for (int s = 128; s > 0; s >>= 1) { if (t < s) red[t] += red[t+s]; __syncthreads(); }
    float mean = red[0] * (1.0f/DM);
    __syncthreads();
    float d0 = v0 - mean, d1 = v1 - mean;
    red[t] = d0*d0 + d1*d1; __syncthreads();
    for (int s = 128; s > 0; s >>= 1) { if (t < s) red[t] += red[t+s]; __syncthreads(); }
    float rstd = rsqrtf(red[0] * (1.0f/DM) + 1e-5f);
    float o0 = d0*rstd*g[t]     + be[t];
    float o1 = d1*rstd*g[t+256] + be[t+256];
    if (RND) { o0 = to_tf32(o0); o1 = to_tf32(o1); }
    out[(size_t)row*DM + t]       = o0;
    out[(size_t)row*DM + t + 256] = o1;
}

// ---------------------------------------------------------------------------
// Mean pool stage 1; fused pool stage 2 + classifier (warp per (b,c))
// ---------------------------------------------------------------------------
__global__ void pool1_kernel() {
    int b = blockIdx.x, r = blockIdx.y;
    int d = threadIdx.x;
    float acc = 0.f;
    for (int l = r*128; l < r*128 + 128; l++)
        acc += g_tmp[(size_t)(b*L_+l)*DM + d];
    g_poolp[(b*8 + r)*DM + d] = acc;
}

__global__ void poolcls_kernel(const float* __restrict__ Wc,
                               const float* __restrict__ bc,
                               float* __restrict__ out) {
    __shared__ float pooled[B_*DM];
    int t = threadIdx.x;          // 512
    int lane = t & 31, w = t >> 5;
    #pragma unroll
    for (int i = 0; i < 4; i++) {
        int f = t + i*512;
        int b = f >> 9, d = f & 511;
        float acc = 0.f;
        #pragma unroll
        for (int r = 0; r < 8; r++) acc += g_poolp[(b*8 + r)*DM + d];
        pooled[f] = acc * (1.0f/L_);
    }
    __syncthreads();
    for (int bcp = w; bcp < B_*10; bcp += 16) {
        int b = bcp / 10, c = bcp % 10;
        float acc = 0.f;
        for (int d = lane; d < DM; d += 32)
            acc += pooled[b*DM + d] * Wc[d*10 + c];
        #pragma unroll
        for (int o = 16; o > 0; o >>= 1) acc += __shfl_xor_sync(0xffffffffu, acc, o);
        if (lane == 0) out[bcp] = acc + bc[c];
    }
}

// ---------------------------------------------------------------------------
extern "C" void kernel_launch(void* const* d_in, const int* in_sizes, int n_in,
                              void* d_out, int out_size) {
    const float* src   = (const float*)d_in[0];
    const int*   idxs  = (const int*)  d_in[1];
    const float* Wemb  = (const float*)d_in[2];
    const float* bemb  = (const float*)d_in[3];
    const float* Wq    = (const float*)d_in[4];
    const float* bq    = (const float*)d_in[5];
    const float* Wk    = (const float*)d_in[6];
    const float* bk    = (const float*)d_in[7];
    const float* Wv    = (const float*)d_in[8];
    const float* bv    = (const float*)d_in[9];
    const float* Wo    = (const float*)d_in[10];
    const float* bo    = (const float*)d_in[11];
    const float* g1    = (const float*)d_in[12];
    const float* beta1 = (const float*)d_in[13];
    const float* W1    = (const float*)d_in[14];
    const float* bf1   = (const float*)d_in[15];
    const float* W2    = (const float*)d_in[16];
    const float* bf2   = (const float*)d_in[17];
    const float* g2    = (const float*)d_in[18];
    const float* beta2 = (const float*)d_in[19];
    const float* gf    = (const float*)d_in[20];
    const float* betaf = (const float*)d_in[21];
    const float* Wc    = (const float*)d_in[22];
    const float* bc    = (const float*)d_in[23];

    void *px_, *ptmp_, *pq_, *pk_, *pv_, *pctx_, *pff_, *psp_, *pwr_;
    cudaGetSymbolAddress(&px_,   g_x);
    cudaGetSymbolAddress(&ptmp_, g_tmp);
    cudaGetSymbolAddress(&pq_,   g_q);
    cudaGetSymbolAddress(&pk_,   g_k);
    cudaGetSymbolAddress(&pv_,   g_v);
    cudaGetSymbolAddress(&pctx_, g_ctx);
    cudaGetSymbolAddress(&pff_,  g_ff);
    cudaGetSymbolAddress(&psp_,  g_split);
    cudaGetSymbolAddress(&pwr_,  g_wr);
    float* px   = (float*)px_;
    float* ptmp = (float*)ptmp_;
    float* pq   = (float*)pq_;
    float* pk   = (float*)pk_;
    float* pv   = (float*)pv_;
    float* pctx = (float*)pctx_;
    float* pff  = (float*)pff_;
    float* psp  = (float*)psp_;
    float* pwr  = (float*)pwr_;

    const int attn_smem = ATT_SMEM_FLOATS * 4;
    static int configured = 0;
    if (!configured) {
        configured = 1;
        cudaFuncSetAttribute(attn_fused, cudaFuncAttributeMaxDynamicSharedMemorySize, attn_smem);
        cudaFuncSetAttribute((const void*)qkv_tc, cudaFuncAttributeMaxDynamicSharedMemorySize, GEMM_SMEM);
        cudaFuncSetAttribute((const void*)gemm_tc<false,false>, cudaFuncAttributeMaxDynamicSharedMemorySize, GEMM_SMEM);
        cudaFuncSetAttribute((const void*)gemm_tc<true,true>,   cudaFuncAttributeMaxDynamicSharedMemorySize, GEMM_SMEM);
        cudaFuncSetAttribute((const void*)ff2_splitk, cudaFuncAttributeMaxDynamicSharedMemorySize, GEMM_SMEM);
    }

    const int QS = 2*DM*DM;
    round_weights<<<(WR_TOTAL/4 + 255)/256, 256>>>(Wq, Wk, Wv, Wo, W1, W2);
    embed_kernel<<<NTOK, 512>>>(src, Wemb, bemb);

    for (int l = 0; l < 2; l++) {
        const float* W1_l = pwr + 4*QS + (size_t)l*DM*DFF;
        const float* W2_l = pwr + 4*QS + 2*DM*DFF + (size_t)l*DFF*DM;
        const float* Wo_l = pwr + 3*QS + (size_t)l*DM*DM;

        dim3 gQKV(DM/128, NTOK/128, 3);
        dim3 gDM(DM/128, NTOK/128);
        dim3 gFF(DFF/128, NTOK/128);
        dim3 gSP(DM/128, NTOK/128, SPLITK);

        qkv_tc<<<gQKV, 256, GEMM_SMEM>>>(px, l, bq + l*DM, bk + l*DM, bv + l*DM,
                                         pq, pk, pv);

        sampleM_kernel<<<(B_*NH*L_)/4, 128>>>(idxs + (size_t)l*L_*SK);
        attn_fused<<<B_*NH, ATT_THREADS, attn_smem>>>();

        gemm_tc<false,false><<<gDM, 256, GEMM_SMEM>>>(pctx, Wo_l, bo + l*DM, px, ptmp, DM, DM);
        ln_kernel<true><<<NTOK, 256>>>(ptmp, px, g1 + l*DM, beta1 + l*DM);

        gemm_tc<true,true><<<gFF, 256, GEMM_SMEM>>>(px, W1_l, bf1 + l*DFF, nullptr, pff, DFF, DM);
        ff2_splitk<<<gSP, 256, GEMM_SMEM>>>(pff, W2_l, psp);
        reduce_ln_kernel<<<NTOK, 256>>>(bf2 + l*DM, px, g2 + l*DM, beta2 + l*DM, px);
    }

    ln_kernel<false><<<NTOK, 256>>>(px, ptmp, gf, betaf);
    pool1_kernel<<<dim3(B_, 8), 512>>>();
    poolcls_kernel<<<1, 512>>>(Wc, bc, (float*)d_out);
}

// round 8
// speedup vs baseline: 1.3075x; 1.0182x over previous
#include <cuda_runtime.h>
#include <cuda_bf16.h>
#include <math.h>
#include <float.h>
#include <stdint.h>

// ---------------------------------------------------------------------------
// Informer: B=4, L=1024, DM=512, NH=8, HD=64, DFF=2048, SK=35, 2 layers
// ---------------------------------------------------------------------------
#define B_   4
#define L_   1024
#define DM   512
#define NH   8
#define HD   64
#define DFF  2048
#define SK   35
#define NTOK (B_*L_)   // 4096
#define SPLITK 4
#define GS 3           // cp.async pipeline stages

__device__ float g_x   [NTOK*DM];
__device__ float g_tmp [NTOK*DM];
__device__ float g_q   [NTOK*DM];
__device__ float g_k   [NTOK*DM];
__device__ float g_v   [NTOK*DM];
__device__ float g_ctx [NTOK*DM];
__device__ float g_ff  [NTOK*DFF];
__device__ float g_split[SPLITK*NTOK*DM];
__device__ float g_M   [B_*NH*L_];
__device__ float g_poolp[B_*8*DM];
__device__ __nv_bfloat16 g_qh[NTOK*DM];   // bf16 copies for sampling
__device__ __nv_bfloat16 g_kh[NTOK*DM];
// pre-rounded (tf32-rna) weights: Wq|Wk|Wv|Wo (both layers each) then W1, W2
#define WR_TOTAL (4*2*DM*DM + 2*DM*DFF + 2*DFF*DM)
__device__ float g_wr[WR_TOTAL];

// ---------------------------------------------------------------------------
__device__ __forceinline__ float to_tf32(float x) {
    uint32_t u;
    asm("cvt.rna.tf32.f32 %0, %1;" : "=r"(u) : "f"(x));
    return __uint_as_float(u);
}

__device__ __forceinline__ void mma_tf32(float* c, const uint32_t* a,
                                         uint32_t b0, uint32_t b1) {
    asm volatile(
        "mma.sync.aligned.m16n8k8.row.col.f32.tf32.tf32.f32 "
        "{%0,%1,%2,%3},{%4,%5,%6,%7},{%8,%9},{%0,%1,%2,%3};"
        : "+f"(c[0]), "+f"(c[1]), "+f"(c[2]), "+f"(c[3])
        : "r"(a[0]), "r"(a[1]), "r"(a[2]), "r"(a[3]), "r"(b0), "r"(b1));
}

__device__ __forceinline__ void cp16(void* smem, const void* g) {
    uint32_t s = (uint32_t)__cvta_generic_to_shared(smem);
    asm volatile("cp.async.cg.shared.global [%0], [%1], 16;\n" :: "r"(s), "l"(g));
}
#define CP_COMMIT() asm volatile("cp.async.commit_group;\n" ::: "memory")
#define CP_WAIT1()  asm volatile("cp.async.wait_group 1;\n" ::: "memory")

// ---------------------------------------------------------------------------
// Fused prologue: embed+posenc (blocks 0..NTOK-1) and weight tf32-rounding
// (remaining blocks). 512 threads.
// ---------------------------------------------------------------------------
#define RND_BLOCKS ((WR_TOTAL/4 + 511) / 512)    // 3072

__global__ void prep_kernel(const float* __restrict__ src,
                            const float* __restrict__ Wemb,
                            const float* __restrict__ bemb,
                            const float* __restrict__ Wq, const float* __restrict__ Wk,
                            const float* __restrict__ Wv, const float* __restrict__ Wo,
                            const float* __restrict__ W1, const float* __restrict__ W2) {
    const int bx = blockIdx.x;
    if (bx < NTOK) {
        int row = bx;
        int l   = row & (L_-1);
        int d   = threadIdx.x;
        __shared__ float s[32];
        if (d < 32) s[d] = src[row*32 + d];
        __syncthreads();
        float acc = bemb[d];
        #pragma unroll
        for (int k = 0; k < 32; k++) acc += s[k] * Wemb[k*DM + d];
        int i2 = d & ~1;
        float div = expf(-(float)i2 * (9.210340371976184f / 512.0f));
        float ang = (float)l * div;
        acc += (d & 1) ? cosf(ang) : sinf(ang);
        g_x[row*DM + d] = to_tf32(acc);
    } else {
        const int QS = 2*DM*DM;
        int i4 = (bx - NTOK) * 512 + threadIdx.x;
        int f  = i4 * 4;
        if (f >= WR_TOTAL) return;
        const float* sp;
        int off;
        if      (f < QS)      { sp = Wq; off = f; }
        else if (f < 2*QS)    { sp = Wk; off = f - QS; }
        else if (f < 3*QS)    { sp = Wv; off = f - 2*QS; }
        else if (f < 4*QS)    { sp = Wo; off = f - 3*QS; }
        else if (f < 4*QS + 2*DM*DFF) { sp = W1; off = f - 4*QS; }
        else                  { sp = W2; off = f - 4*QS - 2*DM*DFF; }
        float4 v = *(const float4*)&sp[off];
        v.x = to_tf32(v.x); v.y = to_tf32(v.y); v.z = to_tf32(v.z); v.w = to_tf32(v.w);
        *(float4*)&g_wr[f] = v;
    }
}

// ---------------------------------------------------------------------------
// tf32 GEMM, cp.async 3-stage pipeline. Block tile 128x128x16, 256 threads.
// Hout != nullptr: also store bf16 copy of the (bias-added) result.
// ---------------------------------------------------------------------------
#define AS(s,m,k) As[(s)*2560 + (m)*20 + (k)]
#define BS(s,k,n) Bs[(s)*2176 + (k)*136 + (n)]
#define GEMM_SMEM ((GS*2560 + GS*2176) * 4)    // 56832 bytes

__device__ __forceinline__ void issue_tile(
        float* As, float* Bs, const float* A, const float* W,
        int lda, int N, int m0, int n0, int k0, int s, int tid) {
    int f0 = tid, f1 = tid + 256;
    int ma0 = f0 >> 2, kc0 = (f0 & 3) << 2;
    int ma1 = f1 >> 2, kc1 = (f1 & 3) << 2;
    cp16(&AS(s,ma0,kc0), A + (size_t)(m0+ma0)*lda + k0 + kc0);
    cp16(&AS(s,ma1,kc1), A + (size_t)(m0+ma1)*lda + k0 + kc1);
    int kr0 = f0 >> 5, nc0 = (f0 & 31) << 2;
    int kr1 = f1 >> 5, nc1 = (f1 & 31) << 2;
    cp16(&BS(s,kr0,nc0), W + (size_t)(k0+kr0)*N + n0 + nc0);
    cp16(&BS(s,kr1,nc1), W + (size_t)(k0+kr1)*N + n0 + nc1);
}

template<bool GELU, bool RAW, bool RND>
__device__ __forceinline__ void gemm_body(
        const float* __restrict__ A, const float* __restrict__ W,
        const float* __restrict__ bias, const float* __restrict__ resid,
        float* __restrict__ C, __nv_bfloat16* __restrict__ Hout,
        int N, int K, int lda, int bx, int by) {
    extern __shared__ float gsm[];
    float* As = gsm;
    float* Bs = gsm + GS*2560;

    const int tid  = threadIdx.x;
    const int w    = tid >> 5;
    const int lane = tid & 31;
    const int grp  = lane >> 2;
    const int qd   = lane & 3;
    const int warp_m = (w & 3) * 32;
    const int warp_n = (w >> 2) * 64;
    const int m0 = by * 128;
    const int n0 = bx * 128;

    float acc[2][8][4];
    #pragma unroll
    for (int mi = 0; mi < 2; mi++)
        #pragma unroll
        for (int ni = 0; ni < 8; ni++)
            #pragma unroll
            for (int j = 0; j < 4; j++) acc[mi][ni][j] = 0.f;

    const int nt = K >> 4;

    issue_tile(As, Bs, A, W, lda, N, m0, n0, 0, 0, tid);  CP_COMMIT();
    issue_tile(As, Bs, A, W, lda, N, m0, n0, 16, 1, tid); CP_COMMIT();

    for (int t = 0; t < nt; t++) {
        CP_WAIT1();
        __syncthreads();
        const int s = t % GS;
        if (t + 2 < nt)
            issue_tile(As, Bs, A, W, lda, N, m0, n0, (t+2) << 4, (t+2) % GS, tid);
        CP_COMMIT();

        #pragma unroll
        for (int kk = 0; kk < 16; kk += 8) {
            uint32_t af[2][4];
            #pragma unroll
            for (int mi = 0; mi < 2; mi++) {
                int mb = warp_m + mi*16 + grp;
                af[mi][0] = __float_as_uint(AS(s, mb,   kk+qd));
                af[mi][1] = __float_as_uint(AS(s, mb+8, kk+qd));
                af[mi][2] = __float_as_uint(AS(s, mb,   kk+qd+4));
                af[mi][3] = __float_as_uint(AS(s, mb+8, kk+qd+4));
            }
            #pragma unroll
            for (int ni = 0; ni < 8; ni++) {
                int nb = warp_n + ni*8 + grp;
                uint32_t b0 = __float_as_uint(BS(s, kk+qd,   nb));
                uint32_t b1 = __float_as_uint(BS(s, kk+qd+4, nb));
                mma_tf32(acc[0][ni], af[0], b0, b1);
                mma_tf32(acc[1][ni], af[1], b0, b1);
            }
        }
    }

    #pragma unroll
    for (int mi = 0; mi < 2; mi++) {
        int r0 = m0 + warp_m + mi*16 + grp;
        #pragma unroll
        for (int ni = 0; ni < 8; ni++) {
            int c = n0 + warp_n + ni*8 + qd*2;
            float v0 = acc[mi][ni][0];
            float v1 = acc[mi][ni][1];
            float v2 = acc[mi][ni][2];
            float v3 = acc[mi][ni][3];
            if (!RAW) {
                float b0 = bias[c], b1 = bias[c+1];
                v0 += b0; v1 += b1; v2 += b0; v3 += b1;
                if (resid) {
                    v0 += resid[(size_t)r0*N + c];     v1 += resid[(size_t)r0*N + c + 1];
                    v2 += resid[(size_t)(r0+8)*N + c]; v3 += resid[(size_t)(r0+8)*N + c + 1];
                }
                if (GELU) {
                    v0 = 0.5f*v0*(1.0f + erff(v0*0.70710678118654752f));
                    v1 = 0.5f*v1*(1.0f + erff(v1*0.70710678118654752f));
                    v2 = 0.5f*v2*(1.0f + erff(v2*0.70710678118654752f));
                    v3 = 0.5f*v3*(1.0f + erff(v3*0.70710678118654752f));
                }
            }
            if (RND) {
                v0 = to_tf32(v0); v1 = to_tf32(v1);
                v2 = to_tf32(v2); v3 = to_tf32(v3);
            }
            *(float2*)&C[(size_t)r0*N + c]     = make_float2(v0, v1);
            *(float2*)&C[(size_t)(r0+8)*N + c] = make_float2(v2, v3);
            if (Hout) {
                *(__nv_bfloat162*)&Hout[(size_t)r0*N + c] =
                    __floats2bfloat162_rn(v0, v1);
                *(__nv_bfloat162*)&Hout[(size_t)(r0+8)*N + c] =
                    __floats2bfloat162_rn(v2, v3);
            }
        }
    }
}

template<bool GELU, bool RND>
__global__ void __launch_bounds__(256, 2)
gemm_tc(const float* __restrict__ A, const float* __restrict__ W,
        const float* __restrict__ bias, const float* __restrict__ resid,
        float* __restrict__ C, int N, int K) {
    gemm_body<GELU, false, RND>(A, W, bias, resid, C, nullptr, N, K, K,
                                blockIdx.x, blockIdx.y);
}

// Fused QKV: blockIdx.z selects projection; Q,K also dual-stored as bf16.
__global__ void __launch_bounds__(256, 2)
qkv_tc(const float* __restrict__ A, int layer,
       const float* __restrict__ bq, const float* __restrict__ bk,
       const float* __restrict__ bv,
       float* __restrict__ Q, float* __restrict__ Ko, float* __restrict__ V) {
    const float* W; const float* bias; float* C; __nv_bfloat16* H;
    const int QS = 2*DM*DM;
    size_t loff = (size_t)layer*DM*DM;
    if (blockIdx.z == 0)      { W = g_wr + loff;        bias = bq; C = Q;  H = g_qh; }
    else if (blockIdx.z == 1) { W = g_wr + QS + loff;   bias = bk; C = Ko; H = g_kh; }
    else                      { W = g_wr + 2*QS + loff; bias = bv; C = V;  H = nullptr; }
    gemm_body<false, false, false>(A, W, bias, nullptr, C, H, DM, DM, DM,
                                   blockIdx.x, blockIdx.y);
}

// Generic split-K partial GEMM: blockIdx.z = k-chunk of size KC.
// A row stride lda, weights W (K x DM row-major), partials into g_split.
template<int KC>
__global__ void __launch_bounds__(256, 2)
splitk_tc(const float* __restrict__ A, const float* __restrict__ W,
          int lda) {
    const int kc = blockIdx.z;
    gemm_body<false, true, false>(A + kc*KC, W + (size_t)kc*KC*DM,
                                  nullptr, nullptr,
                                  g_split + (size_t)kc*NTOK*DM,
                                  nullptr, DM, KC, lda, blockIdx.x, blockIdx.y);
}

// Fused split-K reduce + bias + residual + LayerNorm (output rounded).
// NS = number of partial buffers to sum.
template<int NS>
__global__ void reduce_ln_kernel(const float* __restrict__ bias,
                                 const float* __restrict__ resid,
                                 const float* __restrict__ g,
                                 const float* __restrict__ be,
                                 float* __restrict__ out) {
    int row = blockIdx.x;
    int t   = threadIdx.x;
    size_t o0 = (size_t)row*DM + t;
    size_t o1 = o0 + 256;
    float v0 = resid[o0] + bias[t];
    float v1 = resid[o1] + bias[t+256];
    #pragma unroll
    for (int s = 0; s < NS; s++) {
        v0 += g_split[(size_t)s*NTOK*DM + o0];
        v1 += g_split[(size_t)s*NTOK*DM + o1];
    }
    __shared__ float red[256];
    red[t] = v0 + v1; __syncthreads();
    for (int s = 128; s > 0; s >>= 1) { if (t < s) red[t] += red[t+s]; __syncthreads(); }
    float mean = red[0] * (1.0f/DM);
    __syncthreads();
    float d0 = v0 - mean, d1 = v1 - mean;
    red[t] = d0*d0 + d1*d1; __syncthreads();
    for (int s = 128; s > 0; s >>= 1) { if (t < s) red[t] += red[t+s]; __syncthreads(); }
    float rstd = rsqrtf(red[0] * (1.0f/DM) + 1e-5f);
    out[o0] = to_tf32(d0*rstd*g[t]     + be[t]);
    out[o1] = to_tf32(d1*rstd*g[t+256] + be[t+256]);
}

// ---------------------------------------------------------------------------
// Sampled sparsity measure M. One warp per (b,h,i); two j's per iteration
// (16-lane halves), bf16 Q/K, Q held in registers, idx via register shuffle.
// ---------------------------------------------------------------------------
__global__ void sampleM_kernel(const int* __restrict__ idxs) {
    int wg   = (blockIdx.x * blockDim.x + threadIdx.x) >> 5;
    int lane = threadIdx.x & 31;
    if (wg >= B_*NH*L_) return;
    int i = wg & (L_-1);
    int h = (wg >> 10) & (NH-1);
    int b = wg >> 13;
    const int half = lane >> 4;       // 0: even j, 1: odd j
    const int sub  = lane & 15;       // covers k elems 4*sub..4*sub+3

    const float2* Qr8 = (const float2*)&g_qh[(size_t)(b*L_ + i)*DM + h*HD];
    float2 qraw = Qr8[sub];
    uint32_t qlo = __float_as_uint(qraw.x), qhi = __float_as_uint(qraw.y);
    float2 q0 = __bfloat1622float2(*(__nv_bfloat162*)&qlo);
    float2 q1 = __bfloat1622float2(*(__nv_bfloat162*)&qhi);

    int idxA = idxs[i*SK + (lane < SK ? lane : 0)];
    int idxB = idxs[i*SK + ((32 + lane) < SK ? 32 + lane : 0)];

    float mx = -FLT_MAX, sm = 0.f;
    #pragma unroll 2
    for (int jj = 0; jj < 18; jj++) {
        int j = 2*jj + half;
        int srcA = __shfl_sync(0xffffffffu, idxA, j & 31);
        int srcB = __shfl_sync(0xffffffffu, idxB, (j - 32) & 31);
        int src  = (j < 32) ? srcA : srcB;
        bool valid = (j < SK);
        float p = 0.f;
        if (valid) {
            const float2* Kr8 = (const float2*)&g_kh[(size_t)(b*L_ + src)*DM + h*HD];
            float2 kraw = Kr8[sub];
            uint32_t klo = __float_as_uint(kraw.x), khi = __float_as_uint(kraw.y);
            float2 k0 = __bfloat1622float2(*(__nv_bfloat162*)&klo);
            float2 k1 = __bfloat1622float2(*(__nv_bfloat162*)&khi);
            p = q0.x*k0.x + q0.y*k0.y + q1.x*k1.x + q1.y*k1.y;
        }
        p += __shfl_xor_sync(0xffffffffu, p, 8);
        p += __shfl_xor_sync(0xffffffffu, p, 4);
        p += __shfl_xor_sync(0xffffffffu, p, 2);
        p += __shfl_xor_sync(0xffffffffu, p, 1);
        if (valid) { mx = fmaxf(mx, p); sm += p; }
    }
    float mxo = __shfl_xor_sync(0xffffffffu, mx, 16);
    float smo = __shfl_xor_sync(0xffffffffu, sm, 16);
    mx = fmaxf(mx, mxo);
    sm += smo;
    if (lane == 0) g_M[(b*NH+h)*L_ + i] = mx - sm * (1.0f/SK);
}

// ---------------------------------------------------------------------------
// Fused attention per (b,h): radix-select top-35 + vmean + fill + scores +
// softmax + ctx. Grid = 32 blocks, 512 threads, ~187KB dynamic smem.
// ---------------------------------------------------------------------------
#define ATT_THREADS 512
#define SQ_ROWS 48
#define ATT_SMEM_FLOATS (35*1024 + SQ_ROWS*64 + 64*129 + 64 + 512 + 64)

__device__ __forceinline__ uint32_t f2ord(float f) {
    uint32_t u = __float_as_uint(f);
    return (u & 0x80000000u) ? ~u : (u | 0x80000000u);
}

__global__ void __launch_bounds__(ATT_THREADS, 1)
attn_fused() {
    extern __shared__ float dsm[];
    float* scores = dsm;
    float* sq     = scores + 35*1024;
    float* kt     = sq + SQ_ROWS*64;
    float* vmean  = kt + 64*129;
    float* red    = vmean + 64;
    int*   tops   = (int*)(red + 512);

    const int bh = blockIdx.x;
    const int b  = bh >> 3;
    const int h  = bh & 7;
    const int t  = threadIdx.x;
    const int lane = t & 31;
    const int w  = t >> 5;

    // ---- exact top-35 via MSB radix select
    {
        __shared__ int s_cntA[32];
        __shared__ int s_gt, s_tn;
        int* ties = (int*)scores;
        uint32_t u0 = f2ord(g_M[bh*L_ + t]);
        uint32_t u1 = f2ord(g_M[bh*L_ + t + 512]);
        if (t < 32) s_cntA[t] = 0;
        if (t == 0) { s_gt = 0; s_tn = 0; }
        __syncthreads();
        uint32_t prefix = 0;
        int need = SK;
        for (int bit = 31; bit >= 0; --bit) {
            uint32_t cd = (prefix >> bit) | 1u;
            int c = ((u0 >> bit) == cd) + ((u1 >> bit) == cd);
            int ws = __reduce_add_sync(0xffffffffu, c);
            if (lane == 0 && ws) atomicAdd(&s_cntA[bit], ws);
            __syncthreads();
            int cnt = s_cntA[bit];
            if (cnt >= need) prefix |= (1u << bit);
            else             need -= cnt;
        }
        if (u0 > prefix) tops[atomicAdd(&s_gt, 1)] = t;
        else if (u0 == prefix) ties[atomicAdd(&s_tn, 1)] = t;
        if (u1 > prefix) tops[atomicAdd(&s_gt, 1)] = t + 512;
        else if (u1 == prefix) ties[atomicAdd(&s_tn, 1)] = t + 512;
        __syncthreads();
        if (t == 0) {
            int base = s_gt, tn = s_tn;
            for (int sel = 0; sel < need; sel++) {
                int bi = -1, bvv = 0x7fffffff;
                for (int j = 0; j < tn; j++)
                    if (ties[j] < bvv) { bvv = ties[j]; bi = j; }
                tops[base + sel] = bvv;
                ties[bi] = 0x7fffffff;
            }
        }
        __syncthreads();
    }

    // ---- selected Q rows
    for (int f = t; f < SQ_ROWS*64; f += ATT_THREADS) {
        int u = f >> 6, k = f & 63;
        sq[f] = (u < SK) ? g_q[(size_t)((b<<10) + tops[u])*DM + h*HD + k] : 0.f;
    }

    // ---- vmean
    {
        int e = t & 63, r = t >> 6;
        float acc = 0.f;
        for (int l = r*128; l < r*128 + 128; l++)
            acc += g_v[(size_t)((b<<10) + l)*DM + h*HD + e];
        red[t] = acc;
        __syncthreads();
        if (t < 64) {
            float s = 0.f;
            #pragma unroll
            for (int rr = 0; rr < 8; rr++) s += red[t + rr*64];
            vmean[t] = to_tf32(s * (1.0f/L_));
        }
        __syncthreads();
    }

    // ---- broadcast fill ctx
    {
        const float4* vm4 = (const float4*)vmean;
        for (int f = t; f < (L_*HD)/4; f += ATT_THREADS) {
            int l = f >> 4, ev = f & 15;
            *(float4*)&g_ctx[(size_t)((b<<10) + l)*DM + h*HD + ev*4] = vm4[ev];
        }
    }

    // ---- scores
    for (int st = 0; st < 8; st++) {
        #pragma unroll
        for (int i = 0; i < 4; i++) {
            int f = t + i*ATT_THREADS;
            int s = f >> 4, ec = (f & 15) << 2;
            float4 kv = *(const float4*)&g_k[(size_t)((b<<10) + st*128 + s)*DM + h*HD + ec];
            kt[(ec+0)*129 + s] = kv.x;
            kt[(ec+1)*129 + s] = kv.y;
            kt[(ec+2)*129 + s] = kv.z;
            kt[(ec+3)*129 + s] = kv.w;
        }
        __syncthreads();

        float acc[3][4];
        #pragma unroll
        for (int uu = 0; uu < 3; uu++)
            #pragma unroll
            for (int j = 0; j < 4; j++) acc[uu][j] = 0.f;

        for (int k = 0; k < 64; k++) {
            float kv0 = kt[k*129 + lane];
            float kv1 = kt[k*129 + lane + 32];
            float kv2 = kt[k*129 + lane + 64];
            float kv3 = kt[k*129 + lane + 96];
            #pragma unroll
            for (int uu = 0; uu < 3; uu++) {
                float qv = sq[(uu*16 + w)*64 + k];
                acc[uu][0] += qv*kv0; acc[uu][1] += qv*kv1;
                acc[uu][2] += qv*kv2; acc[uu][3] += qv*kv3;
            }
        }
        #pragma unroll
        for (int uu = 0; uu < 3; uu++) {
            int u = uu*16 + w;
            if (u < SK) {
                scores[u*1024 + st*128 + lane]      = acc[uu][0]*0.125f;
                scores[u*1024 + st*128 + lane + 32] = acc[uu][1]*0.125f;
                scores[u*1024 + st*128 + lane + 64] = acc[uu][2]*0.125f;
                scores[u*1024 + st*128 + lane + 96] = acc[uu][3]*0.125f;
            }
        }
        __syncthreads();
    }

    // ---- softmax
    for (int u = w; u < SK; u += 16) {
        float* row = &scores[u*1024];
        float m = -FLT_MAX;
        #pragma unroll
        for (int i = 0; i < 32; i++) m = fmaxf(m, row[lane + 32*i]);
        #pragma unroll
        for (int o = 16; o > 0; o >>= 1) m = fmaxf(m, __shfl_xor_sync(0xffffffffu, m, o));
        float s = 0.f;
        #pragma unroll
        for (int i = 0; i < 32; i++) {
            float e = expf(row[lane + 32*i] - m);
            row[lane + 32*i] = e;
            s += e;
        }
        #pragma unroll
        for (int o = 16; o > 0; o >>= 1) s += __shfl_xor_sync(0xffffffffu, s, o);
        float inv = 1.0f / s;
        #pragma unroll
        for (int i = 0; i < 32; i++) row[lane + 32*i] *= inv;
    }
    __syncthreads();

    // ---- ctx = probs @ V (scatter, rounded)
    {
        int e = t & 63, ug = t >> 6;
        float acc9[5] = {0.f, 0.f, 0.f, 0.f, 0.f};
        for (int st = 0; st < 8; st++) {
            #pragma unroll
            for (int i = 0; i < 4; i++) {
                int f = t + i*ATT_THREADS;
                int s = f >> 4, ec = (f & 15) << 2;
                float4 vv = *(const float4*)&g_v[(size_t)((b<<10) + st*128 + s)*DM + h*HD + ec];
                kt[(ec+0)*129 + s] = vv.x;
                kt[(ec+1)*129 + s] = vv.y;
                kt[(ec+2)*129 + s] = vv.z;
                kt[(ec+3)*129 + s] = vv.w;
            }
            __syncthreads();
            for (int s = 0; s < 128; s++) {
                float v = kt[e*129 + s];
                #pragma unroll
                for (int uu = 0; uu < 5; uu++) {
                    int u = ug + (uu << 3);
                    if (u < SK) acc9[uu] += scores[u*1024 + st*128 + s] * v;
                }
            }
            __syncthreads();
        }
        #pragma unroll
        for (int uu = 0; uu < 5; uu++) {
            int u = ug + (uu << 3);
            if (u < SK) {
                int qi = tops[u];
                g_ctx[(size_t)((b<<10) + qi)*DM + h*HD + e] = to_tf32(acc9[uu]);
            }
        }
    }
}

// ---------------------------------------------------------------------------
// LayerNorm (row of 512, 256 threads). RND: round output to tf32.
// ---------------------------------------------------------------------------
template<bool RND>
__global__ void ln_kernel(const float* __restrict__ in, float* __restrict__ out,
                          const float* __restrict__ g, const float* __restrict__ be) {
    int row = blockIdx.x;
    int t   = threadIdx.x;
    float v0 = in[(size_t)row*DM + t];
    float v1 = in[(size_t)row*DM + t + 256];
    __shared__ float red[256];
    red[t] = v0 + v1; __syncthreads();
    for (int s = 128; s > 0; s >>= 1) { if (t < s) red[t] += red[t+s]; __syncthreads(); }
    float mean = red[0] * (1.0f/DM);
    __syncthreads();
    float d0 = v0 - mean, d1 = v1 - mean;
    red[t] = d0*d0 + d1*d1; __syncthreads();
    for (int s = 128; s > 0; s >>= 1) { if (t < s) red[t] += red[t+s]; __syncthreads(); }
    float rstd = rsqrtf(red[0] * (1.0f/DM) + 1e-5f);
    float o0 = d0*rstd*g[t]     + be[t];
    float o1 = d1*rstd*g[t+256] + be[t+256];
    if (RND) { o0 = to_tf32(o0); o1 = to_tf32(o1); }
    out[(size_t)row*DM + t]       = o0;
    out[(size_t)row*DM + t + 256] = o1;
}

// ---------------------------------------------------------------------------
// Mean pool stage 1; fused pool stage 2 + classifier (warp per (b,c))
// ---------------------------------------------------------------------------
__global__ void pool1_kernel() {
    int b = blockIdx.x, r = blockIdx.y;
    int d = threadIdx.x;
    float acc = 0.f;
    for (int l = r*128; l < r*128 + 128; l++)
        acc += g_tmp[(size_t)(b*L_+l)*DM + d];
    g_poolp[(b*8 + r)*DM + d] = acc;
}

__global__ void poolcls_kernel(const float* __restrict__ Wc,
                               const float* __restrict__ bc,
                               float* __restrict__ out) {
    __shared__ float pooled[B_*DM];
    int t = threadIdx.x;          // 512
    int lane = t & 31, w = t >> 5;
    #pragma unroll
    for (int i = 0; i < 4; i++) {
        int f = t + i*512;
        int b = f >> 9, d = f & 511;
        float acc = 0.f;
        #pragma unroll
        for (int r = 0; r < 8; r++) acc += g_poolp[(b*8 + r)*DM + d];
        pooled[f] = acc * (1.0f/L_);
    }
    __syncthreads();
    for (int bcp = w; bcp < B_*10; bcp += 16) {
        int b = bcp / 10, c = bcp % 10;
        float acc = 0.f;
        for (int d = lane; d < DM; d += 32)
            acc += pooled[b*DM + d] * Wc[d*10 + c];
        #pragma unroll
        for (int o = 16; o > 0; o >>= 1) acc += __shfl_xor_sync(0xffffffffu, acc, o);
        if (lane == 0) out[bcp] = acc + bc[c];
    }
}

// ---------------------------------------------------------------------------
extern "C" void kernel_launch(void* const* d_in, const int* in_sizes, int n_in,
                              void* d_out, int out_size) {
    const float* src   = (const float*)d_in[0];
    const int*   idxs  = (const int*)  d_in[1];
    const float* Wemb  = (const float*)d_in[2];
    const float* bemb  = (const float*)d_in[3];
    const float* Wq    = (const float*)d_in[4];
    const float* bq    = (const float*)d_in[5];
    const float* Wk    = (const float*)d_in[6];
    const float* bk    = (const float*)d_in[7];
    const float* Wv    = (const float*)d_in[8];
    const float* bv    = (const float*)d_in[9];
    const float* Wo    = (const float*)d_in[10];
    const float* bo    = (const float*)d_in[11];
    const float* g1    = (const float*)d_in[12];
    const float* beta1 = (const float*)d_in[13];
    const float* W1    = (const float*)d_in[14];
    const float* bf1   = (const float*)d_in[15];
    const float* W2    = (const float*)d_in[16];
    const float* bf2   = (const float*)d_in[17];
    const float* g2    = (const float*)d_in[18];
    const float* beta2 = (const float*)d_in[19];
    const float* gf    = (const float*)d_in[20];
    const float* betaf = (const float*)d_in[21];
    const float* Wc    = (const float*)d_in[22];
    const float* bc    = (const float*)d_in[23];

    void *px_, *ptmp_, *pq_, *pk_, *pv_, *pctx_, *pff_, *pwr_;
    cudaGetSymbolAddress(&px_,   g_x);
    cudaGetSymbolAddress(&ptmp_, g_tmp);
    cudaGetSymbolAddress(&pq_,   g_q);
    cudaGetSymbolAddress(&pk_,   g_k);
    cudaGetSymbolAddress(&pv_,   g_v);
    cudaGetSymbolAddress(&pctx_, g_ctx);
    cudaGetSymbolAddress(&pff_,  g_ff);
    cudaGetSymbolAddress(&pwr_,  g_wr);
    float* px   = (float*)px_;
    float* ptmp = (float*)ptmp_;
    float* pq   = (float*)pq_;
    float* pk   = (float*)pk_;
    float* pv   = (float*)pv_;
    float* pctx = (float*)pctx_;
    float* pff  = (float*)pff_;
    float* pwr  = (float*)pwr_;

    const int attn_smem = ATT_SMEM_FLOATS * 4;
    static int configured = 0;
    if (!configured) {
        configured = 1;
        cudaFuncSetAttribute(attn_fused, cudaFuncAttributeMaxDynamicSharedMemorySize, attn_smem);
        cudaFuncSetAttribute((const void*)qkv_tc, cudaFuncAttributeMaxDynamicSharedMemorySize, GEMM_SMEM);
        cudaFuncSetAttribute((const void*)gemm_tc<false,false>, cudaFuncAttributeMaxDynamicSharedMemorySize, GEMM_SMEM);
        cudaFuncSetAttribute((const void*)gemm_tc<true,true>,   cudaFuncAttributeMaxDynamicSharedMemorySize, GEMM_SMEM);
        cudaFuncSetAttribute((const void*)splitk_tc<256>, cudaFuncAttributeMaxDynamicSharedMemorySize, GEMM_SMEM);
        cudaFuncSetAttribute((const void*)splitk_tc<512>, cudaFuncAttributeMaxDynamicSharedMemorySize, GEMM_SMEM);
    }

    const int QS = 2*DM*DM;
    prep_kernel<<<NTOK + RND_BLOCKS, 512>>>(src, Wemb, bemb, Wq, Wk, Wv, Wo, W1, W2);

    for (int l = 0; l < 2; l++) {
        const float* W1_l = pwr + 4*QS + (size_t)l*DM*DFF;
        const float* W2_l = pwr + 4*QS + 2*DM*DFF + (size_t)l*DFF*DM;
        const float* Wo_l = pwr + 3*QS + (size_t)l*DM*DM;

        dim3 gQKV(DM/128, NTOK/128, 3);      // (4, 32, 3)
        dim3 gFF(DFF/128, NTOK/128);         // (16, 32)
        dim3 gWO(DM/128, NTOK/128, 2);       // (4, 32, 2) split-K2
        dim3 gSP(DM/128, NTOK/128, SPLITK);  // (4, 32, 4) split-K4

        qkv_tc<<<gQKV, 256, GEMM_SMEM>>>(px, l, bq + l*DM, bk + l*DM, bv + l*DM,
                                         pq, pk, pv);

        sampleM_kernel<<<(B_*NH*L_)/4, 128>>>(idxs + (size_t)l*L_*SK);
        attn_fused<<<B_*NH, ATT_THREADS, attn_smem>>>();

        // Wo: split-K2 + fused reduce/bias/resid/LN
        splitk_tc<256><<<gWO, 256, GEMM_SMEM>>>(pctx, Wo_l, DM);
        reduce_ln_kernel<2><<<NTOK, 256>>>(bo + l*DM, px, g1 + l*DM, beta1 + l*DM, px);

        gemm_tc<true,true><<<gFF, 256, GEMM_SMEM>>>(px, W1_l, bf1 + l*DFF, nullptr, pff, DFF, DM);
        splitk_tc<512><<<gSP, 256, GEMM_SMEM>>>(pff, W2_l, DFF);
        reduce_ln_kernel<4><<<NTOK, 256>>>(bf2 + l*DM, px, g2 + l*DM, beta2 + l*DM, px);
    }

    ln_kernel<false><<<NTOK, 256>>>(px, ptmp, gf, betaf);
    pool1_kernel<<<dim3(B_, 8), 512>>>();
    poolcls_kernel<<<1, 512>>>(Wc, bc, (float*)d_out);
}

// round 10
// speedup vs baseline: 1.5473x; 1.1834x over previous
#include <cuda_runtime.h>
#include <cuda_bf16.h>
#include <math.h>
#include <float.h>
#include <stdint.h>

// ---------------------------------------------------------------------------
// Informer: B=4, L=1024, DM=512, NH=8, HD=64, DFF=2048, SK=35, 2 layers
// ---------------------------------------------------------------------------
#define B_   4
#define L_   1024
#define DM   512
#define NH   8
#define HD   64
#define DFF  2048
#define SK   35
#define NTOK (B_*L_)   // 4096
#define SPLITK 4
#define GS 3           // cp.async pipeline stages
#define NBH  (B_*NH)   // 32

__device__ float g_x   [NTOK*DM];
__device__ float g_tmp [NTOK*DM];
__device__ float g_q   [NTOK*DM];
__device__ float g_k   [NTOK*DM];
__device__ float g_v   [NTOK*DM];
__device__ float g_ctx [NTOK*DM];
__device__ float g_ff  [NTOK*DFF];
__device__ float g_split[SPLITK*NTOK*DM];
__device__ float g_M   [NBH*L_];
__device__ float g_poolp[B_*8*DM];
__device__ __nv_bfloat16 g_qh[NTOK*DM];   // bf16 copies for sampling
__device__ __nv_bfloat16 g_kh[NTOK*DM];
// attention intermediates
__device__ int   g_top  [NBH*SK];
__device__ float g_qsel [NBH*SK*HD];
__device__ float g_S    [(size_t)NBH*SK*L_];
__device__ float g_pmax [NBH*SK*8];
__device__ float g_psum [NBH*8*SK];
__device__ float g_cpart[(size_t)NBH*8*SK*HD];
// pre-rounded (tf32-rna) weights: Wq|Wk|Wv|Wo (both layers each) then W1, W2
#define WR_TOTAL (4*2*DM*DM + 2*DM*DFF + 2*DFF*DM)
__device__ float g_wr[WR_TOTAL];

// ---------------------------------------------------------------------------
__device__ __forceinline__ float to_tf32(float x) {
    uint32_t u;
    asm("cvt.rna.tf32.f32 %0, %1;" : "=r"(u) : "f"(x));
    return __uint_as_float(u);
}

__device__ __forceinline__ void mma_tf32(float* c, const uint32_t* a,
                                         uint32_t b0, uint32_t b1) {
    asm volatile(
        "mma.sync.aligned.m16n8k8.row.col.f32.tf32.tf32.f32 "
        "{%0,%1,%2,%3},{%4,%5,%6,%7},{%8,%9},{%0,%1,%2,%3};"
        : "+f"(c[0]), "+f"(c[1]), "+f"(c[2]), "+f"(c[3])
        : "r"(a[0]), "r"(a[1]), "r"(a[2]), "r"(a[3]), "r"(b0), "r"(b1));
}

__device__ __forceinline__ void cp16(void* smem, const void* g) {
    uint32_t s = (uint32_t)__cvta_generic_to_shared(smem);
    asm volatile("cp.async.cg.shared.global [%0], [%1], 16;\n" :: "r"(s), "l"(g));
}
#define CP_COMMIT() asm volatile("cp.async.commit_group;\n" ::: "memory")
#define CP_WAIT1()  asm volatile("cp.async.wait_group 1;\n" ::: "memory")

// ---------------------------------------------------------------------------
// Fused prologue: embed+posenc (blocks 0..NTOK-1) and weight tf32-rounding.
// ---------------------------------------------------------------------------
#define RND_BLOCKS ((WR_TOTAL/4 + 511) / 512)

__global__ void prep_kernel(const float* __restrict__ src,
                            const float* __restrict__ Wemb,
                            const float* __restrict__ bemb,
                            const float* __restrict__ Wq, const float* __restrict__ Wk,
                            const float* __restrict__ Wv, const float* __restrict__ Wo,
                            const float* __restrict__ W1, const float* __restrict__ W2) {
    const int bx = blockIdx.x;
    if (bx < NTOK) {
        int row = bx;
        int l   = row & (L_-1);
        int d   = threadIdx.x;
        __shared__ float s[32];
        if (d < 32) s[d] = src[row*32 + d];
        __syncthreads();
        float acc = bemb[d];
        #pragma unroll
        for (int k = 0; k < 32; k++) acc += s[k] * Wemb[k*DM + d];
        int i2 = d & ~1;
        float div = expf(-(float)i2 * (9.210340371976184f / 512.0f));
        float ang = (float)l * div;
        acc += (d & 1) ? cosf(ang) : sinf(ang);
        g_x[row*DM + d] = to_tf32(acc);
    } else {
        const int QS = 2*DM*DM;
        int i4 = (bx - NTOK) * 512 + threadIdx.x;
        int f  = i4 * 4;
        if (f >= WR_TOTAL) return;
        const float* sp;
        int off;
        if      (f < QS)      { sp = Wq; off = f; }
        else if (f < 2*QS)    { sp = Wk; off = f - QS; }
        else if (f < 3*QS)    { sp = Wv; off = f - 2*QS; }
        else if (f < 4*QS)    { sp = Wo; off = f - 3*QS; }
        else if (f < 4*QS + 2*DM*DFF) { sp = W1; off = f - 4*QS; }
        else                  { sp = W2; off = f - 4*QS - 2*DM*DFF; }
        float4 v = *(const float4*)&sp[off];
        v.x = to_tf32(v.x); v.y = to_tf32(v.y); v.z = to_tf32(v.z); v.w = to_tf32(v.w);
        *(float4*)&g_wr[f] = v;
    }
}

// ---------------------------------------------------------------------------
// tf32 GEMM, cp.async 3-stage pipeline. Block tile 128x128x16, 256 threads.
// ---------------------------------------------------------------------------
#define AS(s,m,k) As[(s)*2560 + (m)*20 + (k)]
#define BS(s,k,n) Bs[(s)*2176 + (k)*136 + (n)]
#define GEMM_SMEM ((GS*2560 + GS*2176) * 4)

__device__ __forceinline__ void issue_tile(
        float* As, float* Bs, const float* A, const float* W,
        int lda, int N, int m0, int n0, int k0, int s, int tid) {
    int f0 = tid, f1 = tid + 256;
    int ma0 = f0 >> 2, kc0 = (f0 & 3) << 2;
    int ma1 = f1 >> 2, kc1 = (f1 & 3) << 2;
    cp16(&AS(s,ma0,kc0), A + (size_t)(m0+ma0)*lda + k0 + kc0);
    cp16(&AS(s,ma1,kc1), A + (size_t)(m0+ma1)*lda + k0 + kc1);
    int kr0 = f0 >> 5, nc0 = (f0 & 31) << 2;
    int kr1 = f1 >> 5, nc1 = (f1 & 31) << 2;
    cp16(&BS(s,kr0,nc0), W + (size_t)(k0+kr0)*N + n0 + nc0);
    cp16(&BS(s,kr1,nc1), W + (size_t)(k0+kr1)*N + n0 + nc1);
}

template<bool GELU, bool RAW, bool RND>
__device__ __forceinline__ void gemm_body(
        const float* __restrict__ A, const float* __restrict__ W,
        const float* __restrict__ bias, const float* __restrict__ resid,
        float* __restrict__ C, __nv_bfloat16* __restrict__ Hout,
        int N, int K, int lda, int bx, int by) {
    extern __shared__ float gsm[];
    float* As = gsm;
    float* Bs = gsm + GS*2560;

    const int tid  = threadIdx.x;
    const int w    = tid >> 5;
    const int lane = tid & 31;
    const int grp  = lane >> 2;
    const int qd   = lane & 3;
    const int warp_m = (w & 3) * 32;
    const int warp_n = (w >> 2) * 64;
    const int m0 = by * 128;
    const int n0 = bx * 128;

    float acc[2][8][4];
    #pragma unroll
    for (int mi = 0; mi < 2; mi++)
        #pragma unroll
        for (int ni = 0; ni < 8; ni++)
            #pragma unroll
            for (int j = 0; j < 4; j++) acc[mi][ni][j] = 0.f;

    const int nt = K >> 4;

    issue_tile(As, Bs, A, W, lda, N, m0, n0, 0, 0, tid);  CP_COMMIT();
    issue_tile(As, Bs, A, W, lda, N, m0, n0, 16, 1, tid); CP_COMMIT();

    for (int t = 0; t < nt; t++) {
        CP_WAIT1();
        __syncthreads();
        const int s = t % GS;
        if (t + 2 < nt)
            issue_tile(As, Bs, A, W, lda, N, m0, n0, (t+2) << 4, (t+2) % GS, tid);
        CP_COMMIT();

        #pragma unroll
        for (int kk = 0; kk < 16; kk += 8) {
            uint32_t af[2][4];
            #pragma unroll
            for (int mi = 0; mi < 2; mi++) {
                int mb = warp_m + mi*16 + grp;
                af[mi][0] = __float_as_uint(AS(s, mb,   kk+qd));
                af[mi][1] = __float_as_uint(AS(s, mb+8, kk+qd));
                af[mi][2] = __float_as_uint(AS(s, mb,   kk+qd+4));
                af[mi][3] = __float_as_uint(AS(s, mb+8, kk+qd+4));
            }
            #pragma unroll
            for (int ni = 0; ni < 8; ni++) {
                int nb = warp_n + ni*8 + grp;
                uint32_t b0 = __float_as_uint(BS(s, kk+qd,   nb));
                uint32_t b1 = __float_as_uint(BS(s, kk+qd+4, nb));
                mma_tf32(acc[0][ni], af[0], b0, b1);
                mma_tf32(acc[1][ni], af[1], b0, b1);
            }
        }
    }

    #pragma unroll
    for (int mi = 0; mi < 2; mi++) {
        int r0 = m0 + warp_m + mi*16 + grp;
        #pragma unroll
        for (int ni = 0; ni < 8; ni++) {
            int c = n0 + warp_n + ni*8 + qd*2;
            float v0 = acc[mi][ni][0];
            float v1 = acc[mi][ni][1];
            float v2 = acc[mi][ni][2];
            float v3 = acc[mi][ni][3];
            if (!RAW) {
                float b0 = bias[c], b1 = bias[c+1];
                v0 += b0; v1 += b1; v2 += b0; v3 += b1;
                if (resid) {
                    v0 += resid[(size_t)r0*N + c];     v1 += resid[(size_t)r0*N + c + 1];
                    v2 += resid[(size_t)(r0+8)*N + c]; v3 += resid[(size_t)(r0+8)*N + c + 1];
                }
                if (GELU) {
                    v0 = 0.5f*v0*(1.0f + erff(v0*0.70710678118654752f));
                    v1 = 0.5f*v1*(1.0f + erff(v1*0.70710678118654752f));
                    v2 = 0.5f*v2*(1.0f + erff(v2*0.70710678118654752f));
                    v3 = 0.5f*v3*(1.0f + erff(v3*0.70710678118654752f));
                }
            }
            if (RND) {
                v0 = to_tf32(v0); v1 = to_tf32(v1);
                v2 = to_tf32(v2); v3 = to_tf32(v3);
            }
            *(float2*)&C[(size_t)r0*N + c]     = make_float2(v0, v1);
            *(float2*)&C[(size_t)(r0+8)*N + c] = make_float2(v2, v3);
            if (Hout) {
                *(__nv_bfloat162*)&Hout[(size_t)r0*N + c] =
                    __floats2bfloat162_rn(v0, v1);
                *(__nv_bfloat162*)&Hout[(size_t)(r0+8)*N + c] =
                    __floats2bfloat162_rn(v2, v3);
            }
        }
    }
}

template<bool GELU, bool RND>
__global__ void __launch_bounds__(256, 2)
gemm_tc(const float* __restrict__ A, const float* __restrict__ W,
        const float* __restrict__ bias, const float* __restrict__ resid,
        float* __restrict__ C, int N, int K) {
    gemm_body<GELU, false, RND>(A, W, bias, resid, C, nullptr, N, K, K,
                                blockIdx.x, blockIdx.y);
}

// Fused QKV: blockIdx.z selects projection; Q,K also dual-stored as bf16.
__global__ void __launch_bounds__(256, 2)
qkv_tc(const float* __restrict__ A, int layer,
       const float* __restrict__ bq, const float* __restrict__ bk,
       const float* __restrict__ bv,
       float* __restrict__ Q, float* __restrict__ Ko, float* __restrict__ V) {
    const float* W; const float* bias; float* C; __nv_bfloat16* H;
    const int QS = 2*DM*DM;
    size_t loff = (size_t)layer*DM*DM;
    if (blockIdx.z == 0)      { W = g_wr + loff;        bias = bq; C = Q;  H = g_qh; }
    else if (blockIdx.z == 1) { W = g_wr + QS + loff;   bias = bk; C = Ko; H = g_kh; }
    else                      { W = g_wr + 2*QS + loff; bias = bv; C = V;  H = nullptr; }
    gemm_body<false, false, false>(A, W, bias, nullptr, C, H, DM, DM, DM,
                                   blockIdx.x, blockIdx.y);
}

// Generic split-K partial GEMM: blockIdx.z = k-chunk of size KC.
template<int KC>
__global__ void __launch_bounds__(256, 2)
splitk_tc(const float* __restrict__ A, const float* __restrict__ W,
          int lda) {
    const int kc = blockIdx.z;
    gemm_body<false, true, false>(A + kc*KC, W + (size_t)kc*KC*DM,
                                  nullptr, nullptr,
                                  g_split + (size_t)kc*NTOK*DM,
                                  nullptr, DM, KC, lda, blockIdx.x, blockIdx.y);
}

// Fused split-K reduce + bias + residual + LayerNorm (output rounded).
template<int NS>
__global__ void reduce_ln_kernel(const float* __restrict__ bias,
                                 const float* __restrict__ resid,
                                 const float* __restrict__ g,
                                 const float* __restrict__ be,
                                 float* __restrict__ out) {
    int row = blockIdx.x;
    int t   = threadIdx.x;
    size_t o0 = (size_t)row*DM + t;
    size_t o1 = o0 + 256;
    float v0 = resid[o0] + bias[t];
    float v1 = resid[o1] + bias[t+256];
    #pragma unroll
    for (int s = 0; s < NS; s++) {
        v0 += g_split[(size_t)s*NTOK*DM + o0];
        v1 += g_split[(size_t)s*NTOK*DM + o1];
    }
    __shared__ float red[256];
    red[t] = v0 + v1; __syncthreads();
    for (int s = 128; s > 0; s >>= 1) { if (t < s) red[t] += red[t+s]; __syncthreads(); }
    float mean = red[0] * (1.0f/DM);
    __syncthreads();
    float d0 = v0 - mean, d1 = v1 - mean;
    red[t] = d0*d0 + d1*d1; __syncthreads();
    for (int s = 128; s > 0; s >>= 1) { if (t < s) red[t] += red[t+s]; __syncthreads(); }
    float rstd = rsqrtf(red[0] * (1.0f/DM) + 1e-5f);
    out[o0] = to_tf32(d0*rstd*g[t]     + be[t]);
    out[o1] = to_tf32(d1*rstd*g[t+256] + be[t+256]);
}

// ---------------------------------------------------------------------------
// Sampled sparsity measure M (unchanged from round 7)
// ---------------------------------------------------------------------------
__global__ void sampleM_kernel(const int* __restrict__ idxs) {
    int wg   = (blockIdx.x * blockDim.x + threadIdx.x) >> 5;
    int lane = threadIdx.x & 31;
    if (wg >= NBH*L_) return;
    int i = wg & (L_-1);
    int h = (wg >> 10) & (NH-1);
    int b = wg >> 13;
    const int half = lane >> 4;
    const int sub  = lane & 15;

    const float2* Qr8 = (const float2*)&g_qh[(size_t)(b*L_ + i)*DM + h*HD];
    float2 qraw = Qr8[sub];
    uint32_t qlo = __float_as_uint(qraw.x), qhi = __float_as_uint(qraw.y);
    float2 q0 = __bfloat1622float2(*(__nv_bfloat162*)&qlo);
    float2 q1 = __bfloat1622float2(*(__nv_bfloat162*)&qhi);

    int idxA = idxs[i*SK + (lane < SK ? lane : 0)];
    int idxB = idxs[i*SK + ((32 + lane) < SK ? 32 + lane : 0)];

    float mx = -FLT_MAX, sm = 0.f;
    #pragma unroll 2
    for (int jj = 0; jj < 18; jj++) {
        int j = 2*jj + half;
        int srcA = __shfl_sync(0xffffffffu, idxA, j & 31);
        int srcB = __shfl_sync(0xffffffffu, idxB, (j - 32) & 31);
        int src  = (j < 32) ? srcA : srcB;
        bool valid = (j < SK);
        float p = 0.f;
        if (valid) {
            const float2* Kr8 = (const float2*)&g_kh[(size_t)(b*L_ + src)*DM + h*HD];
            float2 kraw = Kr8[sub];
            uint32_t klo = __float_as_uint(kraw.x), khi = __float_as_uint(kraw.y);
            float2 k0 = __bfloat1622float2(*(__nv_bfloat162*)&klo);
            float2 k1 = __bfloat1622float2(*(__nv_bfloat162*)&khi);
            p = q0.x*k0.x + q0.y*k0.y + q1.x*k1.x + q1.y*k1.y;
        }
        p += __shfl_xor_sync(0xffffffffu, p, 8);
        p += __shfl_xor_sync(0xffffffffu, p, 4);
        p += __shfl_xor_sync(0xffffffffu, p, 2);
        p += __shfl_xor_sync(0xffffffffu, p, 1);
        if (valid) { mx = fmaxf(mx, p); sm += p; }
    }
    float mxo = __shfl_xor_sync(0xffffffffu, mx, 16);
    float smo = __shfl_xor_sync(0xffffffffu, sm, 16);
    mx = fmaxf(mx, mxo);
    sm += smo;
    if (lane == 0) g_M[(b*NH+h)*L_ + i] = mx - sm * (1.0f/SK);
}

// ---------------------------------------------------------------------------
// Attention phase 1: top-k (radix select) + Qsel gather + vmean + ctx fill.
// Grid NBH, 512 threads.
// ---------------------------------------------------------------------------
__device__ __forceinline__ uint32_t f2ord(float f) {
    uint32_t u = __float_as_uint(f);
    return (u & 0x80000000u) ? ~u : (u | 0x80000000u);
}

__global__ void __launch_bounds__(512)
attn_prep() {
    __shared__ int   ties[1024];
    __shared__ int   s_cntA[32];
    __shared__ int   s_gt, s_tn;
    __shared__ float red[512];
    __shared__ __align__(16) float vmean[64];
    __shared__ int   tops[48];

    const int bh = blockIdx.x;
    const int b  = bh >> 3;
    const int h  = bh & 7;
    const int t  = threadIdx.x;
    const int lane = t & 31;

    // ---- exact top-35 via MSB radix select (set semantics; ties -> low idx)
    uint32_t u0 = f2ord(g_M[bh*L_ + t]);
    uint32_t u1 = f2ord(g_M[bh*L_ + t + 512]);
    if (t < 32) s_cntA[t] = 0;
    if (t == 0) { s_gt = 0; s_tn = 0; }
    __syncthreads();
    uint32_t prefix = 0;
    int need = SK;
    for (int bit = 31; bit >= 0; --bit) {
        uint32_t cd = (prefix >> bit) | 1u;
        int c = ((u0 >> bit) == cd) + ((u1 >> bit) == cd);
        int ws = __reduce_add_sync(0xffffffffu, c);
        if (lane == 0 && ws) atomicAdd(&s_cntA[bit], ws);
        __syncthreads();
        int cnt = s_cntA[bit];
        if (cnt >= need) prefix |= (1u << bit);
        else             need -= cnt;
    }
    if (u0 > prefix) tops[atomicAdd(&s_gt, 1)] = t;
    else if (u0 == prefix) ties[atomicAdd(&s_tn, 1)] = t;
    if (u1 > prefix) tops[atomicAdd(&s_gt, 1)] = t + 512;
    else if (u1 == prefix) ties[atomicAdd(&s_tn, 1)] = t + 512;
    __syncthreads();
    if (t == 0) {
        int base = s_gt, tn = s_tn;
        for (int sel = 0; sel < need; sel++) {
            int bi = -1, bvv = 0x7fffffff;
            for (int j = 0; j < tn; j++)
                if (ties[j] < bvv) { bvv = ties[j]; bi = j; }
            tops[base + sel] = bvv;
            ties[bi] = 0x7fffffff;
        }
    }
    __syncthreads();
    if (t < SK) g_top[bh*SK + t] = tops[t];

    // ---- gather selected Q rows into g_qsel
    for (int f = t; f < SK*HD; f += 512) {
        int u = f >> 6, k = f & 63;
        g_qsel[bh*SK*HD + f] = g_q[(size_t)((b<<10) + tops[u])*DM + h*HD + k];
    }

    // ---- vmean
    {
        int e = t & 63, r = t >> 6;
        float acc = 0.f;
        for (int l = r*128; l < r*128 + 128; l++)
            acc += g_v[(size_t)((b<<10) + l)*DM + h*HD + e];
        red[t] = acc;
        __syncthreads();
        if (t < 64) {
            float s = 0.f;
            #pragma unroll
            for (int rr = 0; rr < 8; rr++) s += red[t + rr*64];
            vmean[t] = to_tf32(s * (1.0f/L_));
        }
        __syncthreads();
    }

    // ---- broadcast fill ctx
    {
        const float4* vm4 = (const float4*)vmean;
        for (int f = t; f < (L_*HD)/4; f += 512) {
            int l = f >> 4, ev = f & 15;
            *(float4*)&g_ctx[(size_t)((b<<10) + l)*DM + h*HD + ev*4] = vm4[ev];
        }
    }
}

// ---------------------------------------------------------------------------
// Attention phase 2: scores for one (st, bh). Grid (8, NBH), 256 threads.
// Writes scaled scores to g_S and per-(u,st) max to g_pmax.
// ---------------------------------------------------------------------------
__global__ void __launch_bounds__(256)
attn_score() {
    __shared__ float kt[64*129];     // 33 KB
    __shared__ float sq[SK*HD];      // 8.75 KB

    const int st = blockIdx.x;
    const int bh = blockIdx.y;
    const int b  = bh >> 3;
    const int h  = bh & 7;
    const int t  = threadIdx.x;
    const int lane = t & 31;
    const int w  = t >> 5;           // 0..7

    #pragma unroll
    for (int i = 0; i < 8; i++) {
        int f = t + i*256;
        int s = f >> 4, ec = (f & 15) << 2;
        float4 kv = *(const float4*)&g_k[(size_t)((b<<10) + st*128 + s)*DM + h*HD + ec];
        kt[(ec+0)*129 + s] = kv.x;
        kt[(ec+1)*129 + s] = kv.y;
        kt[(ec+2)*129 + s] = kv.z;
        kt[(ec+3)*129 + s] = kv.w;
    }
    for (int f = t; f < SK*HD; f += 256) sq[f] = g_qsel[bh*SK*HD + f];
    __syncthreads();

    float acc[5][4];
    #pragma unroll
    for (int jj = 0; jj < 5; jj++)
        #pragma unroll
        for (int r = 0; r < 4; r++) acc[jj][r] = 0.f;

    for (int k = 0; k < 64; k++) {
        float kv0 = kt[k*129 + lane];
        float kv1 = kt[k*129 + lane + 32];
        float kv2 = kt[k*129 + lane + 64];
        float kv3 = kt[k*129 + lane + 96];
        #pragma unroll
        for (int jj = 0; jj < 5; jj++) {
            int u = w + 8*jj;
            if (u < SK) {
                float qv = sq[u*HD + k];
                acc[jj][0] += qv*kv0; acc[jj][1] += qv*kv1;
                acc[jj][2] += qv*kv2; acc[jj][3] += qv*kv3;
            }
        }
    }

    #pragma unroll
    for (int jj = 0; jj < 5; jj++) {
        int u = w + 8*jj;
        if (u < SK) {
            float s0 = acc[jj][0]*0.125f, s1 = acc[jj][1]*0.125f;
            float s2 = acc[jj][2]*0.125f, s3 = acc[jj][3]*0.125f;
            float m = fmaxf(fmaxf(s0, s1), fmaxf(s2, s3));
            #pragma unroll
            for (int o = 16; o > 0; o >>= 1) m = fmaxf(m, __shfl_xor_sync(0xffffffffu, m, o));
            if (lane == 0) g_pmax[(bh*SK + u)*8 + st] = m;
            float* row = &g_S[(size_t)(bh*SK + u)*L_ + st*128];
            row[lane]      = s0;
            row[lane + 32] = s1;
            row[lane + 64] = s2;
            row[lane + 96] = s3;
        }
    }
}

// ---------------------------------------------------------------------------
// Attention phase 3: partial softmax+ctx for one (st, bh). Grid (8, NBH),
// 256 threads, dynamic smem. p = exp(s - rowmax); psum & cpart partials.
// ---------------------------------------------------------------------------
#define CTX_SMEM_FLOATS (64*129 + SK*128 + 36)

__global__ void __launch_bounds__(256)
attn_ctx() {
    extern __shared__ float csm[];
    float* vt = csm;                 // 64*129
    float* ps = vt + 64*129;         // SK*128
    float* rm = ps + SK*128;         // 36

    const int st = blockIdx.x;
    const int bh = blockIdx.y;
    const int b  = bh >> 3;
    const int h  = bh & 7;
    const int t  = threadIdx.x;
    const int lane = t & 31;
    const int w  = t >> 5;

    if (t < SK) {
        float m = -FLT_MAX;
        #pragma unroll
        for (int i = 0; i < 8; i++) m = fmaxf(m, g_pmax[(bh*SK + t)*8 + i]);
        rm[t] = m;
    }
    #pragma unroll
    for (int i = 0; i < 8; i++) {
        int f = t + i*256;
        int s = f >> 4, ec = (f & 15) << 2;
        float4 vv = *(const float4*)&g_v[(size_t)((b<<10) + st*128 + s)*DM + h*HD + ec];
        vt[(ec+0)*129 + s] = vv.x;
        vt[(ec+1)*129 + s] = vv.y;
        vt[(ec+2)*129 + s] = vv.z;
        vt[(ec+3)*129 + s] = vv.w;
    }
    __syncthreads();

    for (int f = t; f < SK*128; f += 256) {
        int u = f >> 7, s = f & 127;
        ps[f] = expf(g_S[(size_t)(bh*SK + u)*L_ + st*128 + s] - rm[u]);
    }
    __syncthreads();

    // per-(u, st) partial sums
    #pragma unroll
    for (int jj = 0; jj < 5; jj++) {
        int u = w + 8*jj;
        if (u < SK) {
            float ss = ps[u*128 + lane] + ps[u*128 + lane + 32]
                     + ps[u*128 + lane + 64] + ps[u*128 + lane + 96];
            #pragma unroll
            for (int o = 16; o > 0; o >>= 1) ss += __shfl_xor_sync(0xffffffffu, ss, o);
            if (lane == 0) g_psum[(bh*8 + st)*SK + u] = ss;
        }
    }

    // partial context
    const int e  = t & 63;
    const int ug = t >> 6;           // 0..3
    float acc[9];
    #pragma unroll
    for (int jj = 0; jj < 9; jj++) acc[jj] = 0.f;
    for (int s = 0; s < 128; s++) {
        float v = vt[e*129 + s];
        #pragma unroll
        for (int jj = 0; jj < 9; jj++) {
            int u = ug + 4*jj;
            if (u < SK) acc[jj] += ps[u*128 + s] * v;
        }
    }
    #pragma unroll
    for (int jj = 0; jj < 9; jj++) {
        int u = ug + 4*jj;
        if (u < SK) g_cpart[((size_t)(bh*8 + st)*SK + u)*HD + e] = acc[jj];
    }
}

// ---------------------------------------------------------------------------
// Attention phase 4: reduce partials + normalize + scatter. Grid NBH, 512.
// ---------------------------------------------------------------------------
__global__ void __launch_bounds__(512)
attn_scatter() {
    __shared__ float zinv[48];
    __shared__ int   tops[48];
    const int bh = blockIdx.x;
    const int b  = bh >> 3;
    const int h  = bh & 7;
    const int t  = threadIdx.x;

    if (t < SK) {
        float z = 0.f;
        #pragma unroll
        for (int st = 0; st < 8; st++) z += g_psum[(bh*8 + st)*SK + t];
        zinv[t] = 1.0f / z;
        tops[t] = g_top[bh*SK + t];
    }
    __syncthreads();

    const int e  = t & 63;
    const int ug = t >> 6;           // 0..7
    #pragma unroll
    for (int jj = 0; jj < 5; jj++) {
        int u = ug + 8*jj;
        if (u < SK) {
            float c = 0.f;
            #pragma unroll
            for (int st = 0; st < 8; st++)
                c += g_cpart[((size_t)(bh*8 + st)*SK + u)*HD + e];
            g_ctx[(size_t)((b<<10) + tops[u])*DM + h*HD + e] = to_tf32(c * zinv[u]);
        }
    }
}

// ---------------------------------------------------------------------------
// LayerNorm (row of 512, 256 threads). RND: round output to tf32.
// ---------------------------------------------------------------------------
template<bool RND>
__global__ void ln_kernel(const float* __restrict__ in, float* __restrict__ out,
                          const float* __restrict__ g, const float* __restrict__ be) {
    int row = blockIdx.x;
    int t   = threadIdx.x;
    float v0 = in[(size_t)row*DM + t];
    float v1 = in[(size_t)row*DM + t + 256];
    __shared__ float red[256];
    red[t] = v0 + v1; __syncthreads();
    for (int s = 128; s > 0; s >>= 1) { if (t < s) red[t] += red[t+s]; __syncthreads(); }
    float mean = red[0] * (1.0f/DM);
    __syncthreads();
    float d0 = v0 - mean, d1 = v1 - mean;
    red[t] = d0*d0 + d1*d1; __syncthreads();
    for (int s = 128; s > 0; s >>= 1) { if (t < s) red[t] += red[t+s]; __syncthreads(); }
    float rstd = rsqrtf(red[0] * (1.0f/DM) + 1e-5f);
    float o0 = d0*rstd*g[t]     + be[t];
    float o1 = d1*rstd*g[t+256] + be[t+256];
    if (RND) { o0 = to_tf32(o0); o1 = to_tf32(o1); }
    out[(size_t)row*DM + t]       = o0;
    out[(size_t)row*DM + t + 256] = o1;
}

// ---------------------------------------------------------------------------
// Mean pool stage 1; fused pool stage 2 + classifier (warp per (b,c))
// ---------------------------------------------------------------------------
__global__ void pool1_kernel() {
    int b = blockIdx.x, r = blockIdx.y;
    int d = threadIdx.x;
    float acc = 0.f;
    for (int l = r*128; l < r*128 + 128; l++)
        acc += g_tmp[(size_t)(b*L_+l)*DM + d];
    g_poolp[(b*8 + r)*DM + d] = acc;
}

__global__ void poolcls_kernel(const float* __restrict__ Wc,
                               const float* __restrict__ bc,
                               float* __restrict__ out) {
    __shared__ float pooled[B_*DM];
    int t = threadIdx.x;          // 512
    int lane = t & 31, w = t >> 5;
    #pragma unroll
    for (int i = 0; i < 4; i++) {
        int f = t + i*512;
        int b = f >> 9, d = f & 511;
        float acc = 0.f;
        #pragma unroll
        for (int r = 0; r < 8; r++) acc += g_poolp[(b*8 + r)*DM + d];
        pooled[f] = acc * (1.0f/L_);
    }
    __syncthreads();
    for (int bcp = w; bcp < B_*10; bcp += 16) {
        int b = bcp / 10, c = bcp % 10;
        float acc = 0.f;
        for (int d = lane; d < DM; d += 32)
            acc += pooled[b*DM + d] * Wc[d*10 + c];
        #pragma unroll
        for (int o = 16; o > 0; o >>= 1) acc += __shfl_xor_sync(0xffffffffu, acc, o);
        if (lane == 0) out[bcp] = acc + bc[c];
    }
}

// ---------------------------------------------------------------------------
extern "C" void kernel_launch(void* const* d_in, const int* in_sizes, int n_in,
                              void* d_out, int out_size) {
    const float* src   = (const float*)d_in[0];
    const int*   idxs  = (const int*)  d_in[1];
    const float* Wemb  = (const float*)d_in[2];
    const float* bemb  = (const float*)d_in[3];
    const float* Wq    = (const float*)d_in[4];
    const float* bq    = (const float*)d_in[5];
    const float* Wk    = (const float*)d_in[6];
    const float* bk    = (const float*)d_in[7];
    const float* Wv    = (const float*)d_in[8];
    const float* bv    = (const float*)d_in[9];
    const float* Wo    = (const float*)d_in[10];
    const float* bo    = (const float*)d_in[11];
    const float* g1    = (const float*)d_in[12];
    const float* beta1 = (const float*)d_in[13];
    const float* W1    = (const float*)d_in[14];
    const float* bf1   = (const float*)d_in[15];
    const float* W2    = (const float*)d_in[16];
    const float* bf2   = (const float*)d_in[17];
    const float* g2    = (const float*)d_in[18];
    const float* beta2 = (const float*)d_in[19];
    const float* gf    = (const float*)d_in[20];
    const float* betaf = (const float*)d_in[21];
    const float* Wc    = (const float*)d_in[22];
    const float* bc    = (const float*)d_in[23];

    void *px_, *ptmp_, *pq_, *pk_, *pv_, *pctx_, *pff_, *pwr_;
    cudaGetSymbolAddress(&px_,   g_x);
    cudaGetSymbolAddress(&ptmp_, g_tmp);
    cudaGetSymbolAddress(&pq_,   g_q);
    cudaGetSymbolAddress(&pk_,   g_k);
    cudaGetSymbolAddress(&pv_,   g_v);
    cudaGetSymbolAddress(&pctx_, g_ctx);
    cudaGetSymbolAddress(&pff_,  g_ff);
    cudaGetSymbolAddress(&pwr_,  g_wr);
    float* px   = (float*)px_;
    float* ptmp = (float*)ptmp_;
    float* pq   = (float*)pq_;
    float* pk   = (float*)pk_;
    float* pv   = (float*)pv_;
    float* pctx = (float*)pctx_;
    float* pff  = (float*)pff_;
    float* pwr  = (float*)pwr_;

    const int ctx_smem = CTX_SMEM_FLOATS * 4;
    static int configured = 0;
    if (!configured) {
        configured = 1;
        cudaFuncSetAttribute(attn_ctx, cudaFuncAttributeMaxDynamicSharedMemorySize, ctx_smem);
        cudaFuncSetAttribute((const void*)qkv_tc, cudaFuncAttributeMaxDynamicSharedMemorySize, GEMM_SMEM);
        cudaFuncSetAttribute((const void*)gemm_tc<false,false>, cudaFuncAttributeMaxDynamicSharedMemorySize, GEMM_SMEM);
        cudaFuncSetAttribute((const void*)gemm_tc<true,true>,   cudaFuncAttributeMaxDynamicSharedMemorySize, GEMM_SMEM);
        cudaFuncSetAttribute((const void*)splitk_tc<256>, cudaFuncAttributeMaxDynamicSharedMemorySize, GEMM_SMEM);
        cudaFuncSetAttribute((const void*)splitk_tc<512>, cudaFuncAttributeMaxDynamicSharedMemorySize, GEMM_SMEM);
    }

    const int QS = 2*DM*DM;
    prep_kernel<<<NTOK + RND_BLOCKS, 512>>>(src, Wemb, bemb, Wq, Wk, Wv, Wo, W1, W2);

    for (int l = 0; l < 2; l++) {
        const float* W1_l = pwr + 4*QS + (size_t)l*DM*DFF;
        const float* W2_l = pwr + 4*QS + 2*DM*DFF + (size_t)l*DFF*DM;
        const float* Wo_l = pwr + 3*QS + (size_t)l*DM*DM;

        dim3 gQKV(DM/128, NTOK/128, 3);      // (4, 32, 3)
        dim3 gFF(DFF/128, NTOK/128);         // (16, 32)
        dim3 gWO(DM/128, NTOK/128, 2);       // (4, 32, 2) split-K2
        dim3 gSP(DM/128, NTOK/128, SPLITK);  // (4, 32, 4) split-K4
        dim3 gATT(8, NBH);                   // (8, 32) = 256 blocks

        qkv_tc<<<gQKV, 256, GEMM_SMEM>>>(px, l, bq + l*DM, bk + l*DM, bv + l*DM,
                                         pq, pk, pv);

        sampleM_kernel<<<(NBH*L_)/4, 128>>>(idxs + (size_t)l*L_*SK);
        attn_prep<<<NBH, 512>>>();
        attn_score<<<gATT, 256>>>();
        attn_ctx<<<gATT, 256, ctx_smem>>>();
        attn_scatter<<<NBH, 512>>>();

        splitk_tc<256><<<gWO, 256, GEMM_SMEM>>>(pctx, Wo_l, DM);
        reduce_ln_kernel<2><<<NTOK, 256>>>(bo + l*DM, px, g1 + l*DM, beta1 + l*DM, px);

        gemm_tc<true,true><<<gFF, 256, GEMM_SMEM>>>(px, W1_l, bf1 + l*DFF, nullptr, pff, DFF, DM);
        splitk_tc<512><<<gSP, 256, GEMM_SMEM>>>(pff, W2_l, DFF);
        reduce_ln_kernel<4><<<NTOK, 256>>>(bf2 + l*DM, px, g2 + l*DM, beta2 + l*DM, px);
    }

    ln_kernel<false><<<NTOK, 256>>>(px, ptmp, gf, betaf);
    pool1_kernel<<<dim3(B_, 8), 512>>>();
    poolcls_kernel<<<1, 512>>>(Wc, bc, (float*)d_out);
}

// round 11
// speedup vs baseline: 1.6119x; 1.0418x over previous
#include <cuda_runtime.h>
#include <cuda_bf16.h>
#include <math.h>
#include <float.h>
#include <stdint.h>

// ---------------------------------------------------------------------------
// Informer: B=4, L=1024, DM=512, NH=8, HD=64, DFF=2048, SK=35, 2 layers
// ---------------------------------------------------------------------------
#define B_   4
#define L_   1024
#define DM   512
#define NH   8
#define HD   64
#define DFF  2048
#define SK   35
#define NTOK (B_*L_)   // 4096
#define SPLITK 4
#define GS 3           // cp.async pipeline stages
#define NBH  (B_*NH)   // 32

__device__ float g_x   [NTOK*DM];
__device__ float g_tmp [NTOK*DM];
__device__ float g_q   [NTOK*DM];
__device__ float g_k   [NTOK*DM];
__device__ float g_v   [NTOK*DM];
__device__ float g_ctx [NTOK*DM];
__device__ float g_ff  [NTOK*DFF];
__device__ float g_split[SPLITK*NTOK*DM];
__device__ float g_M   [NBH*L_];
__device__ float g_poolp[B_*8*DM];
__device__ __nv_bfloat16 g_qh[NTOK*DM];   // bf16 copies for sampling
__device__ __nv_bfloat16 g_kh[NTOK*DM];
// attention intermediates
__device__ int   g_top  [NBH*SK];
__device__ float g_qsel [NBH*SK*HD];
__device__ float g_vmp  [NBH*8*64];       // vmean partials
__device__ float g_pmax [NBH*SK*8];
__device__ float g_psum [NBH*8*SK];
__device__ float g_cpart[(size_t)NBH*8*SK*HD];
// pre-rounded (tf32-rna) weights: Wq|Wk|Wv|Wo (both layers each) then W1, W2
#define WR_TOTAL (4*2*DM*DM + 2*DM*DFF + 2*DFF*DM)
__device__ float g_wr[WR_TOTAL];

// ---------------------------------------------------------------------------
__device__ __forceinline__ float to_tf32(float x) {
    uint32_t u;
    asm("cvt.rna.tf32.f32 %0, %1;" : "=r"(u) : "f"(x));
    return __uint_as_float(u);
}

__device__ __forceinline__ void mma_tf32(float* c, const uint32_t* a,
                                         uint32_t b0, uint32_t b1) {
    asm volatile(
        "mma.sync.aligned.m16n8k8.row.col.f32.tf32.tf32.f32 "
        "{%0,%1,%2,%3},{%4,%5,%6,%7},{%8,%9},{%0,%1,%2,%3};"
        : "+f"(c[0]), "+f"(c[1]), "+f"(c[2]), "+f"(c[3])
        : "r"(a[0]), "r"(a[1]), "r"(a[2]), "r"(a[3]), "r"(b0), "r"(b1));
}

__device__ __forceinline__ void cp16(void* smem, const void* g) {
    uint32_t s = (uint32_t)__cvta_generic_to_shared(smem);
    asm volatile("cp.async.cg.shared.global [%0], [%1], 16;\n" :: "r"(s), "l"(g));
}
#define CP_COMMIT() asm volatile("cp.async.commit_group;\n" ::: "memory")
#define CP_WAIT1()  asm volatile("cp.async.wait_group 1;\n" ::: "memory")

// ---------------------------------------------------------------------------
// Fused prologue: embed+posenc (blocks 0..NTOK-1) and weight tf32-rounding.
// ---------------------------------------------------------------------------
#define RND_BLOCKS ((WR_TOTAL/4 + 511) / 512)

__global__ void prep_kernel(const float* __restrict__ src,
                            const float* __restrict__ Wemb,
                            const float* __restrict__ bemb,
                            const float* __restrict__ Wq, const float* __restrict__ Wk,
                            const float* __restrict__ Wv, const float* __restrict__ Wo,
                            const float* __restrict__ W1, const float* __restrict__ W2) {
    const int bx = blockIdx.x;
    if (bx < NTOK) {
        int row = bx;
        int l   = row & (L_-1);
        int d   = threadIdx.x;
        __shared__ float s[32];
        if (d < 32) s[d] = src[row*32 + d];
        __syncthreads();
        float acc = bemb[d];
        #pragma unroll
        for (int k = 0; k < 32; k++) acc += s[k] * Wemb[k*DM + d];
        int i2 = d & ~1;
        float div = expf(-(float)i2 * (9.210340371976184f / 512.0f));
        float ang = (float)l * div;
        acc += (d & 1) ? cosf(ang) : sinf(ang);
        g_x[row*DM + d] = to_tf32(acc);
    } else {
        const int QS = 2*DM*DM;
        int i4 = (bx - NTOK) * 512 + threadIdx.x;
        int f  = i4 * 4;
        if (f >= WR_TOTAL) return;
        const float* sp;
        int off;
        if      (f < QS)      { sp = Wq; off = f; }
        else if (f < 2*QS)    { sp = Wk; off = f - QS; }
        else if (f < 3*QS)    { sp = Wv; off = f - 2*QS; }
        else if (f < 4*QS)    { sp = Wo; off = f - 3*QS; }
        else if (f < 4*QS + 2*DM*DFF) { sp = W1; off = f - 4*QS; }
        else                  { sp = W2; off = f - 4*QS - 2*DM*DFF; }
        float4 v = *(const float4*)&sp[off];
        v.x = to_tf32(v.x); v.y = to_tf32(v.y); v.z = to_tf32(v.z); v.w = to_tf32(v.w);
        *(float4*)&g_wr[f] = v;
    }
}

// ---------------------------------------------------------------------------
// tf32 GEMM, cp.async 3-stage pipeline. Block tile 128x128x16, 256 threads.
// ---------------------------------------------------------------------------
#define AS(s,m,k) As[(s)*2560 + (m)*20 + (k)]
#define BS(s,k,n) Bs[(s)*2176 + (k)*136 + (n)]
#define GEMM_SMEM ((GS*2560 + GS*2176) * 4)

__device__ __forceinline__ void issue_tile(
        float* As, float* Bs, const float* A, const float* W,
        int lda, int N, int m0, int n0, int k0, int s, int tid) {
    int f0 = tid, f1 = tid + 256;
    int ma0 = f0 >> 2, kc0 = (f0 & 3) << 2;
    int ma1 = f1 >> 2, kc1 = (f1 & 3) << 2;
    cp16(&AS(s,ma0,kc0), A + (size_t)(m0+ma0)*lda + k0 + kc0);
    cp16(&AS(s,ma1,kc1), A + (size_t)(m0+ma1)*lda + k0 + kc1);
    int kr0 = f0 >> 5, nc0 = (f0 & 31) << 2;
    int kr1 = f1 >> 5, nc1 = (f1 & 31) << 2;
    cp16(&BS(s,kr0,nc0), W + (size_t)(k0+kr0)*N + n0 + nc0);
    cp16(&BS(s,kr1,nc1), W + (size_t)(k0+kr1)*N + n0 + nc1);
}

template<bool GELU, bool RAW, bool RND>
__device__ __forceinline__ void gemm_body(
        const float* __restrict__ A, const float* __restrict__ W,
        const float* __restrict__ bias, const float* __restrict__ resid,
        float* __restrict__ C, __nv_bfloat16* __restrict__ Hout,
        int N, int K, int lda, int bx, int by) {
    extern __shared__ float gsm[];
    float* As = gsm;
    float* Bs = gsm + GS*2560;

    const int tid  = threadIdx.x;
    const int w    = tid >> 5;
    const int lane = tid & 31;
    const int grp  = lane >> 2;
    const int qd   = lane & 3;
    const int warp_m = (w & 3) * 32;
    const int warp_n = (w >> 2) * 64;
    const int m0 = by * 128;
    const int n0 = bx * 128;

    float acc[2][8][4];
    #pragma unroll
    for (int mi = 0; mi < 2; mi++)
        #pragma unroll
        for (int ni = 0; ni < 8; ni++)
            #pragma unroll
            for (int j = 0; j < 4; j++) acc[mi][ni][j] = 0.f;

    const int nt = K >> 4;

    issue_tile(As, Bs, A, W, lda, N, m0, n0, 0, 0, tid);  CP_COMMIT();
    issue_tile(As, Bs, A, W, lda, N, m0, n0, 16, 1, tid); CP_COMMIT();

    for (int t = 0; t < nt; t++) {
        CP_WAIT1();
        __syncthreads();
        const int s = t % GS;
        if (t + 2 < nt)
            issue_tile(As, Bs, A, W, lda, N, m0, n0, (t+2) << 4, (t+2) % GS, tid);
        CP_COMMIT();

        #pragma unroll
        for (int kk = 0; kk < 16; kk += 8) {
            uint32_t af[2][4];
            #pragma unroll
            for (int mi = 0; mi < 2; mi++) {
                int mb = warp_m + mi*16 + grp;
                af[mi][0] = __float_as_uint(AS(s, mb,   kk+qd));
                af[mi][1] = __float_as_uint(AS(s, mb+8, kk+qd));
                af[mi][2] = __float_as_uint(AS(s, mb,   kk+qd+4));
                af[mi][3] = __float_as_uint(AS(s, mb+8, kk+qd+4));
            }
            #pragma unroll
            for (int ni = 0; ni < 8; ni++) {
                int nb = warp_n + ni*8 + grp;
                uint32_t b0 = __float_as_uint(BS(s, kk+qd,   nb));
                uint32_t b1 = __float_as_uint(BS(s, kk+qd+4, nb));
                mma_tf32(acc[0][ni], af[0], b0, b1);
                mma_tf32(acc[1][ni], af[1], b0, b1);
            }
        }
    }

    #pragma unroll
    for (int mi = 0; mi < 2; mi++) {
        int r0 = m0 + warp_m + mi*16 + grp;
        #pragma unroll
        for (int ni = 0; ni < 8; ni++) {
            int c = n0 + warp_n + ni*8 + qd*2;
            float v0 = acc[mi][ni][0];
            float v1 = acc[mi][ni][1];
            float v2 = acc[mi][ni][2];
            float v3 = acc[mi][ni][3];
            if (!RAW) {
                float b0 = bias[c], b1 = bias[c+1];
                v0 += b0; v1 += b1; v2 += b0; v3 += b1;
                if (resid) {
                    v0 += resid[(size_t)r0*N + c];     v1 += resid[(size_t)r0*N + c + 1];
                    v2 += resid[(size_t)(r0+8)*N + c]; v3 += resid[(size_t)(r0+8)*N + c + 1];
                }
                if (GELU) {
                    v0 = 0.5f*v0*(1.0f + erff(v0*0.70710678118654752f));
                    v1 = 0.5f*v1*(1.0f + erff(v1*0.70710678118654752f));
                    v2 = 0.5f*v2*(1.0f + erff(v2*0.70710678118654752f));
                    v3 = 0.5f*v3*(1.0f + erff(v3*0.70710678118654752f));
                }
            }
            if (RND) {
                v0 = to_tf32(v0); v1 = to_tf32(v1);
                v2 = to_tf32(v2); v3 = to_tf32(v3);
            }
            *(float2*)&C[(size_t)r0*N + c]     = make_float2(v0, v1);
            *(float2*)&C[(size_t)(r0+8)*N + c] = make_float2(v2, v3);
            if (Hout) {
                *(__nv_bfloat162*)&Hout[(size_t)r0*N + c] =
                    __floats2bfloat162_rn(v0, v1);
                *(__nv_bfloat162*)&Hout[(size_t)(r0+8)*N + c] =
                    __floats2bfloat162_rn(v2, v3);
            }
        }
    }
}

template<bool GELU, bool RND>
__global__ void __launch_bounds__(256, 2)
gemm_tc(const float* __restrict__ A, const float* __restrict__ W,
        const float* __restrict__ bias, const float* __restrict__ resid,
        float* __restrict__ C, int N, int K) {
    gemm_body<GELU, false, RND>(A, W, bias, resid, C, nullptr, N, K, K,
                                blockIdx.x, blockIdx.y);
}

// Fused QKV: blockIdx.z selects projection; Q,K also dual-stored as bf16.
__global__ void __launch_bounds__(256, 2)
qkv_tc(const float* __restrict__ A, int layer,
       const float* __restrict__ bq, const float* __restrict__ bk,
       const float* __restrict__ bv,
       float* __restrict__ Q, float* __restrict__ Ko, float* __restrict__ V) {
    const float* W; const float* bias; float* C; __nv_bfloat16* H;
    const int QS = 2*DM*DM;
    size_t loff = (size_t)layer*DM*DM;
    if (blockIdx.z == 0)      { W = g_wr + loff;        bias = bq; C = Q;  H = g_qh; }
    else if (blockIdx.z == 1) { W = g_wr + QS + loff;   bias = bk; C = Ko; H = g_kh; }
    else                      { W = g_wr + 2*QS + loff; bias = bv; C = V;  H = nullptr; }
    gemm_body<false, false, false>(A, W, bias, nullptr, C, H, DM, DM, DM,
                                   blockIdx.x, blockIdx.y);
}

// Generic split-K partial GEMM: blockIdx.z = k-chunk of size KC.
template<int KC>
__global__ void __launch_bounds__(256, 2)
splitk_tc(const float* __restrict__ A, const float* __restrict__ W,
          int lda) {
    const int kc = blockIdx.z;
    gemm_body<false, true, false>(A + kc*KC, W + (size_t)kc*KC*DM,
                                  nullptr, nullptr,
                                  g_split + (size_t)kc*NTOK*DM,
                                  nullptr, DM, KC, lda, blockIdx.x, blockIdx.y);
}

// Fused split-K reduce + bias + residual + LayerNorm (output rounded).
template<int NS>
__global__ void reduce_ln_kernel(const float* __restrict__ bias,
                                 const float* __restrict__ resid,
                                 const float* __restrict__ g,
                                 const float* __restrict__ be,
                                 float* __restrict__ out) {
    int row = blockIdx.x;
    int t   = threadIdx.x;
    size_t o0 = (size_t)row*DM + t;
    size_t o1 = o0 + 256;
    float v0 = resid[o0] + bias[t];
    float v1 = resid[o1] + bias[t+256];
    #pragma unroll
    for (int s = 0; s < NS; s++) {
        v0 += g_split[(size_t)s*NTOK*DM + o0];
        v1 += g_split[(size_t)s*NTOK*DM + o1];
    }
    __shared__ float red[256];
    red[t] = v0 + v1; __syncthreads();
    for (int s = 128; s > 0; s >>= 1) { if (t < s) red[t] += red[t+s]; __syncthreads(); }
    float mean = red[0] * (1.0f/DM);
    __syncthreads();
    float d0 = v0 - mean, d1 = v1 - mean;
    red[t] = d0*d0 + d1*d1; __syncthreads();
    for (int s = 128; s > 0; s >>= 1) { if (t < s) red[t] += red[t+s]; __syncthreads(); }
    float rstd = rsqrtf(red[0] * (1.0f/DM) + 1e-5f);
    out[o0] = to_tf32(d0*rstd*g[t]     + be[t]);
    out[o1] = to_tf32(d1*rstd*g[t+256] + be[t+256]);
}

// ---------------------------------------------------------------------------
// Sampled sparsity measure M (unchanged)
// ---------------------------------------------------------------------------
__global__ void sampleM_kernel(const int* __restrict__ idxs) {
    int wg   = (blockIdx.x * blockDim.x + threadIdx.x) >> 5;
    int lane = threadIdx.x & 31;
    if (wg >= NBH*L_) return;
    int i = wg & (L_-1);
    int h = (wg >> 10) & (NH-1);
    int b = wg >> 13;
    const int half = lane >> 4;
    const int sub  = lane & 15;

    const float2* Qr8 = (const float2*)&g_qh[(size_t)(b*L_ + i)*DM + h*HD];
    float2 qraw = Qr8[sub];
    uint32_t qlo = __float_as_uint(qraw.x), qhi = __float_as_uint(qraw.y);
    float2 q0 = __bfloat1622float2(*(__nv_bfloat162*)&qlo);
    float2 q1 = __bfloat1622float2(*(__nv_bfloat162*)&qhi);

    int idxA = idxs[i*SK + (lane < SK ? lane : 0)];
    int idxB = idxs[i*SK + ((32 + lane) < SK ? 32 + lane : 0)];

    float mx = -FLT_MAX, sm = 0.f;
    #pragma unroll 2
    for (int jj = 0; jj < 18; jj++) {
        int j = 2*jj + half;
        int srcA = __shfl_sync(0xffffffffu, idxA, j & 31);
        int srcB = __shfl_sync(0xffffffffu, idxB, (j - 32) & 31);
        int src  = (j < 32) ? srcA : srcB;
        bool valid = (j < SK);
        float p = 0.f;
        if (valid) {
            const float2* Kr8 = (const float2*)&g_kh[(size_t)(b*L_ + src)*DM + h*HD];
            float2 kraw = Kr8[sub];
            uint32_t klo = __float_as_uint(kraw.x), khi = __float_as_uint(kraw.y);
            float2 k0 = __bfloat1622float2(*(__nv_bfloat162*)&klo);
            float2 k1 = __bfloat1622float2(*(__nv_bfloat162*)&khi);
            p = q0.x*k0.x + q0.y*k0.y + q1.x*k1.x + q1.y*k1.y;
        }
        p += __shfl_xor_sync(0xffffffffu, p, 8);
        p += __shfl_xor_sync(0xffffffffu, p, 4);
        p += __shfl_xor_sync(0xffffffffu, p, 2);
        p += __shfl_xor_sync(0xffffffffu, p, 1);
        if (valid) { mx = fmaxf(mx, p); sm += p; }
    }
    float mxo = __shfl_xor_sync(0xffffffffu, mx, 16);
    float smo = __shfl_xor_sync(0xffffffffu, sm, 16);
    mx = fmaxf(mx, mxo);
    sm += smo;
    if (lane == 0) g_M[(b*NH+h)*L_ + i] = mx - sm * (1.0f/SK);
}

// ---------------------------------------------------------------------------
// vmean partials: grid (NBH, 8), 512 threads. Each block handles 128 V rows.
// ---------------------------------------------------------------------------
__global__ void __launch_bounds__(512)
vmean_part() {
    const int bh = blockIdx.x;
    const int r  = blockIdx.y;
    const int b  = bh >> 3;
    const int h  = bh & 7;
    const int t  = threadIdx.x;
    const int e  = t & 63, rr = t >> 6;    // rr 0..7 -> 16 rows each
    float acc = 0.f;
    int base = r*128 + rr*16;
    for (int l = base; l < base + 16; l++)
        acc += g_v[(size_t)((b<<10) + l)*DM + h*HD + e];
    __shared__ float red[512];
    red[t] = acc;
    __syncthreads();
    if (t < 64) {
        float s = 0.f;
        #pragma unroll
        for (int i = 0; i < 8; i++) s += red[t + i*64];
        g_vmp[(bh*8 + r)*64 + t] = s;
    }
}

// ---------------------------------------------------------------------------
// ctx broadcast fill: grid (NBH, 8), 512 threads. Finalize vmean + fill 128 rows.
// ---------------------------------------------------------------------------
__global__ void __launch_bounds__(512)
fill_kernel() {
    __shared__ __align__(16) float vm[64];
    const int bh = blockIdx.x;
    const int r  = blockIdx.y;
    const int b  = bh >> 3;
    const int h  = bh & 7;
    const int t  = threadIdx.x;
    if (t < 64) {
        float s = 0.f;
        #pragma unroll
        for (int i = 0; i < 8; i++) s += g_vmp[(bh*8 + i)*64 + t];
        vm[t] = to_tf32(s * (1.0f/L_));
    }
    __syncthreads();
    const float4* vm4 = (const float4*)vm;
    #pragma unroll
    for (int i = 0; i < 4; i++) {
        int f = t + i*512;                 // 2048 float4s = 128 rows * 16
        int l = r*128 + (f >> 4), ev = f & 15;
        *(float4*)&g_ctx[(size_t)((b<<10) + l)*DM + h*HD + ev*4] = vm4[ev];
    }
}

// ---------------------------------------------------------------------------
// Attention prep: top-k (radix select) + Qsel gather. Grid NBH, 512 threads.
// ---------------------------------------------------------------------------
__device__ __forceinline__ uint32_t f2ord(float f) {
    uint32_t u = __float_as_uint(f);
    return (u & 0x80000000u) ? ~u : (u | 0x80000000u);
}

__global__ void __launch_bounds__(512)
attn_prep2() {
    __shared__ int ties[1024];
    __shared__ int s_cntA[32];
    __shared__ int s_gt, s_tn;
    __shared__ int tops[48];

    const int bh = blockIdx.x;
    const int b  = bh >> 3;
    const int h  = bh & 7;
    const int t  = threadIdx.x;
    const int lane = t & 31;

    uint32_t u0 = f2ord(g_M[bh*L_ + t]);
    uint32_t u1 = f2ord(g_M[bh*L_ + t + 512]);
    if (t < 32) s_cntA[t] = 0;
    if (t == 0) { s_gt = 0; s_tn = 0; }
    __syncthreads();
    uint32_t prefix = 0;
    int need = SK;
    for (int bit = 31; bit >= 0; --bit) {
        uint32_t cd = (prefix >> bit) | 1u;
        int c = ((u0 >> bit) == cd) + ((u1 >> bit) == cd);
        int ws = __reduce_add_sync(0xffffffffu, c);
        if (lane == 0 && ws) atomicAdd(&s_cntA[bit], ws);
        __syncthreads();
        int cnt = s_cntA[bit];
        if (cnt >= need) prefix |= (1u << bit);
        else             need -= cnt;
    }
    if (u0 > prefix) tops[atomicAdd(&s_gt, 1)] = t;
    else if (u0 == prefix) ties[atomicAdd(&s_tn, 1)] = t;
    if (u1 > prefix) tops[atomicAdd(&s_gt, 1)] = t + 512;
    else if (u1 == prefix) ties[atomicAdd(&s_tn, 1)] = t + 512;
    __syncthreads();
    if (t == 0) {
        int base = s_gt, tn = s_tn;
        for (int sel = 0; sel < need; sel++) {
            int bi = -1, bvv = 0x7fffffff;
            for (int j = 0; j < tn; j++)
                if (ties[j] < bvv) { bvv = ties[j]; bi = j; }
            tops[base + sel] = bvv;
            ties[bi] = 0x7fffffff;
        }
    }
    __syncthreads();
    if (t < SK) g_top[bh*SK + t] = tops[t];

    for (int f = t; f < SK*HD; f += 512) {
        int u = f >> 6, k = f & 63;
        g_qsel[bh*SK*HD + f] = g_q[(size_t)((b<<10) + tops[u])*DM + h*HD + k];
    }
}

// ---------------------------------------------------------------------------
// Merged score+softmax-partial+ctx-partial, flash-style per-st max.
// Grid (8, NBH), 256 threads, dynamic smem.
// ---------------------------------------------------------------------------
#define AF_SMEM_FLOATS (64*129 + SK*64 + SK*128)

__global__ void __launch_bounds__(256)
attn_fused2() {
    extern __shared__ float csm[];
    float* kt = csm;                   // 64*129 (K tile, later V tile)
    float* sq = kt + 64*129;           // SK*64
    float* ps = sq + SK*64;            // SK*128 (exp probs)

    const int st = blockIdx.x;
    const int bh = blockIdx.y;
    const int b  = bh >> 3;
    const int h  = bh & 7;
    const int t  = threadIdx.x;
    const int lane = t & 31;
    const int w  = t >> 5;             // 0..7

    // stage K tile transposed
    #pragma unroll
    for (int i = 0; i < 8; i++) {
        int f = t + i*256;
        int s = f >> 4, ec = (f & 15) << 2;
        float4 kv = *(const float4*)&g_k[(size_t)((b<<10) + st*128 + s)*DM + h*HD + ec];
        kt[(ec+0)*129 + s] = kv.x;
        kt[(ec+1)*129 + s] = kv.y;
        kt[(ec+2)*129 + s] = kv.z;
        kt[(ec+3)*129 + s] = kv.w;
    }
    for (int f = t; f < SK*HD; f += 256) sq[f] = g_qsel[bh*SK*HD + f];
    __syncthreads();

    float acc[5][4];
    #pragma unroll
    for (int jj = 0; jj < 5; jj++)
        #pragma unroll
        for (int r = 0; r < 4; r++) acc[jj][r] = 0.f;

    for (int k = 0; k < 64; k++) {
        float kv0 = kt[k*129 + lane];
        float kv1 = kt[k*129 + lane + 32];
        float kv2 = kt[k*129 + lane + 64];
        float kv3 = kt[k*129 + lane + 96];
        #pragma unroll
        for (int jj = 0; jj < 5; jj++) {
            int u = w + 8*jj;
            if (u < SK) {
                float qv = sq[u*HD + k];
                acc[jj][0] += qv*kv0; acc[jj][1] += qv*kv1;
                acc[jj][2] += qv*kv2; acc[jj][3] += qv*kv3;
            }
        }
    }

    // per-(u,st): local max, exp, partial sum; exps to ps
    #pragma unroll
    for (int jj = 0; jj < 5; jj++) {
        int u = w + 8*jj;
        if (u < SK) {
            float s0 = acc[jj][0]*0.125f, s1 = acc[jj][1]*0.125f;
            float s2 = acc[jj][2]*0.125f, s3 = acc[jj][3]*0.125f;
            float m = fmaxf(fmaxf(s0, s1), fmaxf(s2, s3));
            #pragma unroll
            for (int o = 16; o > 0; o >>= 1) m = fmaxf(m, __shfl_xor_sync(0xffffffffu, m, o));
            float e0 = expf(s0 - m), e1 = expf(s1 - m);
            float e2 = expf(s2 - m), e3 = expf(s3 - m);
            ps[u*128 + lane]      = e0;
            ps[u*128 + lane + 32] = e1;
            ps[u*128 + lane + 64] = e2;
            ps[u*128 + lane + 96] = e3;
            float ss = e0 + e1 + e2 + e3;
            #pragma unroll
            for (int o = 16; o > 0; o >>= 1) ss += __shfl_xor_sync(0xffffffffu, ss, o);
            if (lane == 0) {
                g_pmax[(bh*SK + u)*8 + st] = m;
                g_psum[(bh*8 + st)*SK + u] = ss;
            }
        }
    }
    __syncthreads();

    // stage V tile transposed (overwrite kt)
    #pragma unroll
    for (int i = 0; i < 8; i++) {
        int f = t + i*256;
        int s = f >> 4, ec = (f & 15) << 2;
        float4 vv = *(const float4*)&g_v[(size_t)((b<<10) + st*128 + s)*DM + h*HD + ec];
        kt[(ec+0)*129 + s] = vv.x;
        kt[(ec+1)*129 + s] = vv.y;
        kt[(ec+2)*129 + s] = vv.z;
        kt[(ec+3)*129 + s] = vv.w;
    }
    __syncthreads();

    // partial context
    const int e  = t & 63;
    const int ug = t >> 6;             // 0..3
    float cacc[9];
    #pragma unroll
    for (int jj = 0; jj < 9; jj++) cacc[jj] = 0.f;
    for (int s = 0; s < 128; s++) {
        float v = kt[e*129 + s];
        #pragma unroll
        for (int jj = 0; jj < 9; jj++) {
            int u = ug + 4*jj;
            if (u < SK) cacc[jj] += ps[u*128 + s] * v;
        }
    }
    #pragma unroll
    for (int jj = 0; jj < 9; jj++) {
        int u = ug + 4*jj;
        if (u < SK) g_cpart[((size_t)(bh*8 + st)*SK + u)*HD + e] = cacc[jj];
    }
}

// ---------------------------------------------------------------------------
// Scatter with flash-style recombination. Grid NBH, 512 threads.
// ---------------------------------------------------------------------------
__global__ void __launch_bounds__(512)
attn_scatter() {
    __shared__ float coef[48][8];
    __shared__ float zinv[48];
    __shared__ int   tops[48];
    const int bh = blockIdx.x;
    const int b  = bh >> 3;
    const int h  = bh & 7;
    const int t  = threadIdx.x;

    if (t < SK) {
        float mm[8];
        float M = -FLT_MAX;
        #pragma unroll
        for (int st = 0; st < 8; st++) {
            mm[st] = g_pmax[(bh*SK + t)*8 + st];
            M = fmaxf(M, mm[st]);
        }
        float z = 0.f;
        #pragma unroll
        for (int st = 0; st < 8; st++) {
            float c = expf(mm[st] - M);
            coef[t][st] = c;
            z += c * g_psum[(bh*8 + st)*SK + t];
        }
        zinv[t] = 1.0f / z;
        tops[t] = g_top[bh*SK + t];
    }
    __syncthreads();

    const int e  = t & 63;
    const int ug = t >> 6;             // 0..7
    #pragma unroll
    for (int jj = 0; jj < 5; jj++) {
        int u = ug + 8*jj;
        if (u < SK) {
            float c = 0.f;
            #pragma unroll
            for (int st = 0; st < 8; st++)
                c += coef[u][st] * g_cpart[((size_t)(bh*8 + st)*SK + u)*HD + e];
            g_ctx[(size_t)((b<<10) + tops[u])*DM + h*HD + e] = to_tf32(c * zinv[u]);
        }
    }
}

// ---------------------------------------------------------------------------
// LayerNorm (row of 512, 256 threads). RND: round output to tf32.
// ---------------------------------------------------------------------------
template<bool RND>
__global__ void ln_kernel(const float* __restrict__ in, float* __restrict__ out,
                          const float* __restrict__ g, const float* __restrict__ be) {
    int row = blockIdx.x;
    int t   = threadIdx.x;
    float v0 = in[(size_t)row*DM + t];
    float v1 = in[(size_t)row*DM + t + 256];
    __shared__ float red[256];
    red[t] = v0 + v1; __syncthreads();
    for (int s = 128; s > 0; s >>= 1) { if (t < s) red[t] += red[t+s]; __syncthreads(); }
    float mean = red[0] * (1.0f/DM);
    __syncthreads();
    float d0 = v0 - mean, d1 = v1 - mean;
    red[t] = d0*d0 + d1*d1; __syncthreads();
    for (int s = 128; s > 0; s >>= 1) { if (t < s) red[t] += red[t+s]; __syncthreads(); }
    float rstd = rsqrtf(red[0] * (1.0f/DM) + 1e-5f);
    float o0 = d0*rstd*g[t]     + be[t];
    float o1 = d1*rstd*g[t+256] + be[t+256];
    if (RND) { o0 = to_tf32(o0); o1 = to_tf32(o1); }
    out[(size_t)row*DM + t]       = o0;
    out[(size_t)row*DM + t + 256] = o1;
}

// ---------------------------------------------------------------------------
// Mean pool stage 1; fused pool stage 2 + classifier (warp per (b,c))
// ---------------------------------------------------------------------------
__global__ void pool1_kernel() {
    int b = blockIdx.x, r = blockIdx.y;
    int d = threadIdx.x;
    float acc = 0.f;
    for (int l = r*128; l < r*128 + 128; l++)
        acc += g_tmp[(size_t)(b*L_+l)*DM + d];
    g_poolp[(b*8 + r)*DM + d] = acc;
}

__global__ void poolcls_kernel(const float* __restrict__ Wc,
                               const float* __restrict__ bc,
                               float* __restrict__ out) {
    __shared__ float pooled[B_*DM];
    int t = threadIdx.x;          // 512
    int lane = t & 31, w = t >> 5;
    #pragma unroll
    for (int i = 0; i < 4; i++) {
        int f = t + i*512;
        int b = f >> 9, d = f & 511;
        float acc = 0.f;
        #pragma unroll
        for (int r = 0; r < 8; r++) acc += g_poolp[(b*8 + r)*DM + d];
        pooled[f] = acc * (1.0f/L_);
    }
    __syncthreads();
    for (int bcp = w; bcp < B_*10; bcp += 16) {
        int b = bcp / 10, c = bcp % 10;
        float acc = 0.f;
        for (int d = lane; d < DM; d += 32)
            acc += pooled[b*DM + d] * Wc[d*10 + c];
        #pragma unroll
        for (int o = 16; o > 0; o >>= 1) acc += __shfl_xor_sync(0xffffffffu, acc, o);
        if (lane == 0) out[bcp] = acc + bc[c];
    }
}

// ---------------------------------------------------------------------------
extern "C" void kernel_launch(void* const* d_in, const int* in_sizes, int n_in,
                              void* d_out, int out_size) {
    const float* src   = (const float*)d_in[0];
    const int*   idxs  = (const int*)  d_in[1];
    const float* Wemb  = (const float*)d_in[2];
    const float* bemb  = (const float*)d_in[3];
    const float* Wq    = (const float*)d_in[4];
    const float* bq    = (const float*)d_in[5];
    const float* Wk    = (const float*)d_in[6];
    const float* bk    = (const float*)d_in[7];
    const float* Wv    = (const float*)d_in[8];
    const float* bv    = (const float*)d_in[9];
    const float* Wo    = (const float*)d_in[10];
    const float* bo    = (const float*)d_in[11];
    const float* g1    = (const float*)d_in[12];
    const float* beta1 = (const float*)d_in[13];
    const float* W1    = (const float*)d_in[14];
    const float* bf1   = (const float*)d_in[15];
    const float* W2    = (const float*)d_in[16];
    const float* bf2   = (const float*)d_in[17];
    const float* g2    = (const float*)d_in[18];
    const float* beta2 = (const float*)d_in[19];
    const float* gf    = (const float*)d_in[20];
    const float* betaf = (const float*)d_in[21];
    const float* Wc    = (const float*)d_in[22];
    const float* bc    = (const float*)d_in[23];

    void *px_, *ptmp_, *pq_, *pk_, *pv_, *pctx_, *pff_, *pwr_;
    cudaGetSymbolAddress(&px_,   g_x);
    cudaGetSymbolAddress(&ptmp_, g_tmp);
    cudaGetSymbolAddress(&pq_,   g_q);
    cudaGetSymbolAddress(&pk_,   g_k);
    cudaGetSymbolAddress(&pv_,   g_v);
    cudaGetSymbolAddress(&pctx_, g_ctx);
    cudaGetSymbolAddress(&pff_,  g_ff);
    cudaGetSymbolAddress(&pwr_,  g_wr);
    float* px   = (float*)px_;
    float* ptmp = (float*)ptmp_;
    float* pq   = (float*)pq_;
    float* pk   = (float*)pk_;
    float* pv   = (float*)pv_;
    float* pctx = (float*)pctx_;
    float* pff  = (float*)pff_;
    float* pwr  = (float*)pwr_;

    const int af_smem = AF_SMEM_FLOATS * 4;
    static int configured = 0;
    if (!configured) {
        configured = 1;
        cudaFuncSetAttribute(attn_fused2, cudaFuncAttributeMaxDynamicSharedMemorySize, af_smem);
        cudaFuncSetAttribute((const void*)qkv_tc, cudaFuncAttributeMaxDynamicSharedMemorySize, GEMM_SMEM);
        cudaFuncSetAttribute((const void*)gemm_tc<false,false>, cudaFuncAttributeMaxDynamicSharedMemorySize, GEMM_SMEM);
        cudaFuncSetAttribute((const void*)gemm_tc<true,true>,   cudaFuncAttributeMaxDynamicSharedMemorySize, GEMM_SMEM);
        cudaFuncSetAttribute((const void*)splitk_tc<256>, cudaFuncAttributeMaxDynamicSharedMemorySize, GEMM_SMEM);
        cudaFuncSetAttribute((const void*)splitk_tc<512>, cudaFuncAttributeMaxDynamicSharedMemorySize, GEMM_SMEM);
    }

    const int QS = 2*DM*DM;
    prep_kernel<<<NTOK + RND_BLOCKS, 512>>>(src, Wemb, bemb, Wq, Wk, Wv, Wo, W1, W2);

    for (int l = 0; l < 2; l++) {
        const float* W1_l = pwr + 4*QS + (size_t)l*DM*DFF;
        const float* W2_l = pwr + 4*QS + 2*DM*DFF + (size_t)l*DFF*DM;
        const float* Wo_l = pwr + 3*QS + (size_t)l*DM*DM;

        dim3 gQKV(DM/128, NTOK/128, 3);      // (4, 32, 3)
        dim3 gFF(DFF/128, NTOK/128);         // (16, 32)
        dim3 gWO(DM/128, NTOK/128, 2);       // (4, 32, 2) split-K2
        dim3 gSP(DM/128, NTOK/128, SPLITK);  // (4, 32, 4) split-K4
        dim3 gATT(8, NBH);                   // (8, 32) = 256 blocks
        dim3 gVM(NBH, 8);                    // 256 blocks

        qkv_tc<<<gQKV, 256, GEMM_SMEM>>>(px, l, bq + l*DM, bk + l*DM, bv + l*DM,
                                         pq, pk, pv);

        vmean_part<<<gVM, 512>>>();
        fill_kernel<<<gVM, 512>>>();
        sampleM_kernel<<<(NBH*L_)/4, 128>>>(idxs + (size_t)l*L_*SK);
        attn_prep2<<<NBH, 512>>>();
        attn_fused2<<<gATT, 256, af_smem>>>();
        attn_scatter<<<NBH, 512>>>();

        splitk_tc<256><<<gWO, 256, GEMM_SMEM>>>(pctx, Wo_l, DM);
        reduce_ln_kernel<2><<<NTOK, 256>>>(bo + l*DM, px, g1 + l*DM, beta1 + l*DM, px);

        gemm_tc<true,true><<<gFF, 256, GEMM_SMEM>>>(px, W1_l, bf1 + l*DFF, nullptr, pff, DFF, DM);
        splitk_tc<512><<<gSP, 256, GEMM_SMEM>>>(pff, W2_l, DFF);
        reduce_ln_kernel<4><<<NTOK, 256>>>(bf2 + l*DM, px, g2 + l*DM, beta2 + l*DM, px);
    }

    ln_kernel<false><<<NTOK, 256>>>(px, ptmp, gf, betaf);
    pool1_kernel<<<dim3(B_, 8), 512>>>();
    poolcls_kernel<<<1, 512>>>(Wc, bc, (float*)d_out);
}

// round 12
// speedup vs baseline: 1.7477x; 1.0842x over previous
#include <cuda_runtime.h>
#include <cuda_bf16.h>
#include <math.h>
#include <float.h>
#include <stdint.h>

// ---------------------------------------------------------------------------
// Informer: B=4, L=1024, DM=512, NH=8, HD=64, DFF=2048, SK=35, 2 layers
// ---------------------------------------------------------------------------
#define B_   4
#define L_   1024
#define DM   512
#define NH   8
#define HD   64
#define DFF  2048
#define SK   35
#define NTOK (B_*L_)   // 4096
#define SPLITK 4
#define GS 3           // cp.async pipeline stages
#define NBH  (B_*NH)   // 32

__device__ float g_x   [NTOK*DM];
__device__ float g_tmp [NTOK*DM];
__device__ float g_q   [NTOK*DM];
__device__ float g_k   [NTOK*DM];
__device__ float g_v   [NTOK*DM];
__device__ float g_ctx [NTOK*DM];
__device__ float g_ff  [NTOK*DFF];
__device__ float g_split[SPLITK*NTOK*DM];
__device__ float g_M   [NBH*L_];
__device__ float g_poolp[B_*8*DM];
__device__ __nv_bfloat16 g_qh[NTOK*DM];   // bf16 copies for sampling
__device__ __nv_bfloat16 g_kh[NTOK*DM];
// attention intermediates
__device__ int   g_top  [NBH*SK];
__device__ float g_qsel [NBH*SK*HD];
__device__ float g_vmp  [NBH*8*64];       // vmean partials
__device__ float g_pmax [NBH*SK*8];
__device__ float g_psum [NBH*8*SK];
__device__ float g_cpart[(size_t)NBH*8*SK*HD];
// pre-rounded (tf32-rna) weights: Wq|Wk|Wv|Wo (both layers each) then W1, W2
#define WR_TOTAL (4*2*DM*DM + 2*DM*DFF + 2*DFF*DM)
__device__ float g_wr[WR_TOTAL];

// ---------------------------------------------------------------------------
__device__ __forceinline__ float to_tf32(float x) {
    uint32_t u;
    asm("cvt.rna.tf32.f32 %0, %1;" : "=r"(u) : "f"(x));
    return __uint_as_float(u);
}

__device__ __forceinline__ void mma_tf32(float* c, const uint32_t* a,
                                         uint32_t b0, uint32_t b1) {
    asm volatile(
        "mma.sync.aligned.m16n8k8.row.col.f32.tf32.tf32.f32 "
        "{%0,%1,%2,%3},{%4,%5,%6,%7},{%8,%9},{%0,%1,%2,%3};"
        : "+f"(c[0]), "+f"(c[1]), "+f"(c[2]), "+f"(c[3])
        : "r"(a[0]), "r"(a[1]), "r"(a[2]), "r"(a[3]), "r"(b0), "r"(b1));
}

__device__ __forceinline__ void cp16(void* smem, const void* g) {
    uint32_t s = (uint32_t)__cvta_generic_to_shared(smem);
    asm volatile("cp.async.cg.shared.global [%0], [%1], 16;\n" :: "r"(s), "l"(g));
}
#define CP_COMMIT() asm volatile("cp.async.commit_group;\n" ::: "memory")
#define CP_WAIT1()  asm volatile("cp.async.wait_group 1;\n" ::: "memory")

// ---------------------------------------------------------------------------
// Fused prologue: embed+posenc (blocks 0..NTOK-1) and weight tf32-rounding.
// ---------------------------------------------------------------------------
#define RND_BLOCKS ((WR_TOTAL/4 + 511) / 512)

__global__ void prep_kernel(const float* __restrict__ src,
                            const float* __restrict__ Wemb,
                            const float* __restrict__ bemb,
                            const float* __restrict__ Wq, const float* __restrict__ Wk,
                            const float* __restrict__ Wv, const float* __restrict__ Wo,
                            const float* __restrict__ W1, const float* __restrict__ W2) {
    const int bx = blockIdx.x;
    if (bx < NTOK) {
        int row = bx;
        int l   = row & (L_-1);
        int d   = threadIdx.x;
        __shared__ float s[32];
        if (d < 32) s[d] = src[row*32 + d];
        __syncthreads();
        float acc = bemb[d];
        #pragma unroll
        for (int k = 0; k < 32; k++) acc += s[k] * Wemb[k*DM + d];
        int i2 = d & ~1;
        float div = expf(-(float)i2 * (9.210340371976184f / 512.0f));
        float ang = (float)l * div;
        acc += (d & 1) ? cosf(ang) : sinf(ang);
        g_x[row*DM + d] = to_tf32(acc);
    } else {
        const int QS = 2*DM*DM;
        int i4 = (bx - NTOK) * 512 + threadIdx.x;
        int f  = i4 * 4;
        if (f >= WR_TOTAL) return;
        const float* sp;
        int off;
        if      (f < QS)      { sp = Wq; off = f; }
        else if (f < 2*QS)    { sp = Wk; off = f - QS; }
        else if (f < 3*QS)    { sp = Wv; off = f - 2*QS; }
        else if (f < 4*QS)    { sp = Wo; off = f - 3*QS; }
        else if (f < 4*QS + 2*DM*DFF) { sp = W1; off = f - 4*QS; }
        else                  { sp = W2; off = f - 4*QS - 2*DM*DFF; }
        float4 v = *(const float4*)&sp[off];
        v.x = to_tf32(v.x); v.y = to_tf32(v.y); v.z = to_tf32(v.z); v.w = to_tf32(v.w);
        *(float4*)&g_wr[f] = v;
    }
}

// ---------------------------------------------------------------------------
// tf32 GEMM, cp.async 3-stage pipeline. Block tile 128x128x16, 128 threads
// (4 warps, 2m x 2n, warp tile 64x64 -> 1.0 LDS per MMA).
// ---------------------------------------------------------------------------
#define AS(s,m,k) As[(s)*2560 + (m)*20 + (k)]
#define BS(s,k,n) Bs[(s)*2176 + (k)*136 + (n)]
#define GEMM_SMEM ((GS*2560 + GS*2176) * 4)

__device__ __forceinline__ void issue_tile(
        float* As, float* Bs, const float* A, const float* W,
        int lda, int N, int m0, int n0, int k0, int s, int tid) {
    #pragma unroll
    for (int i = 0; i < 4; i++) {
        int f = tid + i*128;               // 0..511 float4 index
        int ma = f >> 2, kc = (f & 3) << 2;
        cp16(&AS(s,ma,kc), A + (size_t)(m0+ma)*lda + k0 + kc);
        int kr = f >> 5, nc = (f & 31) << 2;
        cp16(&BS(s,kr,nc), W + (size_t)(k0+kr)*N + n0 + nc);
    }
}

template<bool GELU, bool RAW, bool RND>
__device__ __forceinline__ void gemm_body(
        const float* __restrict__ A, const float* __restrict__ W,
        const float* __restrict__ bias, const float* __restrict__ resid,
        float* __restrict__ C, __nv_bfloat16* __restrict__ Hout,
        int N, int K, int lda, int bx, int by) {
    extern __shared__ float gsm[];
    float* As = gsm;
    float* Bs = gsm + GS*2560;

    const int tid  = threadIdx.x;          // 128
    const int w    = tid >> 5;             // 0..3
    const int lane = tid & 31;
    const int grp  = lane >> 2;
    const int qd   = lane & 3;
    const int warp_m = (w & 1) * 64;
    const int warp_n = (w >> 1) * 64;
    const int m0 = by * 128;
    const int n0 = bx * 128;

    float acc[4][8][4];
    #pragma unroll
    for (int mi = 0; mi < 4; mi++)
        #pragma unroll
        for (int ni = 0; ni < 8; ni++)
            #pragma unroll
            for (int j = 0; j < 4; j++) acc[mi][ni][j] = 0.f;

    const int nt = K >> 4;

    issue_tile(As, Bs, A, W, lda, N, m0, n0, 0, 0, tid);  CP_COMMIT();
    issue_tile(As, Bs, A, W, lda, N, m0, n0, 16, 1, tid); CP_COMMIT();

    for (int t = 0; t < nt; t++) {
        CP_WAIT1();
        __syncthreads();
        const int s = t % GS;
        if (t + 2 < nt)
            issue_tile(As, Bs, A, W, lda, N, m0, n0, (t+2) << 4, (t+2) % GS, tid);
        CP_COMMIT();

        #pragma unroll
        for (int kk = 0; kk < 16; kk += 8) {
            uint32_t af[4][4];
            #pragma unroll
            for (int mi = 0; mi < 4; mi++) {
                int mb = warp_m + mi*16 + grp;
                af[mi][0] = __float_as_uint(AS(s, mb,   kk+qd));
                af[mi][1] = __float_as_uint(AS(s, mb+8, kk+qd));
                af[mi][2] = __float_as_uint(AS(s, mb,   kk+qd+4));
                af[mi][3] = __float_as_uint(AS(s, mb+8, kk+qd+4));
            }
            #pragma unroll
            for (int ni = 0; ni < 8; ni++) {
                int nb = warp_n + ni*8 + grp;
                uint32_t b0 = __float_as_uint(BS(s, kk+qd,   nb));
                uint32_t b1 = __float_as_uint(BS(s, kk+qd+4, nb));
                #pragma unroll
                for (int mi = 0; mi < 4; mi++)
                    mma_tf32(acc[mi][ni], af[mi], b0, b1);
            }
        }
    }

    #pragma unroll
    for (int mi = 0; mi < 4; mi++) {
        int r0 = m0 + warp_m + mi*16 + grp;
        #pragma unroll
        for (int ni = 0; ni < 8; ni++) {
            int c = n0 + warp_n + ni*8 + qd*2;
            float v0 = acc[mi][ni][0];
            float v1 = acc[mi][ni][1];
            float v2 = acc[mi][ni][2];
            float v3 = acc[mi][ni][3];
            if (!RAW) {
                float b0 = bias[c], b1 = bias[c+1];
                v0 += b0; v1 += b1; v2 += b0; v3 += b1;
                if (resid) {
                    v0 += resid[(size_t)r0*N + c];     v1 += resid[(size_t)r0*N + c + 1];
                    v2 += resid[(size_t)(r0+8)*N + c]; v3 += resid[(size_t)(r0+8)*N + c + 1];
                }
                if (GELU) {
                    v0 = 0.5f*v0*(1.0f + erff(v0*0.70710678118654752f));
                    v1 = 0.5f*v1*(1.0f + erff(v1*0.70710678118654752f));
                    v2 = 0.5f*v2*(1.0f + erff(v2*0.70710678118654752f));
                    v3 = 0.5f*v3*(1.0f + erff(v3*0.70710678118654752f));
                }
            }
            if (RND) {
                v0 = to_tf32(v0); v1 = to_tf32(v1);
                v2 = to_tf32(v2); v3 = to_tf32(v3);
            }
            *(float2*)&C[(size_t)r0*N + c]     = make_float2(v0, v1);
            *(float2*)&C[(size_t)(r0+8)*N + c] = make_float2(v2, v3);
            if (Hout) {
                *(__nv_bfloat162*)&Hout[(size_t)r0*N + c] =
                    __floats2bfloat162_rn(v0, v1);
                *(__nv_bfloat162*)&Hout[(size_t)(r0+8)*N + c] =
                    __floats2bfloat162_rn(v2, v3);
            }
        }
    }
}

template<bool GELU, bool RND>
__global__ void __launch_bounds__(128, 2)
gemm_tc(const float* __restrict__ A, const float* __restrict__ W,
        const float* __restrict__ bias, const float* __restrict__ resid,
        float* __restrict__ C, int N, int K) {
    gemm_body<GELU, false, RND>(A, W, bias, resid, C, nullptr, N, K, K,
                                blockIdx.x, blockIdx.y);
}

// Fused QKV: blockIdx.z selects projection; Q,K also dual-stored as bf16.
__global__ void __launch_bounds__(128, 2)
qkv_tc(const float* __restrict__ A, int layer,
       const float* __restrict__ bq, const float* __restrict__ bk,
       const float* __restrict__ bv,
       float* __restrict__ Q, float* __restrict__ Ko, float* __restrict__ V) {
    const float* W; const float* bias; float* C; __nv_bfloat16* H;
    const int QS = 2*DM*DM;
    size_t loff = (size_t)layer*DM*DM;
    if (blockIdx.z == 0)      { W = g_wr + loff;        bias = bq; C = Q;  H = g_qh; }
    else if (blockIdx.z == 1) { W = g_wr + QS + loff;   bias = bk; C = Ko; H = g_kh; }
    else                      { W = g_wr + 2*QS + loff; bias = bv; C = V;  H = nullptr; }
    gemm_body<false, false, false>(A, W, bias, nullptr, C, H, DM, DM, DM,
                                   blockIdx.x, blockIdx.y);
}

// Generic split-K partial GEMM: blockIdx.z = k-chunk of size KC.
template<int KC>
__global__ void __launch_bounds__(128, 2)
splitk_tc(const float* __restrict__ A, const float* __restrict__ W,
          int lda) {
    const int kc = blockIdx.z;
    gemm_body<false, true, false>(A + kc*KC, W + (size_t)kc*KC*DM,
                                  nullptr, nullptr,
                                  g_split + (size_t)kc*NTOK*DM,
                                  nullptr, DM, KC, lda, blockIdx.x, blockIdx.y);
}

// Fused split-K reduce + bias + residual + LayerNorm (output rounded).
template<int NS>
__global__ void reduce_ln_kernel(const float* __restrict__ bias,
                                 const float* __restrict__ resid,
                                 const float* __restrict__ g,
                                 const float* __restrict__ be,
                                 float* __restrict__ out) {
    int row = blockIdx.x;
    int t   = threadIdx.x;
    size_t o0 = (size_t)row*DM + t;
    size_t o1 = o0 + 256;
    float v0 = resid[o0] + bias[t];
    float v1 = resid[o1] + bias[t+256];
    #pragma unroll
    for (int s = 0; s < NS; s++) {
        v0 += g_split[(size_t)s*NTOK*DM + o0];
        v1 += g_split[(size_t)s*NTOK*DM + o1];
    }
    __shared__ float red[256];
    red[t] = v0 + v1; __syncthreads();
    for (int s = 128; s > 0; s >>= 1) { if (t < s) red[t] += red[t+s]; __syncthreads(); }
    float mean = red[0] * (1.0f/DM);
    __syncthreads();
    float d0 = v0 - mean, d1 = v1 - mean;
    red[t] = d0*d0 + d1*d1; __syncthreads();
    for (int s = 128; s > 0; s >>= 1) { if (t < s) red[t] += red[t+s]; __syncthreads(); }
    float rstd = rsqrtf(red[0] * (1.0f/DM) + 1e-5f);
    out[o0] = to_tf32(d0*rstd*g[t]     + be[t]);
    out[o1] = to_tf32(d1*rstd*g[t+256] + be[t+256]);
}

// ---------------------------------------------------------------------------
// Sampled sparsity measure M. One warp per (b,h,i); four j's per iteration
// (8-lane groups, float4 = 8 bf16 per lane, 3-shuffle reduce).
// ---------------------------------------------------------------------------
__global__ void sampleM_kernel(const int* __restrict__ idxs) {
    int wg   = (blockIdx.x * blockDim.x + threadIdx.x) >> 5;
    int lane = threadIdx.x & 31;
    if (wg >= NBH*L_) return;
    int i = wg & (L_-1);
    int h = (wg >> 10) & (NH-1);
    int b = wg >> 13;
    const int grp = lane >> 3;        // j offset 0..3
    const int sub = lane & 7;         // k elems 8*sub..8*sub+7

    const float4* Qr16 = (const float4*)&g_qh[(size_t)(b*L_ + i)*DM + h*HD];
    float4 qraw = Qr16[sub];
    uint32_t qa = __float_as_uint(qraw.x), qb = __float_as_uint(qraw.y);
    uint32_t qc = __float_as_uint(qraw.z), qd2 = __float_as_uint(qraw.w);
    float2 q0 = __bfloat1622float2(*(__nv_bfloat162*)&qa);
    float2 q1 = __bfloat1622float2(*(__nv_bfloat162*)&qb);
    float2 q2 = __bfloat1622float2(*(__nv_bfloat162*)&qc);
    float2 q3 = __bfloat1622float2(*(__nv_bfloat162*)&qd2);

    int idxA = idxs[i*SK + (lane < SK ? lane : 0)];
    int idxB = idxs[i*SK + ((32 + lane) < SK ? 32 + lane : 0)];

    float mx = -FLT_MAX, sm = 0.f;
    #pragma unroll
    for (int jj = 0; jj < 9; jj++) {
        int j = 4*jj + grp;           // 0..35
        int srcA = __shfl_sync(0xffffffffu, idxA, j & 31);
        int srcB = __shfl_sync(0xffffffffu, idxB, (j - 32) & 31);
        int src  = (j < 32) ? srcA : srcB;
        bool valid = (j < SK);
        float p = 0.f;
        if (valid) {
            const float4* Kr16 = (const float4*)&g_kh[(size_t)(b*L_ + src)*DM + h*HD];
            float4 kraw = Kr16[sub];
            uint32_t ka = __float_as_uint(kraw.x), kb = __float_as_uint(kraw.y);
            uint32_t kc = __float_as_uint(kraw.z), kd = __float_as_uint(kraw.w);
            float2 k0 = __bfloat1622float2(*(__nv_bfloat162*)&ka);
            float2 k1 = __bfloat1622float2(*(__nv_bfloat162*)&kb);
            float2 k2 = __bfloat1622float2(*(__nv_bfloat162*)&kc);
            float2 k3 = __bfloat1622float2(*(__nv_bfloat162*)&kd);
            p = q0.x*k0.x + q0.y*k0.y + q1.x*k1.x + q1.y*k1.y
              + q2.x*k2.x + q2.y*k2.y + q3.x*k3.x + q3.y*k3.y;
        }
        p += __shfl_xor_sync(0xffffffffu, p, 4);
        p += __shfl_xor_sync(0xffffffffu, p, 2);
        p += __shfl_xor_sync(0xffffffffu, p, 1);
        if (valid) { mx = fmaxf(mx, p); sm += p; }
    }
    mx = fmaxf(mx, __shfl_xor_sync(0xffffffffu, mx, 8));
    sm += __shfl_xor_sync(0xffffffffu, sm, 8);
    mx = fmaxf(mx, __shfl_xor_sync(0xffffffffu, mx, 16));
    sm += __shfl_xor_sync(0xffffffffu, sm, 16);
    if (lane == 0) g_M[(b*NH+h)*L_ + i] = mx - sm * (1.0f/SK);
}

// ---------------------------------------------------------------------------
// vmean partials: grid (NBH, 8), 512 threads.
// ---------------------------------------------------------------------------
__global__ void __launch_bounds__(512)
vmean_part() {
    const int bh = blockIdx.x;
    const int r  = blockIdx.y;
    const int b  = bh >> 3;
    const int h  = bh & 7;
    const int t  = threadIdx.x;
    const int e  = t & 63, rr = t >> 6;
    float acc = 0.f;
    int base = r*128 + rr*16;
    for (int l = base; l < base + 16; l++)
        acc += g_v[(size_t)((b<<10) + l)*DM + h*HD + e];
    __shared__ float red[512];
    red[t] = acc;
    __syncthreads();
    if (t < 64) {
        float s = 0.f;
        #pragma unroll
        for (int i = 0; i < 8; i++) s += red[t + i*64];
        g_vmp[(bh*8 + r)*64 + t] = s;
    }
}

// ---------------------------------------------------------------------------
// ctx broadcast fill: grid (NBH, 8), 512 threads.
// ---------------------------------------------------------------------------
__global__ void __launch_bounds__(512)
fill_kernel() {
    __shared__ __align__(16) float vm[64];
    const int bh = blockIdx.x;
    const int r  = blockIdx.y;
    const int b  = bh >> 3;
    const int h  = bh & 7;
    const int t  = threadIdx.x;
    if (t < 64) {
        float s = 0.f;
        #pragma unroll
        for (int i = 0; i < 8; i++) s += g_vmp[(bh*8 + i)*64 + t];
        vm[t] = to_tf32(s * (1.0f/L_));
    }
    __syncthreads();
    const float4* vm4 = (const float4*)vm;
    #pragma unroll
    for (int i = 0; i < 4; i++) {
        int f = t + i*512;
        int l = r*128 + (f >> 4), ev = f & 15;
        *(float4*)&g_ctx[(size_t)((b<<10) + l)*DM + h*HD + ev*4] = vm4[ev];
    }
}

// ---------------------------------------------------------------------------
// Attention prep: top-k (radix select) + Qsel gather. Grid NBH, 512 threads.
// ---------------------------------------------------------------------------
__device__ __forceinline__ uint32_t f2ord(float f) {
    uint32_t u = __float_as_uint(f);
    return (u & 0x80000000u) ? ~u : (u | 0x80000000u);
}

__global__ void __launch_bounds__(512)
attn_prep2() {
    __shared__ int ties[1024];
    __shared__ int s_cntA[32];
    __shared__ int s_gt, s_tn;
    __shared__ int tops[48];

    const int bh = blockIdx.x;
    const int b  = bh >> 3;
    const int h  = bh & 7;
    const int t  = threadIdx.x;
    const int lane = t & 31;

    uint32_t u0 = f2ord(g_M[bh*L_ + t]);
    uint32_t u1 = f2ord(g_M[bh*L_ + t + 512]);
    if (t < 32) s_cntA[t] = 0;
    if (t == 0) { s_gt = 0; s_tn = 0; }
    __syncthreads();
    uint32_t prefix = 0;
    int need = SK;
    for (int bit = 31; bit >= 0; --bit) {
        uint32_t cd = (prefix >> bit) | 1u;
        int c = ((u0 >> bit) == cd) + ((u1 >> bit) == cd);
        int ws = __reduce_add_sync(0xffffffffu, c);
        if (lane == 0 && ws) atomicAdd(&s_cntA[bit], ws);
        __syncthreads();
        int cnt = s_cntA[bit];
        if (cnt >= need) prefix |= (1u << bit);
        else             need -= cnt;
    }
    if (u0 > prefix) tops[atomicAdd(&s_gt, 1)] = t;
    else if (u0 == prefix) ties[atomicAdd(&s_tn, 1)] = t;
    if (u1 > prefix) tops[atomicAdd(&s_gt, 1)] = t + 512;
    else if (u1 == prefix) ties[atomicAdd(&s_tn, 1)] = t + 512;
    __syncthreads();
    if (t == 0) {
        int base = s_gt, tn = s_tn;
        for (int sel = 0; sel < need; sel++) {
            int bi = -1, bvv = 0x7fffffff;
            for (int j = 0; j < tn; j++)
                if (ties[j] < bvv) { bvv = ties[j]; bi = j; }
            tops[base + sel] = bvv;
            ties[bi] = 0x7fffffff;
        }
    }
    __syncthreads();
    if (t < SK) g_top[bh*SK + t] = tops[t];

    for (int f = t; f < SK*HD; f += 512) {
        int u = f >> 6, k = f & 63;
        g_qsel[bh*SK*HD + f] = g_q[(size_t)((b<<10) + tops[u])*DM + h*HD + k];
    }
}

// ---------------------------------------------------------------------------
// Merged score+softmax-partial+ctx-partial, flash-style per-st max.
// Grid (8, NBH), 256 threads, dynamic smem.
// ---------------------------------------------------------------------------
#define AF_SMEM_FLOATS (64*129 + SK*64 + SK*128)

__global__ void __launch_bounds__(256)
attn_fused2() {
    extern __shared__ float csm[];
    float* kt = csm;                   // 64*129 (K tile, later V tile)
    float* sq = kt + 64*129;           // SK*64
    float* ps = sq + SK*64;            // SK*128 (exp probs)

    const int st = blockIdx.x;
    const int bh = blockIdx.y;
    const int b  = bh >> 3;
    const int h  = bh & 7;
    const int t  = threadIdx.x;
    const int lane = t & 31;
    const int w  = t >> 5;             // 0..7

    #pragma unroll
    for (int i = 0; i < 8; i++) {
        int f = t + i*256;
        int s = f >> 4, ec = (f & 15) << 2;
        float4 kv = *(const float4*)&g_k[(size_t)((b<<10) + st*128 + s)*DM + h*HD + ec];
        kt[(ec+0)*129 + s] = kv.x;
        kt[(ec+1)*129 + s] = kv.y;
        kt[(ec+2)*129 + s] = kv.z;
        kt[(ec+3)*129 + s] = kv.w;
    }
    for (int f = t; f < SK*HD; f += 256) sq[f] = g_qsel[bh*SK*HD + f];
    __syncthreads();

    float acc[5][4];
    #pragma unroll
    for (int jj = 0; jj < 5; jj++)
        #pragma unroll
        for (int r = 0; r < 4; r++) acc[jj][r] = 0.f;

    for (int k = 0; k < 64; k++) {
        float kv0 = kt[k*129 + lane];
        float kv1 = kt[k*129 + lane + 32];
        float kv2 = kt[k*129 + lane + 64];
        float kv3 = kt[k*129 + lane + 96];
        #pragma unroll
        for (int jj = 0; jj < 5; jj++) {
            int u = w + 8*jj;
            if (u < SK) {
                float qv = sq[u*HD + k];
                acc[jj][0] += qv*kv0; acc[jj][1] += qv*kv1;
                acc[jj][2] += qv*kv2; acc[jj][3] += qv*kv3;
            }
        }
    }

    #pragma unroll
    for (int jj = 0; jj < 5; jj++) {
        int u = w + 8*jj;
        if (u < SK) {
            float s0 = acc[jj][0]*0.125f, s1 = acc[jj][1]*0.125f;
            float s2 = acc[jj][2]*0.125f, s3 = acc[jj][3]*0.125f;
            float m = fmaxf(fmaxf(s0, s1), fmaxf(s2, s3));
            #pragma unroll
            for (int o = 16; o > 0; o >>= 1) m = fmaxf(m, __shfl_xor_sync(0xffffffffu, m, o));
            float e0 = expf(s0 - m), e1 = expf(s1 - m);
            float e2 = expf(s2 - m), e3 = expf(s3 - m);
            ps[u*128 + lane]      = e0;
            ps[u*128 + lane + 32] = e1;
            ps[u*128 + lane + 64] = e2;
            ps[u*128 + lane + 96] = e3;
            float ss = e0 + e1 + e2 + e3;
            #pragma unroll
            for (int o = 16; o > 0; o >>= 1) ss += __shfl_xor_sync(0xffffffffu, ss, o);
            if (lane == 0) {
                g_pmax[(bh*SK + u)*8 + st] = m;
                g_psum[(bh*8 + st)*SK + u] = ss;
            }
        }
    }
    __syncthreads();

    #pragma unroll
    for (int i = 0; i < 8; i++) {
        int f = t + i*256;
        int s = f >> 4, ec = (f & 15) << 2;
        float4 vv = *(const float4*)&g_v[(size_t)((b<<10) + st*128 + s)*DM + h*HD + ec];
        kt[(ec+0)*129 + s] = vv.x;
        kt[(ec+1)*129 + s] = vv.y;
        kt[(ec+2)*129 + s] = vv.z;
        kt[(ec+3)*129 + s] = vv.w;
    }
    __syncthreads();

    const int e  = t & 63;
    const int ug = t >> 6;             // 0..3
    float cacc[9];
    #pragma unroll
    for (int jj = 0; jj < 9; jj++) cacc[jj] = 0.f;
    for (int s = 0; s < 128; s++) {
        float v = kt[e*129 + s];
        #pragma unroll
        for (int jj = 0; jj < 9; jj++) {
            int u = ug + 4*jj;
            if (u < SK) cacc[jj] += ps[u*128 + s] * v;
        }
    }
    #pragma unroll
    for (int jj = 0; jj < 9; jj++) {
        int u = ug + 4*jj;
        if (u < SK) g_cpart[((size_t)(bh*8 + st)*SK + u)*HD + e] = cacc[jj];
    }
}

// ---------------------------------------------------------------------------
// Scatter with flash-style recombination. Grid NBH, 512 threads.
// ---------------------------------------------------------------------------
__global__ void __launch_bounds__(512)
attn_scatter() {
    __shared__ float coef[48][8];
    __shared__ float zinv[48];
    __shared__ int   tops[48];
    const int bh = blockIdx.x;
    const int b  = bh >> 3;
    const int h  = bh & 7;
    const int t  = threadIdx.x;

    if (t < SK) {
        float mm[8];
        float M = -FLT_MAX;
        #pragma unroll
        for (int st = 0; st < 8; st++) {
            mm[st] = g_pmax[(bh*SK + t)*8 + st];
            M = fmaxf(M, mm[st]);
        }
        float z = 0.f;
        #pragma unroll
        for (int st = 0; st < 8; st++) {
            float c = expf(mm[st] - M);
            coef[t][st] = c;
            z += c * g_psum[(bh*8 + st)*SK + t];
        }
        zinv[t] = 1.0f / z;
        tops[t] = g_top[bh*SK + t];
    }
    __syncthreads();

    const int e  = t & 63;
    const int ug = t >> 6;             // 0..7
    #pragma unroll
    for (int jj = 0; jj < 5; jj++) {
        int u = ug + 8*jj;
        if (u < SK) {
            float c = 0.f;
            #pragma unroll
            for (int st = 0; st < 8; st++)
                c += coef[u][st] * g_cpart[((size_t)(bh*8 + st)*SK + u)*HD + e];
            g_ctx[(size_t)((b<<10) + tops[u])*DM + h*HD + e] = to_tf32(c * zinv[u]);
        }
    }
}

// ---------------------------------------------------------------------------
// LayerNorm (row of 512, 256 threads). RND: round output to tf32.
// ---------------------------------------------------------------------------
template<bool RND>
__global__ void ln_kernel(const float* __restrict__ in, float* __restrict__ out,
                          const float* __restrict__ g, const float* __restrict__ be) {
    int row = blockIdx.x;
    int t   = threadIdx.x;
    float v0 = in[(size_t)row*DM + t];
    float v1 = in[(size_t)row*DM + t + 256];
    __shared__ float red[256];
    red[t] = v0 + v1; __syncthreads();
    for (int s = 128; s > 0; s >>= 1) { if (t < s) red[t] += red[t+s]; __syncthreads(); }
    float mean = red[0] * (1.0f/DM);
    __syncthreads();
    float d0 = v0 - mean, d1 = v1 - mean;
    red[t] = d0*d0 + d1*d1; __syncthreads();
    for (int s = 128; s > 0; s >>= 1) { if (t < s) red[t] += red[t+s]; __syncthreads(); }
    float rstd = rsqrtf(red[0] * (1.0f/DM) + 1e-5f);
    float o0 = d0*rstd*g[t]     + be[t];
    float o1 = d1*rstd*g[t+256] + be[t+256];
    if (RND) { o0 = to_tf32(o0); o1 = to_tf32(o1); }
    out[(size_t)row*DM + t]       = o0;
    out[(size_t)row*DM + t + 256] = o1;
}

// ---------------------------------------------------------------------------
// Mean pool stage 1; fused pool stage 2 + classifier (warp per (b,c))
// ---------------------------------------------------------------------------
__global__ void pool1_kernel() {
    int b = blockIdx.x, r = blockIdx.y;
    int d = threadIdx.x;
    float acc = 0.f;
    for (int l = r*128; l < r*128 + 128; l++)
        acc += g_tmp[(size_t)(b*L_+l)*DM + d];
    g_poolp[(b*8 + r)*DM + d] = acc;
}

__global__ void poolcls_kernel(const float* __restrict__ Wc,
                               const float* __restrict__ bc,
                               float* __restrict__ out) {
    __shared__ float pooled[B_*DM];
    int t = threadIdx.x;          // 512
    int lane = t & 31, w = t >> 5;
    #pragma unroll
    for (int i = 0; i < 4; i++) {
        int f = t + i*512;
        int b = f >> 9, d = f & 511;
        float acc = 0.f;
        #pragma unroll
        for (int r = 0; r < 8; r++) acc += g_poolp[(b*8 + r)*DM + d];
        pooled[f] = acc * (1.0f/L_);
    }
    __syncthreads();
    for (int bcp = w; bcp < B_*10; bcp += 16) {
        int b = bcp / 10, c = bcp % 10;
        float acc = 0.f;
        for (int d = lane; d < DM; d += 32)
            acc += pooled[b*DM + d] * Wc[d*10 + c];
        #pragma unroll
        for (int o = 16; o > 0; o >>= 1) acc += __shfl_xor_sync(0xffffffffu, acc, o);
        if (lane == 0) out[bcp] = acc + bc[c];
    }
}

// ---------------------------------------------------------------------------
extern "C" void kernel_launch(void* const* d_in, const int* in_sizes, int n_in,
                              void* d_out, int out_size) {
    const float* src   = (const float*)d_in[0];
    const int*   idxs  = (const int*)  d_in[1];
    const float* Wemb  = (const float*)d_in[2];
    const float* bemb  = (const float*)d_in[3];
    const float* Wq    = (const float*)d_in[4];
    const float* bq    = (const float*)d_in[5];
    const float* Wk    = (const float*)d_in[6];
    const float* bk    = (const float*)d_in[7];
    const float* Wv    = (const float*)d_in[8];
    const float* bv    = (const float*)d_in[9];
    const float* Wo    = (const float*)d_in[10];
    const float* bo    = (const float*)d_in[11];
    const float* g1    = (const float*)d_in[12];
    const float* beta1 = (const float*)d_in[13];
    const float* W1    = (const float*)d_in[14];
    const float* bf1   = (const float*)d_in[15];
    const float* W2    = (const float*)d_in[16];
    const float* bf2   = (const float*)d_in[17];
    const float* g2    = (const float*)d_in[18];
    const float* beta2 = (const float*)d_in[19];
    const float* gf    = (const float*)d_in[20];
    const float* betaf = (const float*)d_in[21];
    const float* Wc    = (const float*)d_in[22];
    const float* bc    = (const float*)d_in[23];

    void *px_, *ptmp_, *pq_, *pk_, *pv_, *pctx_, *pff_, *pwr_;
    cudaGetSymbolAddress(&px_,   g_x);
    cudaGetSymbolAddress(&ptmp_, g_tmp);
    cudaGetSymbolAddress(&pq_,   g_q);
    cudaGetSymbolAddress(&pk_,   g_k);
    cudaGetSymbolAddress(&pv_,   g_v);
    cudaGetSymbolAddress(&pctx_, g_ctx);
    cudaGetSymbolAddress(&pff_,  g_ff);
    cudaGetSymbolAddress(&pwr_,  g_wr);
    float* px   = (float*)px_;
    float* ptmp = (float*)ptmp_;
    float* pq   = (float*)pq_;
    float* pk   = (float*)pk_;
    float* pv   = (float*)pv_;
    float* pctx = (float*)pctx_;
    float* pff  = (float*)pff_;
    float* pwr  = (float*)pwr_;

    const int af_smem = AF_SMEM_FLOATS * 4;
    static int configured = 0;
    if (!configured) {
        configured = 1;
        cudaFuncSetAttribute(attn_fused2, cudaFuncAttributeMaxDynamicSharedMemorySize, af_smem);
        cudaFuncSetAttribute((const void*)qkv_tc, cudaFuncAttributeMaxDynamicSharedMemorySize, GEMM_SMEM);
        cudaFuncSetAttribute((const void*)gemm_tc<false,false>, cudaFuncAttributeMaxDynamicSharedMemorySize, GEMM_SMEM);
        cudaFuncSetAttribute((const void*)gemm_tc<true,true>,   cudaFuncAttributeMaxDynamicSharedMemorySize, GEMM_SMEM);
        cudaFuncSetAttribute((const void*)splitk_tc<256>, cudaFuncAttributeMaxDynamicSharedMemorySize, GEMM_SMEM);
        cudaFuncSetAttribute((const void*)splitk_tc<512>, cudaFuncAttributeMaxDynamicSharedMemorySize, GEMM_SMEM);
    }

    const int QS = 2*DM*DM;
    prep_kernel<<<NTOK + RND_BLOCKS, 512>>>(src, Wemb, bemb, Wq, Wk, Wv, Wo, W1, W2);

    for (int l = 0; l < 2; l++) {
        const float* W1_l = pwr + 4*QS + (size_t)l*DM*DFF;
        const float* W2_l = pwr + 4*QS + 2*DM*DFF + (size_t)l*DFF*DM;
        const float* Wo_l = pwr + 3*QS + (size_t)l*DM*DM;

        dim3 gQKV(DM/128, NTOK/128, 3);      // (4, 32, 3)
        dim3 gFF(DFF/128, NTOK/128);         // (16, 32)
        dim3 gWO(DM/128, NTOK/128, 2);       // (4, 32, 2) split-K2
        dim3 gSP(DM/128, NTOK/128, SPLITK);  // (4, 32, 4) split-K4
        dim3 gATT(8, NBH);                   // (8, 32)
        dim3 gVM(NBH, 8);                    // 256 blocks

        qkv_tc<<<gQKV, 128, GEMM_SMEM>>>(px, l, bq + l*DM, bk + l*DM, bv + l*DM,
                                         pq, pk, pv);

        vmean_part<<<gVM, 512>>>();
        fill_kernel<<<gVM, 512>>>();
        sampleM_kernel<<<(NBH*L_)/4, 128>>>(idxs + (size_t)l*L_*SK);
        attn_prep2<<<NBH, 512>>>();
        attn_fused2<<<gATT, 256, af_smem>>>();
        attn_scatter<<<NBH, 512>>>();

        splitk_tc<256><<<gWO, 128, GEMM_SMEM>>>(pctx, Wo_l, DM);
        reduce_ln_kernel<2><<<NTOK, 256>>>(bo + l*DM, px, g1 + l*DM, beta1 + l*DM, px);

        gemm_tc<true,true><<<gFF, 128, GEMM_SMEM>>>(px, W1_l, bf1 + l*DFF, nullptr, pff, DFF, DM);
        splitk_tc<512><<<gSP, 128, GEMM_SMEM>>>(pff, W2_l, DFF);
        reduce_ln_kernel<4><<<NTOK, 256>>>(bf2 + l*DM, px, g2 + l*DM, beta2 + l*DM, px);
    }

    ln_kernel<false><<<NTOK, 256>>>(px, ptmp, gf, betaf);
    pool1_kernel<<<dim3(B_, 8), 512>>>();
    poolcls_kernel<<<1, 512>>>(Wc, bc, (float*)d_out);
}

// round 13
// speedup vs baseline: 1.7880x; 1.0231x over previous
#include <cuda_runtime.h>
#include <cuda_bf16.h>
#include <math.h>
#include <float.h>
#include <stdint.h>

// ---------------------------------------------------------------------------
// Informer: B=4, L=1024, DM=512, NH=8, HD=64, DFF=2048, SK=35, 2 layers
// ---------------------------------------------------------------------------
#define B_   4
#define L_   1024
#define DM   512
#define NH   8
#define HD   64
#define DFF  2048
#define SK   35
#define NTOK (B_*L_)   // 4096
#define SPLITK 4
#define GS 3           // cp.async pipeline stages
#define NBH  (B_*NH)   // 32

__device__ float g_x   [NTOK*DM];
__device__ float g_q   [NTOK*DM];
__device__ float g_k   [NTOK*DM];
__device__ float g_v   [NTOK*DM];
__device__ float g_ctx [NTOK*DM];
__device__ float g_ff  [NTOK*DFF];
__device__ float g_split[SPLITK*NTOK*DM];
__device__ float g_M   [NBH*L_];
__device__ float g_poolp[B_*8*DM];
__device__ __nv_bfloat16 g_qh[NTOK*DM];   // bf16 copies for sampling
__device__ __nv_bfloat16 g_kh[NTOK*DM];
// attention intermediates
__device__ int   g_top  [NBH*SK];
__device__ float g_qsel [NBH*SK*HD];
__device__ float g_vmp  [NBH*8*64];       // vmean partials
__device__ float g_pmax [NBH*SK*8];
__device__ float g_psum [NBH*8*SK];
__device__ float g_cpart[(size_t)NBH*8*SK*HD];
// pre-rounded (tf32-rna) weights: Wq|Wk|Wv|Wo (both layers each) then W1, W2
#define WR_TOTAL (4*2*DM*DM + 2*DM*DFF + 2*DFF*DM)
__device__ float g_wr[WR_TOTAL];

// ---------------------------------------------------------------------------
__device__ __forceinline__ float to_tf32(float x) {
    uint32_t u;
    asm("cvt.rna.tf32.f32 %0, %1;" : "=r"(u) : "f"(x));
    return __uint_as_float(u);
}

__device__ __forceinline__ void mma_tf32(float* c, const uint32_t* a,
                                         uint32_t b0, uint32_t b1) {
    asm volatile(
        "mma.sync.aligned.m16n8k8.row.col.f32.tf32.tf32.f32 "
        "{%0,%1,%2,%3},{%4,%5,%6,%7},{%8,%9},{%0,%1,%2,%3};"
        : "+f"(c[0]), "+f"(c[1]), "+f"(c[2]), "+f"(c[3])
        : "r"(a[0]), "r"(a[1]), "r"(a[2]), "r"(a[3]), "r"(b0), "r"(b1));
}

__device__ __forceinline__ void cp16(void* smem, const void* g) {
    uint32_t s = (uint32_t)__cvta_generic_to_shared(smem);
    asm volatile("cp.async.cg.shared.global [%0], [%1], 16;\n" :: "r"(s), "l"(g));
}
#define CP_COMMIT() asm volatile("cp.async.commit_group;\n" ::: "memory")
#define CP_WAIT1()  asm volatile("cp.async.wait_group 1;\n" ::: "memory")

// ---------------------------------------------------------------------------
// Fused prologue: embed+posenc (blocks 0..NTOK-1) and weight tf32-rounding.
// ---------------------------------------------------------------------------
#define RND_BLOCKS ((WR_TOTAL/4 + 511) / 512)

__global__ void prep_kernel(const float* __restrict__ src,
                            const float* __restrict__ Wemb,
                            const float* __restrict__ bemb,
                            const float* __restrict__ Wq, const float* __restrict__ Wk,
                            const float* __restrict__ Wv, const float* __restrict__ Wo,
                            const float* __restrict__ W1, const float* __restrict__ W2) {
    const int bx = blockIdx.x;
    if (bx < NTOK) {
        int row = bx;
        int l   = row & (L_-1);
        int d   = threadIdx.x;
        __shared__ float s[32];
        if (d < 32) s[d] = src[row*32 + d];
        __syncthreads();
        float acc = bemb[d];
        #pragma unroll
        for (int k = 0; k < 32; k++) acc += s[k] * Wemb[k*DM + d];
        int i2 = d & ~1;
        float div = expf(-(float)i2 * (9.210340371976184f / 512.0f));
        float ang = (float)l * div;
        acc += (d & 1) ? cosf(ang) : sinf(ang);
        g_x[row*DM + d] = to_tf32(acc);
    } else {
        const int QS = 2*DM*DM;
        int i4 = (bx - NTOK) * 512 + threadIdx.x;
        int f  = i4 * 4;
        if (f >= WR_TOTAL) return;
        const float* sp;
        int off;
        if      (f < QS)      { sp = Wq; off = f; }
        else if (f < 2*QS)    { sp = Wk; off = f - QS; }
        else if (f < 3*QS)    { sp = Wv; off = f - 2*QS; }
        else if (f < 4*QS)    { sp = Wo; off = f - 3*QS; }
        else if (f < 4*QS + 2*DM*DFF) { sp = W1; off = f - 4*QS; }
        else                  { sp = W2; off = f - 4*QS - 2*DM*DFF; }
        float4 v = *(const float4*)&sp[off];
        v.x = to_tf32(v.x); v.y = to_tf32(v.y); v.z = to_tf32(v.z); v.w = to_tf32(v.w);
        *(float4*)&g_wr[f] = v;
    }
}

// ---------------------------------------------------------------------------
// tf32 GEMM, cp.async 3-stage pipeline. Block tile 128x128x16, 128 threads
// (4 warps, 2m x 2n, warp tile 64x64 -> 1.0 LDS per MMA).
// ---------------------------------------------------------------------------
#define AS(s,m,k) As[(s)*2560 + (m)*20 + (k)]
#define BS(s,k,n) Bs[(s)*2176 + (k)*136 + (n)]
#define GEMM_SMEM ((GS*2560 + GS*2176) * 4)

__device__ __forceinline__ void issue_tile(
        float* As, float* Bs, const float* A, const float* W,
        int lda, int N, int m0, int n0, int k0, int s, int tid) {
    #pragma unroll
    for (int i = 0; i < 4; i++) {
        int f = tid + i*128;
        int ma = f >> 2, kc = (f & 3) << 2;
        cp16(&AS(s,ma,kc), A + (size_t)(m0+ma)*lda + k0 + kc);
        int kr = f >> 5, nc = (f & 31) << 2;
        cp16(&BS(s,kr,nc), W + (size_t)(k0+kr)*N + n0 + nc);
    }
}

template<bool GELU, bool RAW, bool RND>
__device__ __forceinline__ void gemm_body(
        const float* __restrict__ A, const float* __restrict__ W,
        const float* __restrict__ bias, const float* __restrict__ resid,
        float* __restrict__ C, __nv_bfloat16* __restrict__ Hout,
        int N, int K, int lda, int bx, int by) {
    extern __shared__ float gsm[];
    float* As = gsm;
    float* Bs = gsm + GS*2560;

    const int tid  = threadIdx.x;          // 128
    const int w    = tid >> 5;             // 0..3
    const int lane = tid & 31;
    const int grp  = lane >> 2;
    const int qd   = lane & 3;
    const int warp_m = (w & 1) * 64;
    const int warp_n = (w >> 1) * 64;
    const int m0 = by * 128;
    const int n0 = bx * 128;

    float acc[4][8][4];
    #pragma unroll
    for (int mi = 0; mi < 4; mi++)
        #pragma unroll
        for (int ni = 0; ni < 8; ni++)
            #pragma unroll
            for (int j = 0; j < 4; j++) acc[mi][ni][j] = 0.f;

    const int nt = K >> 4;

    issue_tile(As, Bs, A, W, lda, N, m0, n0, 0, 0, tid);  CP_COMMIT();
    issue_tile(As, Bs, A, W, lda, N, m0, n0, 16, 1, tid); CP_COMMIT();

    for (int t = 0; t < nt; t++) {
        CP_WAIT1();
        __syncthreads();
        const int s = t % GS;
        if (t + 2 < nt)
            issue_tile(As, Bs, A, W, lda, N, m0, n0, (t+2) << 4, (t+2) % GS, tid);
        CP_COMMIT();

        #pragma unroll
        for (int kk = 0; kk < 16; kk += 8) {
            uint32_t af[4][4];
            #pragma unroll
            for (int mi = 0; mi < 4; mi++) {
                int mb = warp_m + mi*16 + grp;
                af[mi][0] = __float_as_uint(AS(s, mb,   kk+qd));
                af[mi][1] = __float_as_uint(AS(s, mb+8, kk+qd));
                af[mi][2] = __float_as_uint(AS(s, mb,   kk+qd+4));
                af[mi][3] = __float_as_uint(AS(s, mb+8, kk+qd+4));
            }
            #pragma unroll
            for (int ni = 0; ni < 8; ni++) {
                int nb = warp_n + ni*8 + grp;
                uint32_t b0 = __float_as_uint(BS(s, kk+qd,   nb));
                uint32_t b1 = __float_as_uint(BS(s, kk+qd+4, nb));
                #pragma unroll
                for (int mi = 0; mi < 4; mi++)
                    mma_tf32(acc[mi][ni], af[mi], b0, b1);
            }
        }
    }

    #pragma unroll
    for (int mi = 0; mi < 4; mi++) {
        int r0 = m0 + warp_m + mi*16 + grp;
        #pragma unroll
        for (int ni = 0; ni < 8; ni++) {
            int c = n0 + warp_n + ni*8 + qd*2;
            float v0 = acc[mi][ni][0];
            float v1 = acc[mi][ni][1];
            float v2 = acc[mi][ni][2];
            float v3 = acc[mi][ni][3];
            if (!RAW) {
                float b0 = bias[c], b1 = bias[c+1];
                v0 += b0; v1 += b1; v2 += b0; v3 += b1;
                if (resid) {
                    v0 += resid[(size_t)r0*N + c];     v1 += resid[(size_t)r0*N + c + 1];
                    v2 += resid[(size_t)(r0+8)*N + c]; v3 += resid[(size_t)(r0+8)*N + c + 1];
                }
                if (GELU) {
                    v0 = 0.5f*v0*(1.0f + erff(v0*0.70710678118654752f));
                    v1 = 0.5f*v1*(1.0f + erff(v1*0.70710678118654752f));
                    v2 = 0.5f*v2*(1.0f + erff(v2*0.70710678118654752f));
                    v3 = 0.5f*v3*(1.0f + erff(v3*0.70710678118654752f));
                }
            }
            if (RND) {
                v0 = to_tf32(v0); v1 = to_tf32(v1);
                v2 = to_tf32(v2); v3 = to_tf32(v3);
            }
            *(float2*)&C[(size_t)r0*N + c]     = make_float2(v0, v1);
            *(float2*)&C[(size_t)(r0+8)*N + c] = make_float2(v2, v3);
            if (Hout) {
                *(__nv_bfloat162*)&Hout[(size_t)r0*N + c] =
                    __floats2bfloat162_rn(v0, v1);
                *(__nv_bfloat162*)&Hout[(size_t)(r0+8)*N + c] =
                    __floats2bfloat162_rn(v2, v3);
            }
        }
    }
}

template<bool GELU, bool RND>
__global__ void __launch_bounds__(128, 2)
gemm_tc(const float* __restrict__ A, const float* __restrict__ W,
        const float* __restrict__ bias, const float* __restrict__ resid,
        float* __restrict__ C, int N, int K) {
    gemm_body<GELU, false, RND>(A, W, bias, resid, C, nullptr, N, K, K,
                                blockIdx.x, blockIdx.y);
}

// Fused QKV: blockIdx.z selects projection; Q,K also dual-stored as bf16.
__global__ void __launch_bounds__(128, 2)
qkv_tc(const float* __restrict__ A, int layer,
       const float* __restrict__ bq, const float* __restrict__ bk,
       const float* __restrict__ bv,
       float* __restrict__ Q, float* __restrict__ Ko, float* __restrict__ V) {
    const float* W; const float* bias; float* C; __nv_bfloat16* H;
    const int QS = 2*DM*DM;
    size_t loff = (size_t)layer*DM*DM;
    if (blockIdx.z == 0)      { W = g_wr + loff;        bias = bq; C = Q;  H = g_qh; }
    else if (blockIdx.z == 1) { W = g_wr + QS + loff;   bias = bk; C = Ko; H = g_kh; }
    else                      { W = g_wr + 2*QS + loff; bias = bv; C = V;  H = nullptr; }
    gemm_body<false, false, false>(A, W, bias, nullptr, C, H, DM, DM, DM,
                                   blockIdx.x, blockIdx.y);
}

// Generic split-K partial GEMM: blockIdx.z = k-chunk of size KC.
template<int KC>
__global__ void __launch_bounds__(128, 2)
splitk_tc(const float* __restrict__ A, const float* __restrict__ W,
          int lda) {
    const int kc = blockIdx.z;
    gemm_body<false, true, false>(A + kc*KC, W + (size_t)kc*KC*DM,
                                  nullptr, nullptr,
                                  g_split + (size_t)kc*NTOK*DM,
                                  nullptr, DM, KC, lda, blockIdx.x, blockIdx.y);
}

// Fused split-K reduce + bias + residual + LayerNorm (output rounded).
template<int NS>
__global__ void reduce_ln_kernel(const float* __restrict__ bias,
                                 const float* __restrict__ resid,
                                 const float* __restrict__ g,
                                 const float* __restrict__ be,
                                 float* __restrict__ out) {
    int row = blockIdx.x;
    int t   = threadIdx.x;
    size_t o0 = (size_t)row*DM + t;
    size_t o1 = o0 + 256;
    float v0 = resid[o0] + bias[t];
    float v1 = resid[o1] + bias[t+256];
    #pragma unroll
    for (int s = 0; s < NS; s++) {
        v0 += g_split[(size_t)s*NTOK*DM + o0];
        v1 += g_split[(size_t)s*NTOK*DM + o1];
    }
    __shared__ float red[256];
    red[t] = v0 + v1; __syncthreads();
    for (int s = 128; s > 0; s >>= 1) { if (t < s) red[t] += red[t+s]; __syncthreads(); }
    float mean = red[0] * (1.0f/DM);
    __syncthreads();
    float d0 = v0 - mean, d1 = v1 - mean;
    red[t] = d0*d0 + d1*d1; __syncthreads();
    for (int s = 128; s > 0; s >>= 1) { if (t < s) red[t] += red[t+s]; __syncthreads(); }
    float rstd = rsqrtf(red[0] * (1.0f/DM) + 1e-5f);
    out[o0] = to_tf32(d0*rstd*g[t]     + be[t]);
    out[o1] = to_tf32(d1*rstd*g[t+256] + be[t+256]);
}

// ---------------------------------------------------------------------------
// Merged vmean partials (blocks 0..255) + sampled measure M (rest).
// 512 threads. sampleM: one warp per (b,h,i), 16 warps/block.
// ---------------------------------------------------------------------------
__global__ void __launch_bounds__(512)
vm_sample_kernel(const int* __restrict__ idxs) {
    const int bx = blockIdx.x;
    const int t  = threadIdx.x;
    if (bx < 256) {
        const int bh = bx >> 3;
        const int r  = bx & 7;
        const int b  = bh >> 3;
        const int h  = bh & 7;
        const int e  = t & 63, rr = t >> 6;
        float acc = 0.f;
        int base = r*128 + rr*16;
        for (int l = base; l < base + 16; l++)
            acc += g_v[(size_t)((b<<10) + l)*DM + h*HD + e];
        __shared__ float red[512];
        red[t] = acc;
        __syncthreads();
        if (t < 64) {
            float s = 0.f;
            #pragma unroll
            for (int i = 0; i < 8; i++) s += red[t + i*64];
            g_vmp[(bh*8 + r)*64 + t] = s;
        }
        return;
    }
    // ---- sampleM: warp per (b,h,i)
    int lane = t & 31;
    int wg   = (bx - 256) * 16 + (t >> 5);
    if (wg >= NBH*L_) return;
    int i = wg & (L_-1);
    int h = (wg >> 10) & (NH-1);
    int b = wg >> 13;
    const int grp = lane >> 3;
    const int sub = lane & 7;

    const float4* Qr16 = (const float4*)&g_qh[(size_t)(b*L_ + i)*DM + h*HD];
    float4 qraw = Qr16[sub];
    uint32_t qa = __float_as_uint(qraw.x), qb = __float_as_uint(qraw.y);
    uint32_t qc = __float_as_uint(qraw.z), qd2 = __float_as_uint(qraw.w);
    float2 q0 = __bfloat1622float2(*(__nv_bfloat162*)&qa);
    float2 q1 = __bfloat1622float2(*(__nv_bfloat162*)&qb);
    float2 q2 = __bfloat1622float2(*(__nv_bfloat162*)&qc);
    float2 q3 = __bfloat1622float2(*(__nv_bfloat162*)&qd2);

    int idxA = idxs[i*SK + (lane < SK ? lane : 0)];
    int idxB = idxs[i*SK + ((32 + lane) < SK ? 32 + lane : 0)];

    float mx = -FLT_MAX, sm = 0.f;
    #pragma unroll
    for (int jj = 0; jj < 9; jj++) {
        int j = 4*jj + grp;
        int srcA = __shfl_sync(0xffffffffu, idxA, j & 31);
        int srcB = __shfl_sync(0xffffffffu, idxB, (j - 32) & 31);
        int src  = (j < 32) ? srcA : srcB;
        bool valid = (j < SK);
        float p = 0.f;
        if (valid) {
            const float4* Kr16 = (const float4*)&g_kh[(size_t)(b*L_ + src)*DM + h*HD];
            float4 kraw = Kr16[sub];
            uint32_t ka = __float_as_uint(kraw.x), kb = __float_as_uint(kraw.y);
            uint32_t kc = __float_as_uint(kraw.z), kd = __float_as_uint(kraw.w);
            float2 k0 = __bfloat1622float2(*(__nv_bfloat162*)&ka);
            float2 k1 = __bfloat1622float2(*(__nv_bfloat162*)&kb);
            float2 k2 = __bfloat1622float2(*(__nv_bfloat162*)&kc);
            float2 k3 = __bfloat1622float2(*(__nv_bfloat162*)&kd);
            p = q0.x*k0.x + q0.y*k0.y + q1.x*k1.x + q1.y*k1.y
              + q2.x*k2.x + q2.y*k2.y + q3.x*k3.x + q3.y*k3.y;
        }
        p += __shfl_xor_sync(0xffffffffu, p, 4);
        p += __shfl_xor_sync(0xffffffffu, p, 2);
        p += __shfl_xor_sync(0xffffffffu, p, 1);
        if (valid) { mx = fmaxf(mx, p); sm += p; }
    }
    mx = fmaxf(mx, __shfl_xor_sync(0xffffffffu, mx, 8));
    sm += __shfl_xor_sync(0xffffffffu, sm, 8);
    mx = fmaxf(mx, __shfl_xor_sync(0xffffffffu, mx, 16));
    sm += __shfl_xor_sync(0xffffffffu, sm, 16);
    if (lane == 0) g_M[(b*NH+h)*L_ + i] = mx - sm * (1.0f/SK);
}

// ---------------------------------------------------------------------------
// Merged ctx broadcast fill (blocks 0..255) + top-k/Qsel prep (blocks 256..287).
// 512 threads.
// ---------------------------------------------------------------------------
__device__ __forceinline__ uint32_t f2ord(float f) {
    uint32_t u = __float_as_uint(f);
    return (u & 0x80000000u) ? ~u : (u | 0x80000000u);
}

__global__ void __launch_bounds__(512)
fill_prep_kernel() {
    __shared__ __align__(16) float vm[64];
    __shared__ int ties[1024];
    __shared__ int s_cntA[32];
    __shared__ int s_gt, s_tn;
    __shared__ int tops[48];

    const int bx = blockIdx.x;
    const int t  = threadIdx.x;

    if (bx < 256) {
        const int bh = bx >> 3;
        const int r  = bx & 7;
        const int b  = bh >> 3;
        const int h  = bh & 7;
        if (t < 64) {
            float s = 0.f;
            #pragma unroll
            for (int i = 0; i < 8; i++) s += g_vmp[(bh*8 + i)*64 + t];
            vm[t] = to_tf32(s * (1.0f/L_));
        }
        __syncthreads();
        const float4* vm4 = (const float4*)vm;
        #pragma unroll
        for (int i = 0; i < 4; i++) {
            int f = t + i*512;
            int l = r*128 + (f >> 4), ev = f & 15;
            *(float4*)&g_ctx[(size_t)((b<<10) + l)*DM + h*HD + ev*4] = vm4[ev];
        }
        return;
    }

    // ---- top-k + Qsel gather
    const int bh = bx - 256;
    const int b  = bh >> 3;
    const int h  = bh & 7;
    const int lane = t & 31;

    uint32_t u0 = f2ord(g_M[bh*L_ + t]);
    uint32_t u1 = f2ord(g_M[bh*L_ + t + 512]);
    if (t < 32) s_cntA[t] = 0;
    if (t == 0) { s_gt = 0; s_tn = 0; }
    __syncthreads();
    uint32_t prefix = 0;
    int need = SK;
    for (int bit = 31; bit >= 0; --bit) {
        uint32_t cd = (prefix >> bit) | 1u;
        int c = ((u0 >> bit) == cd) + ((u1 >> bit) == cd);
        int ws = __reduce_add_sync(0xffffffffu, c);
        if (lane == 0 && ws) atomicAdd(&s_cntA[bit], ws);
        __syncthreads();
        int cnt = s_cntA[bit];
        if (cnt >= need) prefix |= (1u << bit);
        else             need -= cnt;
    }
    if (u0 > prefix) tops[atomicAdd(&s_gt, 1)] = t;
    else if (u0 == prefix) ties[atomicAdd(&s_tn, 1)] = t;
    if (u1 > prefix) tops[atomicAdd(&s_gt, 1)] = t + 512;
    else if (u1 == prefix) ties[atomicAdd(&s_tn, 1)] = t + 512;
    __syncthreads();
    if (t == 0) {
        int base = s_gt, tn = s_tn;
        for (int sel = 0; sel < need; sel++) {
            int bi = -1, bvv = 0x7fffffff;
            for (int j = 0; j < tn; j++)
                if (ties[j] < bvv) { bvv = ties[j]; bi = j; }
            tops[base + sel] = bvv;
            ties[bi] = 0x7fffffff;
        }
    }
    __syncthreads();
    if (t < SK) g_top[bh*SK + t] = tops[t];

    for (int f = t; f < SK*HD; f += 512) {
        int u = f >> 6, k = f & 63;
        g_qsel[bh*SK*HD + f] = g_q[(size_t)((b<<10) + tops[u])*DM + h*HD + k];
    }
}

// ---------------------------------------------------------------------------
// Merged score+softmax-partial+ctx-partial, flash-style per-st max.
// Grid (8, NBH), 256 threads, dynamic smem.
// ---------------------------------------------------------------------------
#define AF_SMEM_FLOATS (64*129 + SK*64 + SK*128)

__global__ void __launch_bounds__(256)
attn_fused2() {
    extern __shared__ float csm[];
    float* kt = csm;                   // 64*129 (K tile, later V tile)
    float* sq = kt + 64*129;           // SK*64
    float* ps = sq + SK*64;            // SK*128

    const int st = blockIdx.x;
    const int bh = blockIdx.y;
    const int b  = bh >> 3;
    const int h  = bh & 7;
    const int t  = threadIdx.x;
    const int lane = t & 31;
    const int w  = t >> 5;

    #pragma unroll
    for (int i = 0; i < 8; i++) {
        int f = t + i*256;
        int s = f >> 4, ec = (f & 15) << 2;
        float4 kv = *(const float4*)&g_k[(size_t)((b<<10) + st*128 + s)*DM + h*HD + ec];
        kt[(ec+0)*129 + s] = kv.x;
        kt[(ec+1)*129 + s] = kv.y;
        kt[(ec+2)*129 + s] = kv.z;
        kt[(ec+3)*129 + s] = kv.w;
    }
    for (int f = t; f < SK*HD; f += 256) sq[f] = g_qsel[bh*SK*HD + f];
    __syncthreads();

    float acc[5][4];
    #pragma unroll
    for (int jj = 0; jj < 5; jj++)
        #pragma unroll
        for (int r = 0; r < 4; r++) acc[jj][r] = 0.f;

    for (int k = 0; k < 64; k++) {
        float kv0 = kt[k*129 + lane];
        float kv1 = kt[k*129 + lane + 32];
        float kv2 = kt[k*129 + lane + 64];
        float kv3 = kt[k*129 + lane + 96];
        #pragma unroll
        for (int jj = 0; jj < 5; jj++) {
            int u = w + 8*jj;
            if (u < SK) {
                float qv = sq[u*HD + k];
                acc[jj][0] += qv*kv0; acc[jj][1] += qv*kv1;
                acc[jj][2] += qv*kv2; acc[jj][3] += qv*kv3;
            }
        }
    }

    #pragma unroll
    for (int jj = 0; jj < 5; jj++) {
        int u = w + 8*jj;
        if (u < SK) {
            float s0 = acc[jj][0]*0.125f, s1 = acc[jj][1]*0.125f;
            float s2 = acc[jj][2]*0.125f, s3 = acc[jj][3]*0.125f;
            float m = fmaxf(fmaxf(s0, s1), fmaxf(s2, s3));
            #pragma unroll
            for (int o = 16; o > 0; o >>= 1) m = fmaxf(m, __shfl_xor_sync(0xffffffffu, m, o));
            float e0 = expf(s0 - m), e1 = expf(s1 - m);
            float e2 = expf(s2 - m), e3 = expf(s3 - m);
            ps[u*128 + lane]      = e0;
            ps[u*128 + lane + 32] = e1;
            ps[u*128 + lane + 64] = e2;
            ps[u*128 + lane + 96] = e3;
            float ss = e0 + e1 + e2 + e3;
            #pragma unroll
            for (int o = 16; o > 0; o >>= 1) ss += __shfl_xor_sync(0xffffffffu, ss, o);
            if (lane == 0) {
                g_pmax[(bh*SK + u)*8 + st] = m;
                g_psum[(bh*8 + st)*SK + u] = ss;
            }
        }
    }
    __syncthreads();

    #pragma unroll
    for (int i = 0; i < 8; i++) {
        int f = t + i*256;
        int s = f >> 4, ec = (f & 15) << 2;
        float4 vv = *(const float4*)&g_v[(size_t)((b<<10) + st*128 + s)*DM + h*HD + ec];
        kt[(ec+0)*129 + s] = vv.x;
        kt[(ec+1)*129 + s] = vv.y;
        kt[(ec+2)*129 + s] = vv.z;
        kt[(ec+3)*129 + s] = vv.w;
    }
    __syncthreads();

    const int e  = t & 63;
    const int ug = t >> 6;
    float cacc[9];
    #pragma unroll
    for (int jj = 0; jj < 9; jj++) cacc[jj] = 0.f;
    for (int s = 0; s < 128; s++) {
        float v = kt[e*129 + s];
        #pragma unroll
        for (int jj = 0; jj < 9; jj++) {
            int u = ug + 4*jj;
            if (u < SK) cacc[jj] += ps[u*128 + s] * v;
        }
    }
    #pragma unroll
    for (int jj = 0; jj < 9; jj++) {
        int u = ug + 4*jj;
        if (u < SK) g_cpart[((size_t)(bh*8 + st)*SK + u)*HD + e] = cacc[jj];
    }
}

// ---------------------------------------------------------------------------
// Scatter with flash-style recombination. Grid NBH, 512 threads.
// ---------------------------------------------------------------------------
__global__ void __launch_bounds__(512)
attn_scatter() {
    __shared__ float coef[48][8];
    __shared__ float zinv[48];
    __shared__ int   tops[48];
    const int bh = blockIdx.x;
    const int b  = bh >> 3;
    const int h  = bh & 7;
    const int t  = threadIdx.x;

    if (t < SK) {
        float mm[8];
        float M = -FLT_MAX;
        #pragma unroll
        for (int st = 0; st < 8; st++) {
            mm[st] = g_pmax[(bh*SK + t)*8 + st];
            M = fmaxf(M, mm[st]);
        }
        float z = 0.f;
        #pragma unroll
        for (int st = 0; st < 8; st++) {
            float c = expf(mm[st] - M);
            coef[t][st] = c;
            z += c * g_psum[(bh*8 + st)*SK + t];
        }
        zinv[t] = 1.0f / z;
        tops[t] = g_top[bh*SK + t];
    }
    __syncthreads();

    const int e  = t & 63;
    const int ug = t >> 6;
    #pragma unroll
    for (int jj = 0; jj < 5; jj++) {
        int u = ug + 8*jj;
        if (u < SK) {
            float c = 0.f;
            #pragma unroll
            for (int st = 0; st < 8; st++)
                c += coef[u][st] * g_cpart[((size_t)(bh*8 + st)*SK + u)*HD + e];
            g_ctx[(size_t)((b<<10) + tops[u])*DM + h*HD + e] = to_tf32(c * zinv[u]);
        }
    }
}

// ---------------------------------------------------------------------------
// Fused final LayerNorm + mean-pool stage1. Grid (B_, 8), 512 threads.
// Warp per row (two-pass LN, matching reference), pooling in registers.
// ---------------------------------------------------------------------------
__global__ void __launch_bounds__(512)
lnpool_kernel(const float* __restrict__ in,
              const float* __restrict__ g, const float* __restrict__ be) {
    __shared__ float part[16][512];
    const int b = blockIdx.x, r = blockIdx.y;
    const int t = threadIdx.x;
    const int lane = t & 31, w = t >> 5;

    float gj[16], bj[16];
    #pragma unroll
    for (int j = 0; j < 16; j++) {
        gj[j] = g[lane + 32*j];
        bj[j] = be[lane + 32*j];
    }

    float acc[16];
    #pragma unroll
    for (int j = 0; j < 16; j++) acc[j] = 0.f;

    for (int rr = 0; rr < 8; rr++) {
        int row = b*L_ + r*128 + w*8 + rr;
        float v[16];
        float s = 0.f;
        #pragma unroll
        for (int j = 0; j < 16; j++) {
            v[j] = in[(size_t)row*DM + lane + 32*j];
            s += v[j];
        }
        #pragma unroll
        for (int o = 16; o > 0; o >>= 1) s += __shfl_xor_sync(0xffffffffu, s, o);
        float mean = s * (1.0f/DM);
        float s2 = 0.f;
        #pragma unroll
        for (int j = 0; j < 16; j++) {
            float d = v[j] - mean;
            s2 += d*d;
        }
        #pragma unroll
        for (int o = 16; o > 0; o >>= 1) s2 += __shfl_xor_sync(0xffffffffu, s2, o);
        float rstd = rsqrtf(s2 * (1.0f/DM) + 1e-5f);
        #pragma unroll
        for (int j = 0; j < 16; j++)
            acc[j] += (v[j] - mean)*rstd*gj[j] + bj[j];
    }
    #pragma unroll
    for (int j = 0; j < 16; j++) part[w][lane + 32*j] = acc[j];
    __syncthreads();
    // reduce 16 warps -> poolp
    float s = 0.f;
    #pragma unroll
    for (int ww = 0; ww < 16; ww++) s += part[ww][t];
    g_poolp[(b*8 + r)*DM + t] = s;
}

// ---------------------------------------------------------------------------
// Fused pool stage 2 + classifier (warp per (b,c))
// ---------------------------------------------------------------------------
__global__ void poolcls_kernel(const float* __restrict__ Wc,
                               const float* __restrict__ bc,
                               float* __restrict__ out) {
    __shared__ float pooled[B_*DM];
    int t = threadIdx.x;          // 512
    int lane = t & 31, w = t >> 5;
    #pragma unroll
    for (int i = 0; i < 4; i++) {
        int f = t + i*512;
        int b = f >> 9, d = f & 511;
        float acc = 0.f;
        #pragma unroll
        for (int r = 0; r < 8; r++) acc += g_poolp[(b*8 + r)*DM + d];
        pooled[f] = acc * (1.0f/L_);
    }
    __syncthreads();
    for (int bcp = w; bcp < B_*10; bcp += 16) {
        int b = bcp / 10, c = bcp % 10;
        float acc = 0.f;
        for (int d = lane; d < DM; d += 32)
            acc += pooled[b*DM + d] * Wc[d*10 + c];
        #pragma unroll
        for (int o = 16; o > 0; o >>= 1) acc += __shfl_xor_sync(0xffffffffu, acc, o);
        if (lane == 0) out[bcp] = acc + bc[c];
    }
}

// ---------------------------------------------------------------------------
extern "C" void kernel_launch(void* const* d_in, const int* in_sizes, int n_in,
                              void* d_out, int out_size) {
    const float* src   = (const float*)d_in[0];
    const int*   idxs  = (const int*)  d_in[1];
    const float* Wemb  = (const float*)d_in[2];
    const float* bemb  = (const float*)d_in[3];
    const float* Wq    = (const float*)d_in[4];
    const float* bq    = (const float*)d_in[5];
    const float* Wk    = (const float*)d_in[6];
    const float* bk    = (const float*)d_in[7];
    const float* Wv    = (const float*)d_in[8];
    const float* bv    = (const float*)d_in[9];
    const float* Wo    = (const float*)d_in[10];
    const float* bo    = (const float*)d_in[11];
    const float* g1    = (const float*)d_in[12];
    const float* beta1 = (const float*)d_in[13];
    const float* W1    = (const float*)d_in[14];
    const float* bf1   = (const float*)d_in[15];
    const float* W2    = (const float*)d_in[16];
    const float* bf2   = (const float*)d_in[17];
    const float* g2    = (const float*)d_in[18];
    const float* beta2 = (const float*)d_in[19];
    const float* gf    = (const float*)d_in[20];
    const float* betaf = (const float*)d_in[21];
    const float* Wc    = (const float*)d_in[22];
    const float* bc    = (const float*)d_in[23];

    void *px_, *pq_, *pk_, *pv_, *pctx_, *pff_, *pwr_;
    cudaGetSymbolAddress(&px_,   g_x);
    cudaGetSymbolAddress(&pq_,   g_q);
    cudaGetSymbolAddress(&pk_,   g_k);
    cudaGetSymbolAddress(&pv_,   g_v);
    cudaGetSymbolAddress(&pctx_, g_ctx);
    cudaGetSymbolAddress(&pff_,  g_ff);
    cudaGetSymbolAddress(&pwr_,  g_wr);
    float* px   = (float*)px_;
    float* pq   = (float*)pq_;
    float* pk   = (float*)pk_;
    float* pv   = (float*)pv_;
    float* pctx = (float*)pctx_;
    float* pff  = (float*)pff_;
    float* pwr  = (float*)pwr_;

    const int af_smem = AF_SMEM_FLOATS * 4;
    static int configured = 0;
    if (!configured) {
        configured = 1;
        cudaFuncSetAttribute(attn_fused2, cudaFuncAttributeMaxDynamicSharedMemorySize, af_smem);
        cudaFuncSetAttribute((const void*)qkv_tc, cudaFuncAttributeMaxDynamicSharedMemorySize, GEMM_SMEM);
        cudaFuncSetAttribute((const void*)gemm_tc<false,false>, cudaFuncAttributeMaxDynamicSharedMemorySize, GEMM_SMEM);
        cudaFuncSetAttribute((const void*)gemm_tc<true,true>,   cudaFuncAttributeMaxDynamicSharedMemorySize, GEMM_SMEM);
        cudaFuncSetAttribute((const void*)splitk_tc<256>, cudaFuncAttributeMaxDynamicSharedMemorySize, GEMM_SMEM);
        cudaFuncSetAttribute((const void*)splitk_tc<512>, cudaFuncAttributeMaxDynamicSharedMemorySize, GEMM_SMEM);
    }

    const int QS = 2*DM*DM;
    prep_kernel<<<NTOK + RND_BLOCKS, 512>>>(src, Wemb, bemb, Wq, Wk, Wv, Wo, W1, W2);

    for (int l = 0; l < 2; l++) {
        const float* W1_l = pwr + 4*QS + (size_t)l*DM*DFF;
        const float* W2_l = pwr + 4*QS + 2*DM*DFF + (size_t)l*DFF*DM;
        const float* Wo_l = pwr + 3*QS + (size_t)l*DM*DM;

        dim3 gQKV(DM/128, NTOK/128, 3);      // (4, 32, 3)
        dim3 gFF(DFF/128, NTOK/128);         // (16, 32)
        dim3 gWO(DM/128, NTOK/128, 2);       // (4, 32, 2) split-K2
        dim3 gSP(DM/128, NTOK/128, SPLITK);  // (4, 32, 4) split-K4
        dim3 gATT(8, NBH);                   // (8, 32)

        qkv_tc<<<gQKV, 128, GEMM_SMEM>>>(px, l, bq + l*DM, bk + l*DM, bv + l*DM,
                                         pq, pk, pv);

        vm_sample_kernel<<<256 + 2048, 512>>>(idxs + (size_t)l*L_*SK);
        fill_prep_kernel<<<256 + NBH, 512>>>();
        attn_fused2<<<gATT, 256, af_smem>>>();
        attn_scatter<<<NBH, 512>>>();

        splitk_tc<256><<<gWO, 128, GEMM_SMEM>>>(pctx, Wo_l, DM);
        reduce_ln_kernel<2><<<NTOK, 256>>>(bo + l*DM, px, g1 + l*DM, beta1 + l*DM, px);

        gemm_tc<true,true><<<gFF, 128, GEMM_SMEM>>>(px, W1_l, bf1 + l*DFF, nullptr, pff, DFF, DM);
        splitk_tc<512><<<gSP, 128, GEMM_SMEM>>>(pff, W2_l, DFF);
        reduce_ln_kernel<4><<<NTOK, 256>>>(bf2 + l*DM, px, g2 + l*DM, beta2 + l*DM, px);
    }

    lnpool_kernel<<<dim3(B_, 8), 512>>>(px, gf, betaf);
    poolcls_kernel<<<1, 512>>>(Wc, bc, (float*)d_out);
}